// round 11
// baseline (speedup 1.0000x reference)
#include <cuda_runtime.h>
#include <math.h>
#include <stdint.h>
#include <mma.h>

using namespace nvcuda;

#define NQ      16384
#define CDIM    256
#define HEADS   8
#define HD      32
#define NPTS    4
#define NLAYERS 6
#define NCAM    6
#define HF      58
#define WF      100
#define NPIX    (HF*WF)
#define NFEAT   (NCAM*NPIX)
#define FFN     512

// ---------------- scratch ----------------------------------------------------
__device__ __align__(256) float g_q[NQ*CDIM];
__device__ __align__(256) float g_q_rnd[NQ*CDIM];
__device__ __align__(256) float g_a[NQ*CDIM];
__device__ __align__(256) float g_hid[NQ*FFN];
__device__ __align__(256) float g_v[NQ*CDIM];
__device__ __align__(256) float g_vimg[NFEAT*CDIM];
__device__ __align__(256) float g_offattn[NQ*96];
__device__ __align__(256) float g_feats[NFEAT*CDIM];
__device__ __align__(256) float g_refcam[NCAM*NQ*NPTS*2];
__device__ __align__(256) float g_valid[NCAM*NQ*NPTS];
__device__ __align__(256) float g_cnt[NQ];
__device__ __align__(256) float g_inv[NCAM*16];
__device__ __align__(256) float g_tvw[NLAYERS*CDIM*CDIM];
__device__ __align__(256) float g_tpw[NLAYERS*CDIM*CDIM];
__device__ __align__(256) float g_svw[NLAYERS*CDIM*CDIM];
__device__ __align__(256) float g_spw[NLAYERS*CDIM*CDIM];
__device__ __align__(256) float g_f1w[NLAYERS*CDIM*FFN];
__device__ __align__(256) float g_f2w[NLAYERS*FFN*CDIM];
__device__ __align__(256) float g_oaw[2*NLAYERS*CDIM*128];
__device__ __align__(256) float g_oab[2*NLAYERS*128];

// ---------------- helpers ------------------------------------------------------
__device__ __forceinline__ float tf32r(float x) {
    float o;
    asm("cvt.rna.tf32.f32 %0, %1;" : "=f"(o) : "f"(x));
    return o;
}
__device__ __forceinline__ void cp_async16(void* sp, const void* gp) {
    uint32_t s = (uint32_t)__cvta_generic_to_shared(sp);
    asm volatile("cp.async.cg.shared.global [%0], [%1], 16;\n" :: "r"(s), "l"(gp));
}
__device__ __forceinline__ void cp_commit() { asm volatile("cp.async.commit_group;\n" ::: "memory"); }
template<int N> __device__ __forceinline__ void cp_wait() {
    asm volatile("cp.async.wait_group %0;\n" :: "n"(N) : "memory");
}

// ---------------- big tf32 GEMM: 128x128 tile, BK=32, 3-stage pipeline ---------
#define TBM 128
#define TBN 128
#define TBK 32
#define TLDA 36
#define TLDB 132
#define TA_ST (TBM*TLDA)   // 4608 floats
#define TB_ST (TBK*TLDB)   // 4224 floats
#define TLDC 132
#define T_SMEM (3*(TA_ST+TB_ST)*4)   // 105984 B

template<int EPI, bool AVG>
__global__ __launch_bounds__(256, 2) void k_gemm128(
    const float* __restrict__ A, const float* __restrict__ A2,
    const float* __restrict__ B,
    const float* __restrict__ bias, float* __restrict__ out,
    int M, int N, int K, int ldb)
{
    extern __shared__ float sm[];
    float* As = sm;
    float* Bs = sm + 3*TA_ST;
    float* Cs = sm;

    int tid = threadIdx.x;
    int wid = tid >> 5;
    int wr = wid & 1;
    int wc = wid >> 1;
    int m0 = blockIdx.x * TBM;
    int n0 = blockIdx.y * TBN;

    wmma::fragment<wmma::accumulator, 16, 16, 8, float> c[4][2];
    #pragma unroll
    for (int i = 0; i < 4; i++)
        #pragma unroll
        for (int j = 0; j < 2; j++)
            wmma::fill_fragment(c[i][j], 0.f);

    auto load_st = [&](int t, int b) {
        int k0 = t * TBK;
        float* as = As + b*TA_ST;
        float* bs = Bs + b*TB_ST;
        #pragma unroll
        for (int i = 0; i < 4; i++) {
            int cid = tid + i*256;
            int r = cid >> 3, c4 = cid & 7;
            int m = m0 + r; if (m >= M) m = M - 1;
            if (AVG) {
                float4 v1 = *(const float4*)&A[(size_t)m*K + k0 + c4*4];
                float4 v2 = *(const float4*)&A2[(size_t)m*K + k0 + c4*4];
                float4 v;
                v.x = tf32r(0.5f*(v1.x + v2.x));
                v.y = tf32r(0.5f*(v1.y + v2.y));
                v.z = tf32r(0.5f*(v1.z + v2.z));
                v.w = tf32r(0.5f*(v1.w + v2.w));
                *(float4*)&as[r*TLDA + c4*4] = v;
            } else {
                cp_async16(&as[r*TLDA + c4*4], &A[(size_t)m*K + k0 + c4*4]);
            }
        }
        #pragma unroll
        for (int i = 0; i < 4; i++) {
            int cid = tid + i*256;
            int r = cid >> 5, c4 = cid & 31;
            cp_async16(&bs[r*TLDB + c4*4], &B[(size_t)(k0 + r)*ldb + n0 + c4*4]);
        }
        cp_commit();
    };

    int T = K / TBK;
    load_st(0, 0);
    if (T > 1) load_st(1, 1);
    for (int t = 0; t < T; t++) {
        int buf = t % 3;
        if (t + 2 < T) {
            load_st(t + 2, (t + 2) % 3);
            cp_wait<2>();
        } else if (t + 1 < T) {
            cp_wait<1>();
        } else {
            cp_wait<0>();
        }
        __syncthreads();
        const float* as = As + buf*TA_ST;
        const float* bs = Bs + buf*TB_ST;
        #pragma unroll
        for (int kk = 0; kk < TBK; kk += 8) {
            wmma::fragment<wmma::matrix_a, 16, 16, 8, wmma::precision::tf32, wmma::row_major> a[4];
            wmma::fragment<wmma::matrix_b, 16, 16, 8, wmma::precision::tf32, wmma::row_major> bfrag[2];
            #pragma unroll
            for (int i = 0; i < 4; i++)
                wmma::load_matrix_sync(a[i], &as[(wr*64 + i*16)*TLDA + kk], TLDA);
            #pragma unroll
            for (int j = 0; j < 2; j++)
                wmma::load_matrix_sync(bfrag[j], &bs[kk*TLDB + wc*32 + j*16], TLDB);
            #pragma unroll
            for (int i = 0; i < 4; i++)
                #pragma unroll
                for (int j = 0; j < 2; j++)
                    wmma::mma_sync(c[i][j], a[i], bfrag[j], c[i][j]);
        }
        __syncthreads();
    }

    // chunked epilogue (64 rows at a time)
    int e4 = tid & 31, er = tid >> 5;
    int nn = n0 + e4*4;
    float4 bv = make_float4(0.f, 0.f, 0.f, 0.f);
    if (nn < N) bv = *(const float4*)&bias[nn];
    #pragma unroll
    for (int chunk = 0; chunk < 2; chunk++) {
        if (wr == chunk) {
            #pragma unroll
            for (int i = 0; i < 4; i++)
                #pragma unroll
                for (int j = 0; j < 2; j++)
                    wmma::store_matrix_sync(&Cs[(i*16)*TLDC + wc*32 + j*16],
                                            c[i][j], TLDC, wmma::mem_row_major);
        }
        __syncthreads();
        if (nn < N) {
            #pragma unroll
            for (int i = 0; i < 8; i++) {
                int r = er + i*8;
                int m = m0 + chunk*64 + r;
                if (m < M) {
                    float4 v = *(float4*)&Cs[r*TLDC + e4*4];
                    v.x += bv.x; v.y += bv.y; v.z += bv.z; v.w += bv.w;
                    if (EPI == 1) {
                        v.x = tf32r(fmaxf(v.x, 0.f)); v.y = tf32r(fmaxf(v.y, 0.f));
                        v.z = tf32r(fmaxf(v.z, 0.f)); v.w = tf32r(fmaxf(v.w, 0.f));
                    }
                    *(float4*)&out[(size_t)m*N + nn] = v;
                }
            }
        }
        __syncthreads();
    }
}

// ---------------- small GEMM: 64x128 tile (for N<=128), 2-stage ----------------
#define SBM 64
#define SBK 32
#define SLDA 36
#define SLDB 132
#define SA_ST (SBM*SLDA)   // 2304
#define SB_ST (SBK*SLDB)   // 4224
#define SLDC 132
#define S_SMEM (2*(SA_ST+SB_ST)*4)   // 52224 B

__global__ __launch_bounds__(256, 2) void k_gemm64(
    const float* __restrict__ A, const float* __restrict__ B,
    const float* __restrict__ bias, float* __restrict__ out,
    int M, int N, int K, int ldb)
{
    extern __shared__ float sm[];
    float* As = sm;
    float* Bs = sm + 2*SA_ST;
    float* Cs = sm;

    int tid = threadIdx.x;
    int wid = tid >> 5;
    int wr = wid & 1;    // 2 warp-rows (32 rows each)
    int wc = wid >> 1;   // 4 warp-cols (32 cols each)
    int m0 = blockIdx.x * SBM;

    wmma::fragment<wmma::accumulator, 16, 16, 8, float> c[2][2];
    #pragma unroll
    for (int i = 0; i < 2; i++)
        #pragma unroll
        for (int j = 0; j < 2; j++)
            wmma::fill_fragment(c[i][j], 0.f);

    auto load_st = [&](int t, int b) {
        int k0 = t * SBK;
        float* as = As + b*SA_ST;
        float* bs = Bs + b*SB_ST;
        #pragma unroll
        for (int i = 0; i < 2; i++) {
            int cid = tid + i*256;
            int r = cid >> 3, c4 = cid & 7;
            cp_async16(&as[r*SLDA + c4*4], &A[(size_t)(m0 + r)*K + k0 + c4*4]);
        }
        #pragma unroll
        for (int i = 0; i < 4; i++) {
            int cid = tid + i*256;
            int r = cid >> 5, c4 = cid & 31;
            cp_async16(&bs[r*SLDB + c4*4], &B[(size_t)(k0 + r)*ldb + c4*4]);
        }
        cp_commit();
    };

    int T = K / SBK;
    load_st(0, 0);
    for (int t = 0; t < T; t++) {
        int b = t & 1;
        if (t + 1 < T) {
            load_st(t + 1, b ^ 1);
            cp_wait<1>();
        } else {
            cp_wait<0>();
        }
        __syncthreads();
        const float* as = As + b*SA_ST;
        const float* bs = Bs + b*SB_ST;
        #pragma unroll
        for (int kk = 0; kk < SBK; kk += 8) {
            wmma::fragment<wmma::matrix_a, 16, 16, 8, wmma::precision::tf32, wmma::row_major> a[2];
            wmma::fragment<wmma::matrix_b, 16, 16, 8, wmma::precision::tf32, wmma::row_major> bfrag[2];
            #pragma unroll
            for (int i = 0; i < 2; i++)
                wmma::load_matrix_sync(a[i], &as[(wr*32 + i*16)*SLDA + kk], SLDA);
            #pragma unroll
            for (int j = 0; j < 2; j++)
                wmma::load_matrix_sync(bfrag[j], &bs[kk*SLDB + wc*32 + j*16], SLDB);
            #pragma unroll
            for (int i = 0; i < 2; i++)
                #pragma unroll
                for (int j = 0; j < 2; j++)
                    wmma::mma_sync(c[i][j], a[i], bfrag[j], c[i][j]);
        }
        __syncthreads();
    }

    #pragma unroll
    for (int i = 0; i < 2; i++)
        #pragma unroll
        for (int j = 0; j < 2; j++)
            wmma::store_matrix_sync(&Cs[(wr*32 + i*16)*SLDC + wc*32 + j*16],
                                    c[i][j], SLDC, wmma::mem_row_major);
    __syncthreads();

    int e4 = tid & 31, er = tid >> 5;
    int nn = e4*4;
    if (nn < N) {
        float4 bv = *(const float4*)&bias[nn];
        #pragma unroll
        for (int i = 0; i < 8; i++) {
            int r = er + i*8;
            int m = m0 + r;
            float4 v = *(float4*)&Cs[r*SLDC + e4*4];
            v.x += bv.x; v.y += bv.y; v.z += bv.z; v.w += bv.w;
            *(float4*)&out[(size_t)m*N + nn] = v;
        }
    }
}

// ---------------- fused GEMM + residual + LN (N=256), BK=32 pipelined ----------
#define LM 64
#define LBK 32
#define LLDA 40
#define LLDB 264
#define LA_ST (LM*LLDA)
#define LB_ST (LBK*LLDB)
#define LLDC 260
#define L_SMEM ((2*(LA_ST+LB_ST))*4)   // 88064 B

__global__ __launch_bounds__(256, 2) void k_gemm_ln(
    const float* __restrict__ A, const float* __restrict__ W,
    const float* __restrict__ bias, const float* __restrict__ resid,
    const float* __restrict__ gam, const float* __restrict__ bet,
    float* __restrict__ outp, float* __restrict__ ornd, int M, int K)
{
    extern __shared__ float sm[];
    float* As = sm;
    float* Bs = sm + 2*LA_ST;
    float* Cs = sm;

    int tid = threadIdx.x;
    int wid = tid >> 5;
    int lane = tid & 31;
    int wr = wid & 1;
    int wc = wid >> 1;
    int m0 = blockIdx.x * LM;

    wmma::fragment<wmma::accumulator, 16, 16, 8, float> c[2][4];
    #pragma unroll
    for (int i = 0; i < 2; i++)
        #pragma unroll
        for (int j = 0; j < 4; j++)
            wmma::fill_fragment(c[i][j], 0.f);

    auto load_st = [&](int t, int b) {
        int k0 = t * LBK;
        float* as = As + b*LA_ST;
        float* bs = Bs + b*LB_ST;
        #pragma unroll
        for (int i = 0; i < 2; i++) {
            int cid = tid + i*256;
            int r = cid >> 3, c4 = cid & 7;
            cp_async16(&as[r*LLDA + c4*4], &A[(size_t)(m0 + r)*K + k0 + c4*4]);
        }
        #pragma unroll
        for (int i = 0; i < 8; i++) {
            int cid = tid + i*256;
            int r = cid >> 6, c4 = cid & 63;
            cp_async16(&bs[r*LLDB + c4*4], &W[(size_t)(k0 + r)*CDIM + c4*4]);
        }
        cp_commit();
    };

    int T = K / LBK;
    load_st(0, 0);
    for (int t = 0; t < T; t++) {
        int b = t & 1;
        if (t + 1 < T) {
            load_st(t + 1, b ^ 1);
            cp_wait<1>();
        } else {
            cp_wait<0>();
        }
        __syncthreads();
        const float* as = As + b*LA_ST;
        const float* bs = Bs + b*LB_ST;
        #pragma unroll
        for (int kk = 0; kk < LBK; kk += 8) {
            wmma::fragment<wmma::matrix_a, 16, 16, 8, wmma::precision::tf32, wmma::row_major> a[2];
            wmma::fragment<wmma::matrix_b, 16, 16, 8, wmma::precision::tf32, wmma::row_major> bfrag[4];
            #pragma unroll
            for (int i = 0; i < 2; i++)
                wmma::load_matrix_sync(a[i], &as[(wr*32 + i*16)*LLDA + kk], LLDA);
            #pragma unroll
            for (int j = 0; j < 4; j++)
                wmma::load_matrix_sync(bfrag[j], &bs[kk*LLDB + wc*64 + j*16], LLDB);
            #pragma unroll
            for (int i = 0; i < 2; i++)
                #pragma unroll
                for (int j = 0; j < 4; j++)
                    wmma::mma_sync(c[i][j], a[i], bfrag[j], c[i][j]);
        }
        __syncthreads();
    }

    #pragma unroll
    for (int i = 0; i < 2; i++)
        #pragma unroll
        for (int j = 0; j < 4; j++)
            wmma::store_matrix_sync(&Cs[(wr*32 + i*16)*LLDC + wc*64 + j*16],
                                    c[i][j], LLDC, wmma::mem_row_major);
    __syncthreads();

    float4 bv0 = *(const float4*)&bias[lane*8];
    float4 bv1 = *(const float4*)&bias[lane*8 + 4];
    float4 gv0 = *(const float4*)&gam[lane*8];
    float4 gv1 = *(const float4*)&gam[lane*8 + 4];
    float4 tv0 = *(const float4*)&bet[lane*8];
    float4 tv1 = *(const float4*)&bet[lane*8 + 4];

    #pragma unroll
    for (int i = 0; i < 8; i++) {
        int r = wid*8 + i;
        int m = m0 + r;
        float4 c0 = *(float4*)&Cs[r*LLDC + lane*8];
        float4 c1 = *(float4*)&Cs[r*LLDC + lane*8 + 4];
        float4 q0 = *(const float4*)&resid[(size_t)m*CDIM + lane*8];
        float4 q1 = *(const float4*)&resid[(size_t)m*CDIM + lane*8 + 4];
        float x0 = q0.x + c0.x + bv0.x, x1 = q0.y + c0.y + bv0.y;
        float x2 = q0.z + c0.z + bv0.z, x3 = q0.w + c0.w + bv0.w;
        float x4 = q1.x + c1.x + bv1.x, x5 = q1.y + c1.y + bv1.y;
        float x6 = q1.z + c1.z + bv1.z, x7 = q1.w + c1.w + bv1.w;
        float s = x0+x1+x2+x3+x4+x5+x6+x7;
        #pragma unroll
        for (int o = 16; o > 0; o >>= 1) s += __shfl_xor_sync(0xffffffffu, s, o);
        float mean = s * (1.f/CDIM);
        float d0 = x0-mean, d1 = x1-mean, d2 = x2-mean, d3 = x3-mean;
        float d4 = x4-mean, d5 = x5-mean, d6 = x6-mean, d7 = x7-mean;
        float sq = d0*d0+d1*d1+d2*d2+d3*d3+d4*d4+d5*d5+d6*d6+d7*d7;
        #pragma unroll
        for (int o = 16; o > 0; o >>= 1) sq += __shfl_xor_sync(0xffffffffu, sq, o);
        float rstd = rsqrtf(sq * (1.f/CDIM) + 1e-5f);
        float o0 = d0*rstd*gv0.x + tv0.x, o1 = d1*rstd*gv0.y + tv0.y;
        float o2 = d2*rstd*gv0.z + tv0.z, o3 = d3*rstd*gv0.w + tv0.w;
        float o4 = d4*rstd*gv1.x + tv1.x, o5 = d5*rstd*gv1.y + tv1.y;
        float o6 = d6*rstd*gv1.z + tv1.z, o7 = d7*rstd*gv1.w + tv1.w;
        *(float4*)&outp[(size_t)m*CDIM + lane*8]     = make_float4(o0, o1, o2, o3);
        *(float4*)&outp[(size_t)m*CDIM + lane*8 + 4] = make_float4(o4, o5, o6, o7);
        *(float4*)&ornd[(size_t)m*CDIM + lane*8]     = make_float4(tf32r(o0), tf32r(o1), tf32r(o2), tf32r(o3));
        *(float4*)&ornd[(size_t)m*CDIM + lane*8 + 4] = make_float4(tf32r(o4), tf32r(o5), tf32r(o6), tf32r(o7));
    }
}

// ---------------- geometry / prep ------------------------------------------------
__global__ void k_invert(const float* __restrict__ extr) {
    int c = threadIdx.x;
    if (c >= NCAM) return;
    float a[4][8];
    for (int i = 0; i < 4; i++)
        for (int j = 0; j < 4; j++) {
            a[i][j] = extr[c*16 + i*4 + j];
            a[i][j+4] = (i == j) ? 1.f : 0.f;
        }
    for (int col = 0; col < 4; col++) {
        int piv = col;
        for (int r = col+1; r < 4; r++)
            if (fabsf(a[r][col]) > fabsf(a[piv][col])) piv = r;
        if (piv != col)
            for (int j = 0; j < 8; j++) { float t = a[col][j]; a[col][j] = a[piv][j]; a[piv][j] = t; }
        float d = 1.f / a[col][col];
        for (int j = 0; j < 8; j++) a[col][j] *= d;
        for (int r = 0; r < 4; r++) {
            if (r == col) continue;
            float f = a[r][col];
            for (int j = 0; j < 8; j++) a[r][j] -= f * a[col][j];
        }
    }
    for (int i = 0; i < 4; i++)
        for (int j = 0; j < 4; j++)
            g_inv[c*16 + i*4 + j] = a[i][j+4];
}

__global__ void k_geom(const float* __restrict__ intr) {
    int idx = blockIdx.x * blockDim.x + threadIdx.x;
    if (idx >= NCAM*NQ*NPTS) return;
    int p = idx % NPTS;
    int n = (idx / NPTS) % NQ;
    int c = idx / (NPTS * NQ);
    float gx = ((n & 127) + 0.5f) / 128.f;
    float gy = ((n >> 7)  + 0.5f) / 128.f;
    float xm = -51.2f + gx * 102.4f;
    float ym = -51.2f + gy * 102.4f;
    float zm = -5.0f + (p + 0.5f) * 2.0f;
    const float* Mi = &g_inv[c*16];
    float px = Mi[0]*xm + Mi[1]*ym + Mi[2]*zm  + Mi[3];
    float py = Mi[4]*xm + Mi[5]*ym + Mi[6]*zm  + Mi[7];
    float pz = Mi[8]*xm + Mi[9]*ym + Mi[10]*zm + Mi[11];
    const float* I = &intr[c*9];
    float ix = I[0]*px + I[1]*py + I[2]*pz;
    float iy = I[3]*px + I[4]*py + I[5]*pz;
    float iz = I[6]*px + I[7]*py + I[8]*pz;
    float zc = fmaxf(iz, 1e-5f);
    float un = ix / (zc * WF);
    float vn = iy / (zc * HF);
    float val = (iz > 1e-5f && un >= 0.f && un <= 1.f && vn >= 0.f && vn <= 1.f) ? 1.f : 0.f;
    g_refcam[idx*2+0] = un;
    g_refcam[idx*2+1] = vn;
    g_valid[idx] = val;
}

__global__ void k_cnt() {
    int n = blockIdx.x * blockDim.x + threadIdx.x;
    if (n >= NQ) return;
    float s = 0.f;
    for (int c = 0; c < NCAM; c++)
        for (int p = 0; p < NPTS; p++)
            s += g_valid[(c*NQ + n)*NPTS + p];
    g_cnt[n] = fmaxf(s, 1.f);
}

__global__ void k_feats_t(const float* __restrict__ in) {
    __shared__ float tile[32][33];
    int pix0 = blockIdx.x * 32, ch0 = blockIdx.y * 32, c = blockIdx.z;
    int tx = threadIdx.x, ty = threadIdx.y;
    for (int i = ty; i < 32; i += 8) {
        int pix = pix0 + tx;
        tile[i][tx] = (pix < NPIX) ? in[((size_t)c*CDIM + ch0 + i)*NPIX + pix] : 0.f;
    }
    __syncthreads();
    for (int i = ty; i < 32; i += 8) {
        int pix = pix0 + i;
        if (pix < NPIX)
            g_feats[((size_t)c*NPIX + pix)*CDIM + ch0 + tx] = tf32r(tile[tx][i]);
    }
}

__global__ void k_round(const float* __restrict__ W, float* __restrict__ out, int n) {
    int i = blockIdx.x * blockDim.x + threadIdx.x;
    if (i < n) out[i] = tf32r(W[i]);
}

__global__ void k_prep_oa(const float* __restrict__ tow, const float* __restrict__ taw,
                          const float* __restrict__ sow, const float* __restrict__ saw,
                          const float* __restrict__ tob, const float* __restrict__ tab,
                          const float* __restrict__ sob, const float* __restrict__ sab) {
    int idx = blockIdx.x * blockDim.x + threadIdx.x;
    int total = 2*NLAYERS*CDIM*128;
    if (idx < total) {
        int n = idx % 128;
        int k = (idx / 128) % CDIM;
        int l = (idx / (128*CDIM)) % NLAYERS;
        int s = idx / (128*CDIM*NLAYERS);
        const float* ow = s ? sow : tow;
        const float* aw = s ? saw : taw;
        float w = 0.f;
        if (n < 64)      w = ow[((size_t)l*CDIM + k)*64 + n];
        else if (n < 96) w = aw[((size_t)l*CDIM + k)*32 + (n - 64)];
        g_oaw[idx] = tf32r(w);
    }
    if (idx < 2*NLAYERS*128) {
        int j = idx % 128;
        int l = (idx / 128) % NLAYERS;
        int s = idx / (128*NLAYERS);
        const float* ob = s ? sob : tob;
        const float* ab = s ? sab : tab;
        float b = 0.f;
        if (j < 64)      b = ob[l*64 + j];
        else if (j < 96) b = ab[l*32 + (j - 64)];
        g_oab[idx] = b;
    }
}

__global__ void k_init_q(const float* __restrict__ src) {
    int i = blockIdx.x * blockDim.x + threadIdx.x;
    if (i >= NQ*CDIM) return;
    float v = src[i];
    g_q[i] = v;
    g_q_rnd[i] = tf32r(v);
}

// ---------------- samplers --------------------------------------------------------
__device__ __forceinline__ float bilin(const float* __restrict__ base, int H, int W,
                                       int stride, float ix, float iy) {
    float x0f = floorf(ix), y0f = floorf(iy);
    int x0 = (int)x0f, y0 = (int)y0f;
    float fx = ix - x0f, fy = iy - y0f;
    float out = 0.f;
    #pragma unroll
    for (int dy = 0; dy < 2; dy++) {
        int yi = y0 + dy;
        if (yi < 0 || yi >= H) continue;
        float wy = dy ? fy : 1.f - fy;
        #pragma unroll
        for (int dx = 0; dx < 2; dx++) {
            int xi = x0 + dx;
            if (xi < 0 || xi >= W) continue;
            float wx = dx ? fx : 1.f - fx;
            out += wy * wx * base[((size_t)yi*W + xi) * stride];
        }
    }
    return out;
}

__global__ void k_tsa_sample() {
    int n = blockIdx.x;
    int h = threadIdx.x >> 5;
    int lane = threadIdx.x & 31;
    const float* oa = &g_offattn[n*96];
    float lg0 = oa[64 + h*4 + 0], lg1 = oa[64 + h*4 + 1];
    float lg2 = oa[64 + h*4 + 2], lg3 = oa[64 + h*4 + 3];
    float mx = fmaxf(fmaxf(lg0, lg1), fmaxf(lg2, lg3));
    float e0 = expf(lg0-mx), e1 = expf(lg1-mx), e2 = expf(lg2-mx), e3 = expf(lg3-mx);
    float rse = 1.f / (e0+e1+e2+e3);
    float w[4] = {e0*rse, e1*rse, e2*rse, e3*rse};
    float refx = ((n & 127) + 0.5f);
    float refy = ((n >> 7)  + 0.5f);
    const float* base = g_v + h*HD + lane;
    float acc = 0.f;
    #pragma unroll
    for (int p = 0; p < 4; p++) {
        float ox = oa[(h*4 + p)*2 + 0];
        float oy = oa[(h*4 + p)*2 + 1];
        acc += w[p] * bilin(base, 128, 128, CDIM, refx + ox - 0.5f, refy + oy - 0.5f);
    }
    g_a[(size_t)n*CDIM + h*HD + lane] = tf32r(acc);
}

__global__ void k_sca_sample() {
    int n = blockIdx.x;
    int h = threadIdx.x >> 5;
    int lane = threadIdx.x & 31;
    const float* oa = &g_offattn[n*96];
    float lg0 = oa[64 + h*4 + 0], lg1 = oa[64 + h*4 + 1];
    float lg2 = oa[64 + h*4 + 2], lg3 = oa[64 + h*4 + 3];
    float mx = fmaxf(fmaxf(lg0, lg1), fmaxf(lg2, lg3));
    float e0 = expf(lg0-mx), e1 = expf(lg1-mx), e2 = expf(lg2-mx), e3 = expf(lg3-mx);
    float rse = 1.f / (e0+e1+e2+e3);
    float w[4], ox[4], oy[4];
    w[0] = e0*rse; w[1] = e1*rse; w[2] = e2*rse; w[3] = e3*rse;
    #pragma unroll
    for (int p = 0; p < 4; p++) {
        ox[p] = oa[(h*4 + p)*2 + 0];
        oy[p] = oa[(h*4 + p)*2 + 1];
    }
    float acc = 0.f;
    for (int c = 0; c < NCAM; c++) {
        const float* rc = &g_refcam[((size_t)(c*NQ + n))*NPTS*2];
        const float* vv = &g_valid[((size_t)(c*NQ + n))*NPTS];
        const float* base = g_vimg + (size_t)c*NPIX*CDIM + h*HD + lane;
        #pragma unroll
        for (int p = 0; p < 4; p++) {
            if (vv[p] == 0.f) continue;
            float ix = rc[p*2+0]*WF + ox[p] - 0.5f;
            float iy = rc[p*2+1]*HF + oy[p] - 0.5f;
            acc += w[p] * bilin(base, HF, WF, CDIM, ix, iy);
        }
    }
    g_a[(size_t)n*CDIM + h*HD + lane] = tf32r(acc / g_cnt[n]);
}

__global__ void k_out_t(float* __restrict__ out) {
    __shared__ float tile[32][33];
    int n0 = blockIdx.x * 32, c0 = blockIdx.y * 32;
    int tx = threadIdx.x, ty = threadIdx.y;
    for (int i = ty; i < 32; i += 8)
        tile[i][tx] = g_q[(size_t)(n0 + i)*CDIM + c0 + tx];
    __syncthreads();
    for (int i = ty; i < 32; i += 8)
        out[(size_t)(c0 + i)*NQ + n0 + tx] = tile[tx][i];
}

// ---------------- host --------------------------------------------------------
static void gemm128_s(cudaStream_t st, const float* A, const float* B,
                      const float* bias, float* out,
                      int M, int N, int K, int ldb, bool relu) {
    dim3 g((M + TBM - 1) / TBM, (ldb + TBN - 1) / TBN);
    if (relu) k_gemm128<1, false><<<g, 256, T_SMEM, st>>>(A, A, B, bias, out, M, N, K, ldb);
    else      k_gemm128<0, false><<<g, 256, T_SMEM, st>>>(A, A, B, bias, out, M, N, K, ldb);
}
static void gemm128(const float* A, const float* B, const float* bias, float* out,
                    int M, int N, int K, int ldb, bool relu) {
    gemm128_s(0, A, B, bias, out, M, N, K, ldb, relu);
}
static void gemm128_avg(const float* A, const float* A2, const float* B,
                        const float* bias, float* out, int M, int N, int K, int ldb) {
    dim3 g((M + TBM - 1) / TBM, (ldb + TBN - 1) / TBN);
    k_gemm128<0, true><<<g, 256, T_SMEM>>>(A, A2, B, bias, out, M, N, K, ldb);
}
static void gemm64(const float* A, const float* B, const float* bias, float* out,
                   int M, int N, int K, int ldb) {
    k_gemm64<<<M / SBM, 256, S_SMEM>>>(A, B, bias, out, M, N, K, ldb);
}
static void gemm_ln(const float* A, const float* W, const float* bias,
                    const float* resid, const float* gam, const float* bet,
                    float* outp, float* ornd, int M, int K) {
    k_gemm_ln<<<M / LM, 256, L_SMEM>>>(A, W, bias, resid, gam, bet, outp, ornd, M, K);
}

extern "C" void kernel_launch(void* const* d_in, const int* in_sizes, int n_in,
                              void* d_out, int out_size) {
    static bool init_done = false;
    static cudaStream_t s2;
    static cudaEvent_t ev_fork[NLAYERS], ev_join[NLAYERS];
    if (!init_done) {
        cudaFuncSetAttribute((const void*)k_gemm128<0, false>, cudaFuncAttributeMaxDynamicSharedMemorySize, T_SMEM);
        cudaFuncSetAttribute((const void*)k_gemm128<1, false>, cudaFuncAttributeMaxDynamicSharedMemorySize, T_SMEM);
        cudaFuncSetAttribute((const void*)k_gemm128<0, true>,  cudaFuncAttributeMaxDynamicSharedMemorySize, T_SMEM);
        cudaFuncSetAttribute((const void*)k_gemm64,            cudaFuncAttributeMaxDynamicSharedMemorySize, S_SMEM);
        cudaFuncSetAttribute((const void*)k_gemm_ln,           cudaFuncAttributeMaxDynamicSharedMemorySize, L_SMEM);
        cudaStreamCreateWithFlags(&s2, cudaStreamNonBlocking);
        for (int l = 0; l < NLAYERS; l++) {
            cudaEventCreateWithFlags(&ev_fork[l], cudaEventDisableTiming);
            cudaEventCreateWithFlags(&ev_join[l], cudaEventDisableTiming);
        }
        init_done = true;
    }

    const float* image_feats = (const float*)d_in[0];
    const float* intr        = (const float*)d_in[1];
    const float* extr        = (const float*)d_in[2];
    const float* prev        = (const float*)d_in[3];
    const float* bev         = (const float*)d_in[4];
    const float* tsa_vw = (const float*)d_in[5];
    const float* tsa_vb = (const float*)d_in[6];
    const float* tsa_pw = (const float*)d_in[11];
    const float* tsa_pb = (const float*)d_in[12];
    const float* sca_vw = (const float*)d_in[13];
    const float* sca_vb = (const float*)d_in[14];
    const float* sca_pw = (const float*)d_in[19];
    const float* sca_pb = (const float*)d_in[20];
    const float* ffn_w1 = (const float*)d_in[21];
    const float* ffn_b1 = (const float*)d_in[22];
    const float* ffn_w2 = (const float*)d_in[23];
    const float* ffn_b2 = (const float*)d_in[24];
    const float* ln1_g  = (const float*)d_in[25];
    const float* ln1_b  = (const float*)d_in[26];
    const float* ln2_g  = (const float*)d_in[27];
    const float* ln2_b  = (const float*)d_in[28];
    const float* ln3_g  = (const float*)d_in[29];
    const float* ln3_b  = (const float*)d_in[30];

    float *q_, *qr_, *a_, *hid_, *v_, *vimg_, *oa_, *feats_;
    float *tvw_, *tpw_, *svw_, *spw_, *f1w_, *f2w_, *oaw_, *oab_;
    cudaGetSymbolAddress((void**)&q_,    g_q);
    cudaGetSymbolAddress((void**)&qr_,   g_q_rnd);
    cudaGetSymbolAddress((void**)&a_,    g_a);
    cudaGetSymbolAddress((void**)&hid_,  g_hid);
    cudaGetSymbolAddress((void**)&v_,    g_v);
    cudaGetSymbolAddress((void**)&vimg_, g_vimg);
    cudaGetSymbolAddress((void**)&oa_,   g_offattn);
    cudaGetSymbolAddress((void**)&feats_, g_feats);
    cudaGetSymbolAddress((void**)&tvw_,  g_tvw);
    cudaGetSymbolAddress((void**)&tpw_,  g_tpw);
    cudaGetSymbolAddress((void**)&svw_,  g_svw);
    cudaGetSymbolAddress((void**)&spw_,  g_spw);
    cudaGetSymbolAddress((void**)&f1w_,  g_f1w);
    cudaGetSymbolAddress((void**)&f2w_,  g_f2w);
    cudaGetSymbolAddress((void**)&oaw_,  g_oaw);
    cudaGetSymbolAddress((void**)&oab_,  g_oab);

    const int WB = 256;
    {
        dim3 gt((NPIX + 31)/32, CDIM/32, NCAM);
        k_feats_t<<<gt, dim3(32, 8)>>>(image_feats);                      // 1
    }
    k_round<<<(NLAYERS*CDIM*CDIM + WB-1)/WB, WB>>>(sca_vw, svw_, NLAYERS*CDIM*CDIM);  // 2
    k_invert<<<1, NCAM>>>(extr);                                          // 3
    gemm128(feats_, svw_, sca_vb, vimg_, NFEAT, CDIM, CDIM, CDIM, false); // 4 (profile slot)
    k_geom<<<(NCAM*NQ*NPTS + 255)/256, 256>>>(intr);
    k_cnt<<<(NQ + 255)/256, 256>>>();
    k_round<<<(NLAYERS*CDIM*CDIM + WB-1)/WB, WB>>>(tsa_vw, tvw_, NLAYERS*CDIM*CDIM);
    k_round<<<(NLAYERS*CDIM*CDIM + WB-1)/WB, WB>>>(tsa_pw, tpw_, NLAYERS*CDIM*CDIM);
    k_round<<<(NLAYERS*CDIM*CDIM + WB-1)/WB, WB>>>(sca_pw, spw_, NLAYERS*CDIM*CDIM);
    k_round<<<(NLAYERS*CDIM*FFN + WB-1)/WB, WB>>>(ffn_w1, f1w_, NLAYERS*CDIM*FFN);
    k_round<<<(NLAYERS*FFN*CDIM + WB-1)/WB, WB>>>(ffn_w2, f2w_, NLAYERS*FFN*CDIM);
    k_prep_oa<<<(2*NLAYERS*CDIM*128 + WB-1)/WB, WB>>>(
        (const float*)d_in[7], (const float*)d_in[9],
        (const float*)d_in[15], (const float*)d_in[17],
        (const float*)d_in[8], (const float*)d_in[10],
        (const float*)d_in[16], (const float*)d_in[18]);
    k_init_q<<<(NQ*CDIM + 255)/256, 256>>>(bev);

    for (int l = 0; l < NLAYERS; l++) {
        size_t wo = (size_t)l*CDIM*CDIM;

        if (l > 0) {
            cudaEventRecord(ev_fork[l], 0);
            cudaStreamWaitEvent(s2, ev_fork[l], 0);
            gemm128_s(s2, feats_, svw_ + wo, sca_vb + l*CDIM, vimg_,
                      NFEAT, CDIM, CDIM, CDIM, false);
            cudaEventRecord(ev_join[l], s2);
        }

        // ---- TSA (main stream) ----
        gemm128_avg(q_, prev, tvw_ + wo, tsa_vb + l*CDIM, v_, NQ, CDIM, CDIM, CDIM);
        gemm64(qr_, oaw_ + (size_t)l*CDIM*128, oab_ + l*128, oa_, NQ, 96, CDIM, 128);
        k_tsa_sample<<<NQ, 256>>>();
        gemm_ln(a_, tpw_ + wo, tsa_pb + l*CDIM, q_, ln1_g + l*CDIM, ln1_b + l*CDIM,
                q_, qr_, NQ, CDIM);

        // ---- SCA ----
        gemm64(qr_, oaw_ + (size_t)(NLAYERS + l)*CDIM*128, oab_ + (NLAYERS + l)*128,
               oa_, NQ, 96, CDIM, 128);
        if (l > 0)
            cudaStreamWaitEvent(0, ev_join[l], 0);
        k_sca_sample<<<NQ, 256>>>();
        gemm_ln(a_, spw_ + wo, sca_pb + l*CDIM, q_, ln2_g + l*CDIM, ln2_b + l*CDIM,
                q_, qr_, NQ, CDIM);

        // ---- FFN ----
        gemm128(qr_, f1w_ + (size_t)l*CDIM*FFN, ffn_b1 + l*FFN, hid_, NQ, FFN, CDIM, FFN, true);
        gemm_ln(hid_, f2w_ + (size_t)l*FFN*CDIM, ffn_b2 + l*CDIM, q_,
                ln3_g + l*CDIM, ln3_b + l*CDIM, q_, qr_, NQ, FFN);
    }

    k_out_t<<<dim3(NQ/32, CDIM/32), dim3(32, 8)>>>((float*)d_out);
}

// round 12
// speedup vs baseline: 1.0249x; 1.0249x over previous
#include <cuda_runtime.h>
#include <math.h>
#include <stdint.h>
#include <mma.h>

using namespace nvcuda;

#define NQ      16384
#define CDIM    256
#define HEADS   8
#define HD      32
#define NPTS    4
#define NLAYERS 6
#define NCAM    6
#define HF      58
#define WF      100
#define NPIX    (HF*WF)
#define NFEAT   (NCAM*NPIX)
#define FFN     512

// ---------------- scratch ----------------------------------------------------
__device__ __align__(256) float g_q[NQ*CDIM];
__device__ __align__(256) float g_q_rnd[NQ*CDIM];
__device__ __align__(256) float g_a[NQ*CDIM];
__device__ __align__(256) float g_hid[NQ*FFN];
__device__ __align__(256) float g_v[NQ*CDIM];
__device__ __align__(256) float g_vimg[NFEAT*CDIM];
__device__ __align__(256) float g_offattn[NQ*96];
__device__ __align__(256) float g_feats[NFEAT*CDIM];
__device__ __align__(256) float g_refcam[NCAM*NQ*NPTS*2];
__device__ __align__(256) float g_valid[NCAM*NQ*NPTS];
__device__ __align__(256) float g_cnt[NQ];
__device__ __align__(256) float g_inv[NCAM*16];
__device__ __align__(256) float g_tvw[NLAYERS*CDIM*CDIM];
__device__ __align__(256) float g_tpw[NLAYERS*CDIM*CDIM];
__device__ __align__(256) float g_svw[NLAYERS*CDIM*CDIM];
__device__ __align__(256) float g_spw[NLAYERS*CDIM*CDIM];
__device__ __align__(256) float g_f1w[NLAYERS*CDIM*FFN];
__device__ __align__(256) float g_f2w[NLAYERS*FFN*CDIM];
__device__ __align__(256) float g_oaw[2*NLAYERS*CDIM*128];
__device__ __align__(256) float g_oab[2*NLAYERS*128];

// ---------------- helpers ------------------------------------------------------
__device__ __forceinline__ float tf32r(float x) {
    float o;
    asm("cvt.rna.tf32.f32 %0, %1;" : "=f"(o) : "f"(x));
    return o;
}
__device__ __forceinline__ void cp_async16(void* sp, const void* gp) {
    uint32_t s = (uint32_t)__cvta_generic_to_shared(sp);
    asm volatile("cp.async.cg.shared.global [%0], [%1], 16;\n" :: "r"(s), "l"(gp));
}
__device__ __forceinline__ void cp_commit() { asm volatile("cp.async.commit_group;\n" ::: "memory"); }
template<int N> __device__ __forceinline__ void cp_wait() {
    asm volatile("cp.async.wait_group %0;\n" :: "n"(N) : "memory");
}

// ---------------- big tf32 GEMM: 128x128 tile, BK=32, 2-stage (R9 config) ------
#define TBM 128
#define TBN 128
#define TBK 32
#define TLDA 40
#define TLDB 136
#define TA_ST (TBM*TLDA)
#define TB_ST (TBK*TLDB)
#define TLDC 132
#define T_SMEM ((2*(TA_ST+TB_ST))*4)   // 75776 B

template<int EPI, bool AVG>
__global__ __launch_bounds__(256, 2) void k_gemm128(
    const float* __restrict__ A, const float* __restrict__ A2,
    const float* __restrict__ B,
    const float* __restrict__ bias, float* __restrict__ out,
    int M, int N, int K, int ldb)
{
    extern __shared__ float sm[];
    float* As = sm;
    float* Bs = sm + 2*TA_ST;
    float* Cs = sm;

    int tid = threadIdx.x;
    int wid = tid >> 5;
    int wr = wid & 1;
    int wc = wid >> 1;
    int m0 = blockIdx.x * TBM;
    int n0 = blockIdx.y * TBN;

    wmma::fragment<wmma::accumulator, 16, 16, 8, float> c[4][2];
    #pragma unroll
    for (int i = 0; i < 4; i++)
        #pragma unroll
        for (int j = 0; j < 2; j++)
            wmma::fill_fragment(c[i][j], 0.f);

    auto load_st = [&](int t, int b) {
        int k0 = t * TBK;
        float* as = As + b*TA_ST;
        float* bs = Bs + b*TB_ST;
        #pragma unroll
        for (int i = 0; i < 4; i++) {
            int cid = tid + i*256;
            int r = cid >> 3, c4 = cid & 7;
            int m = m0 + r; if (m >= M) m = M - 1;
            if (AVG) {
                float4 v1 = *(const float4*)&A[(size_t)m*K + k0 + c4*4];
                float4 v2 = *(const float4*)&A2[(size_t)m*K + k0 + c4*4];
                float4 v;
                v.x = tf32r(0.5f*(v1.x + v2.x));
                v.y = tf32r(0.5f*(v1.y + v2.y));
                v.z = tf32r(0.5f*(v1.z + v2.z));
                v.w = tf32r(0.5f*(v1.w + v2.w));
                *(float4*)&as[r*TLDA + c4*4] = v;
            } else {
                cp_async16(&as[r*TLDA + c4*4], &A[(size_t)m*K + k0 + c4*4]);
            }
        }
        #pragma unroll
        for (int i = 0; i < 4; i++) {
            int cid = tid + i*256;
            int r = cid >> 5, c4 = cid & 31;
            cp_async16(&bs[r*TLDB + c4*4], &B[(size_t)(k0 + r)*ldb + n0 + c4*4]);
        }
        cp_commit();
    };

    int T = K / TBK;
    load_st(0, 0);
    for (int t = 0; t < T; t++) {
        int b = t & 1;
        if (t + 1 < T) {
            load_st(t + 1, b ^ 1);
            cp_wait<1>();
        } else {
            cp_wait<0>();
        }
        __syncthreads();
        const float* as = As + b*TA_ST;
        const float* bs = Bs + b*TB_ST;
        #pragma unroll
        for (int kk = 0; kk < TBK; kk += 8) {
            wmma::fragment<wmma::matrix_a, 16, 16, 8, wmma::precision::tf32, wmma::row_major> a[4];
            wmma::fragment<wmma::matrix_b, 16, 16, 8, wmma::precision::tf32, wmma::row_major> bfrag[2];
            #pragma unroll
            for (int i = 0; i < 4; i++)
                wmma::load_matrix_sync(a[i], &as[(wr*64 + i*16)*TLDA + kk], TLDA);
            #pragma unroll
            for (int j = 0; j < 2; j++)
                wmma::load_matrix_sync(bfrag[j], &bs[kk*TLDB + wc*32 + j*16], TLDB);
            #pragma unroll
            for (int i = 0; i < 4; i++)
                #pragma unroll
                for (int j = 0; j < 2; j++)
                    wmma::mma_sync(c[i][j], a[i], bfrag[j], c[i][j]);
        }
        __syncthreads();
    }

    // chunked epilogue (64 rows at a time)
    int e4 = tid & 31, er = tid >> 5;
    int nn = n0 + e4*4;
    float4 bv = make_float4(0.f, 0.f, 0.f, 0.f);
    if (nn < N) bv = *(const float4*)&bias[nn];
    #pragma unroll
    for (int chunk = 0; chunk < 2; chunk++) {
        if (wr == chunk) {
            #pragma unroll
            for (int i = 0; i < 4; i++)
                #pragma unroll
                for (int j = 0; j < 2; j++)
                    wmma::store_matrix_sync(&Cs[(i*16)*TLDC + wc*32 + j*16],
                                            c[i][j], TLDC, wmma::mem_row_major);
        }
        __syncthreads();
        if (nn < N) {
            #pragma unroll
            for (int i = 0; i < 8; i++) {
                int r = er + i*8;
                int m = m0 + chunk*64 + r;
                if (m < M) {
                    float4 v = *(float4*)&Cs[r*TLDC + e4*4];
                    v.x += bv.x; v.y += bv.y; v.z += bv.z; v.w += bv.w;
                    if (EPI == 1) {
                        v.x = tf32r(fmaxf(v.x, 0.f)); v.y = tf32r(fmaxf(v.y, 0.f));
                        v.z = tf32r(fmaxf(v.z, 0.f)); v.w = tf32r(fmaxf(v.w, 0.f));
                    }
                    *(float4*)&out[(size_t)m*N + nn] = v;
                }
            }
        }
        __syncthreads();
    }
}

// ---------------- small GEMM: 64x128 tile (for N<=128), 2-stage ----------------
#define SBM 64
#define SBK 32
#define SLDA 36
#define SLDB 132
#define SA_ST (SBM*SLDA)
#define SB_ST (SBK*SLDB)
#define SLDC 132
#define S_SMEM (2*(SA_ST+SB_ST)*4)   // 52224 B

__global__ __launch_bounds__(256, 2) void k_gemm64(
    const float* __restrict__ A, const float* __restrict__ B,
    const float* __restrict__ bias, float* __restrict__ out,
    int M, int N, int K, int ldb)
{
    extern __shared__ float sm[];
    float* As = sm;
    float* Bs = sm + 2*SA_ST;
    float* Cs = sm;

    int tid = threadIdx.x;
    int wid = tid >> 5;
    int wr = wid & 1;
    int wc = wid >> 1;
    int m0 = blockIdx.x * SBM;

    wmma::fragment<wmma::accumulator, 16, 16, 8, float> c[2][2];
    #pragma unroll
    for (int i = 0; i < 2; i++)
        #pragma unroll
        for (int j = 0; j < 2; j++)
            wmma::fill_fragment(c[i][j], 0.f);

    auto load_st = [&](int t, int b) {
        int k0 = t * SBK;
        float* as = As + b*SA_ST;
        float* bs = Bs + b*SB_ST;
        #pragma unroll
        for (int i = 0; i < 2; i++) {
            int cid = tid + i*256;
            int r = cid >> 3, c4 = cid & 7;
            cp_async16(&as[r*SLDA + c4*4], &A[(size_t)(m0 + r)*K + k0 + c4*4]);
        }
        #pragma unroll
        for (int i = 0; i < 4; i++) {
            int cid = tid + i*256;
            int r = cid >> 5, c4 = cid & 31;
            cp_async16(&bs[r*SLDB + c4*4], &B[(size_t)(k0 + r)*ldb + c4*4]);
        }
        cp_commit();
    };

    int T = K / SBK;
    load_st(0, 0);
    for (int t = 0; t < T; t++) {
        int b = t & 1;
        if (t + 1 < T) {
            load_st(t + 1, b ^ 1);
            cp_wait<1>();
        } else {
            cp_wait<0>();
        }
        __syncthreads();
        const float* as = As + b*SA_ST;
        const float* bs = Bs + b*SB_ST;
        #pragma unroll
        for (int kk = 0; kk < SBK; kk += 8) {
            wmma::fragment<wmma::matrix_a, 16, 16, 8, wmma::precision::tf32, wmma::row_major> a[2];
            wmma::fragment<wmma::matrix_b, 16, 16, 8, wmma::precision::tf32, wmma::row_major> bfrag[2];
            #pragma unroll
            for (int i = 0; i < 2; i++)
                wmma::load_matrix_sync(a[i], &as[(wr*32 + i*16)*SLDA + kk], SLDA);
            #pragma unroll
            for (int j = 0; j < 2; j++)
                wmma::load_matrix_sync(bfrag[j], &bs[kk*SLDB + wc*32 + j*16], SLDB);
            #pragma unroll
            for (int i = 0; i < 2; i++)
                #pragma unroll
                for (int j = 0; j < 2; j++)
                    wmma::mma_sync(c[i][j], a[i], bfrag[j], c[i][j]);
        }
        __syncthreads();
    }

    #pragma unroll
    for (int i = 0; i < 2; i++)
        #pragma unroll
        for (int j = 0; j < 2; j++)
            wmma::store_matrix_sync(&Cs[(wr*32 + i*16)*SLDC + wc*32 + j*16],
                                    c[i][j], SLDC, wmma::mem_row_major);
    __syncthreads();

    int e4 = tid & 31, er = tid >> 5;
    int nn = e4*4;
    if (nn < N) {
        float4 bv = *(const float4*)&bias[nn];
        #pragma unroll
        for (int i = 0; i < 8; i++) {
            int r = er + i*8;
            int m = m0 + r;
            float4 v = *(float4*)&Cs[r*SLDC + e4*4];
            v.x += bv.x; v.y += bv.y; v.z += bv.z; v.w += bv.w;
            *(float4*)&out[(size_t)m*N + nn] = v;
        }
    }
}

// ---------------- fused GEMM + residual + LN (N=256), BK=32 pipelined ----------
#define LM 64
#define LBK 32
#define LLDA 40
#define LLDB 264
#define LA_ST (LM*LLDA)
#define LB_ST (LBK*LLDB)
#define LLDC 260
#define L_SMEM ((2*(LA_ST+LB_ST))*4)   // 88064 B

__global__ __launch_bounds__(256, 2) void k_gemm_ln(
    const float* __restrict__ A, const float* __restrict__ W,
    const float* __restrict__ bias, const float* __restrict__ resid,
    const float* __restrict__ gam, const float* __restrict__ bet,
    float* __restrict__ outp, float* __restrict__ ornd, int M, int K)
{
    extern __shared__ float sm[];
    float* As = sm;
    float* Bs = sm + 2*LA_ST;
    float* Cs = sm;

    int tid = threadIdx.x;
    int wid = tid >> 5;
    int lane = tid & 31;
    int wr = wid & 1;
    int wc = wid >> 1;
    int m0 = blockIdx.x * LM;

    wmma::fragment<wmma::accumulator, 16, 16, 8, float> c[2][4];
    #pragma unroll
    for (int i = 0; i < 2; i++)
        #pragma unroll
        for (int j = 0; j < 4; j++)
            wmma::fill_fragment(c[i][j], 0.f);

    auto load_st = [&](int t, int b) {
        int k0 = t * LBK;
        float* as = As + b*LA_ST;
        float* bs = Bs + b*LB_ST;
        #pragma unroll
        for (int i = 0; i < 2; i++) {
            int cid = tid + i*256;
            int r = cid >> 3, c4 = cid & 7;
            cp_async16(&as[r*LLDA + c4*4], &A[(size_t)(m0 + r)*K + k0 + c4*4]);
        }
        #pragma unroll
        for (int i = 0; i < 8; i++) {
            int cid = tid + i*256;
            int r = cid >> 6, c4 = cid & 63;
            cp_async16(&bs[r*LLDB + c4*4], &W[(size_t)(k0 + r)*CDIM + c4*4]);
        }
        cp_commit();
    };

    int T = K / LBK;
    load_st(0, 0);
    for (int t = 0; t < T; t++) {
        int b = t & 1;
        if (t + 1 < T) {
            load_st(t + 1, b ^ 1);
            cp_wait<1>();
        } else {
            cp_wait<0>();
        }
        __syncthreads();
        const float* as = As + b*LA_ST;
        const float* bs = Bs + b*LB_ST;
        #pragma unroll
        for (int kk = 0; kk < LBK; kk += 8) {
            wmma::fragment<wmma::matrix_a, 16, 16, 8, wmma::precision::tf32, wmma::row_major> a[2];
            wmma::fragment<wmma::matrix_b, 16, 16, 8, wmma::precision::tf32, wmma::row_major> bfrag[4];
            #pragma unroll
            for (int i = 0; i < 2; i++)
                wmma::load_matrix_sync(a[i], &as[(wr*32 + i*16)*LLDA + kk], LLDA);
            #pragma unroll
            for (int j = 0; j < 4; j++)
                wmma::load_matrix_sync(bfrag[j], &bs[kk*LLDB + wc*64 + j*16], LLDB);
            #pragma unroll
            for (int i = 0; i < 2; i++)
                #pragma unroll
                for (int j = 0; j < 4; j++)
                    wmma::mma_sync(c[i][j], a[i], bfrag[j], c[i][j]);
        }
        __syncthreads();
    }

    #pragma unroll
    for (int i = 0; i < 2; i++)
        #pragma unroll
        for (int j = 0; j < 4; j++)
            wmma::store_matrix_sync(&Cs[(wr*32 + i*16)*LLDC + wc*64 + j*16],
                                    c[i][j], LLDC, wmma::mem_row_major);
    __syncthreads();

    float4 bv0 = *(const float4*)&bias[lane*8];
    float4 bv1 = *(const float4*)&bias[lane*8 + 4];
    float4 gv0 = *(const float4*)&gam[lane*8];
    float4 gv1 = *(const float4*)&gam[lane*8 + 4];
    float4 tv0 = *(const float4*)&bet[lane*8];
    float4 tv1 = *(const float4*)&bet[lane*8 + 4];

    #pragma unroll
    for (int i = 0; i < 8; i++) {
        int r = wid*8 + i;
        int m = m0 + r;
        float4 c0 = *(float4*)&Cs[r*LLDC + lane*8];
        float4 c1 = *(float4*)&Cs[r*LLDC + lane*8 + 4];
        float4 q0 = *(const float4*)&resid[(size_t)m*CDIM + lane*8];
        float4 q1 = *(const float4*)&resid[(size_t)m*CDIM + lane*8 + 4];
        float x0 = q0.x + c0.x + bv0.x, x1 = q0.y + c0.y + bv0.y;
        float x2 = q0.z + c0.z + bv0.z, x3 = q0.w + c0.w + bv0.w;
        float x4 = q1.x + c1.x + bv1.x, x5 = q1.y + c1.y + bv1.y;
        float x6 = q1.z + c1.z + bv1.z, x7 = q1.w + c1.w + bv1.w;
        float s = x0+x1+x2+x3+x4+x5+x6+x7;
        #pragma unroll
        for (int o = 16; o > 0; o >>= 1) s += __shfl_xor_sync(0xffffffffu, s, o);
        float mean = s * (1.f/CDIM);
        float d0 = x0-mean, d1 = x1-mean, d2 = x2-mean, d3 = x3-mean;
        float d4 = x4-mean, d5 = x5-mean, d6 = x6-mean, d7 = x7-mean;
        float sq = d0*d0+d1*d1+d2*d2+d3*d3+d4*d4+d5*d5+d6*d6+d7*d7;
        #pragma unroll
        for (int o = 16; o > 0; o >>= 1) sq += __shfl_xor_sync(0xffffffffu, sq, o);
        float rstd = rsqrtf(sq * (1.f/CDIM) + 1e-5f);
        float o0 = d0*rstd*gv0.x + tv0.x, o1 = d1*rstd*gv0.y + tv0.y;
        float o2 = d2*rstd*gv0.z + tv0.z, o3 = d3*rstd*gv0.w + tv0.w;
        float o4 = d4*rstd*gv1.x + tv1.x, o5 = d5*rstd*gv1.y + tv1.y;
        float o6 = d6*rstd*gv1.z + tv1.z, o7 = d7*rstd*gv1.w + tv1.w;
        *(float4*)&outp[(size_t)m*CDIM + lane*8]     = make_float4(o0, o1, o2, o3);
        *(float4*)&outp[(size_t)m*CDIM + lane*8 + 4] = make_float4(o4, o5, o6, o7);
        *(float4*)&ornd[(size_t)m*CDIM + lane*8]     = make_float4(tf32r(o0), tf32r(o1), tf32r(o2), tf32r(o3));
        *(float4*)&ornd[(size_t)m*CDIM + lane*8 + 4] = make_float4(tf32r(o4), tf32r(o5), tf32r(o6), tf32r(o7));
    }
}

// ---------------- geometry / prep ------------------------------------------------
__global__ void k_invert(const float* __restrict__ extr) {
    int c = threadIdx.x;
    if (c >= NCAM) return;
    float a[4][8];
    for (int i = 0; i < 4; i++)
        for (int j = 0; j < 4; j++) {
            a[i][j] = extr[c*16 + i*4 + j];
            a[i][j+4] = (i == j) ? 1.f : 0.f;
        }
    for (int col = 0; col < 4; col++) {
        int piv = col;
        for (int r = col+1; r < 4; r++)
            if (fabsf(a[r][col]) > fabsf(a[piv][col])) piv = r;
        if (piv != col)
            for (int j = 0; j < 8; j++) { float t = a[col][j]; a[col][j] = a[piv][j]; a[piv][j] = t; }
        float d = 1.f / a[col][col];
        for (int j = 0; j < 8; j++) a[col][j] *= d;
        for (int r = 0; r < 4; r++) {
            if (r == col) continue;
            float f = a[r][col];
            for (int j = 0; j < 8; j++) a[r][j] -= f * a[col][j];
        }
    }
    for (int i = 0; i < 4; i++)
        for (int j = 0; j < 4; j++)
            g_inv[c*16 + i*4 + j] = a[i][j+4];
}

__global__ void k_geom(const float* __restrict__ intr) {
    int idx = blockIdx.x * blockDim.x + threadIdx.x;
    if (idx >= NCAM*NQ*NPTS) return;
    int p = idx % NPTS;
    int n = (idx / NPTS) % NQ;
    int c = idx / (NPTS * NQ);
    float gx = ((n & 127) + 0.5f) / 128.f;
    float gy = ((n >> 7)  + 0.5f) / 128.f;
    float xm = -51.2f + gx * 102.4f;
    float ym = -51.2f + gy * 102.4f;
    float zm = -5.0f + (p + 0.5f) * 2.0f;
    const float* Mi = &g_inv[c*16];
    float px = Mi[0]*xm + Mi[1]*ym + Mi[2]*zm  + Mi[3];
    float py = Mi[4]*xm + Mi[5]*ym + Mi[6]*zm  + Mi[7];
    float pz = Mi[8]*xm + Mi[9]*ym + Mi[10]*zm + Mi[11];
    const float* I = &intr[c*9];
    float ix = I[0]*px + I[1]*py + I[2]*pz;
    float iy = I[3]*px + I[4]*py + I[5]*pz;
    float iz = I[6]*px + I[7]*py + I[8]*pz;
    float zc = fmaxf(iz, 1e-5f);
    float un = ix / (zc * WF);
    float vn = iy / (zc * HF);
    float val = (iz > 1e-5f && un >= 0.f && un <= 1.f && vn >= 0.f && vn <= 1.f) ? 1.f : 0.f;
    g_refcam[idx*2+0] = un;
    g_refcam[idx*2+1] = vn;
    g_valid[idx] = val;
}

__global__ void k_cnt() {
    int n = blockIdx.x * blockDim.x + threadIdx.x;
    if (n >= NQ) return;
    float s = 0.f;
    for (int c = 0; c < NCAM; c++)
        for (int p = 0; p < NPTS; p++)
            s += g_valid[(c*NQ + n)*NPTS + p];
    g_cnt[n] = fmaxf(s, 1.f);
}

__global__ void k_feats_t(const float* __restrict__ in) {
    __shared__ float tile[32][33];
    int pix0 = blockIdx.x * 32, ch0 = blockIdx.y * 32, c = blockIdx.z;
    int tx = threadIdx.x, ty = threadIdx.y;
    for (int i = ty; i < 32; i += 8) {
        int pix = pix0 + tx;
        tile[i][tx] = (pix < NPIX) ? in[((size_t)c*CDIM + ch0 + i)*NPIX + pix] : 0.f;
    }
    __syncthreads();
    for (int i = ty; i < 32; i += 8) {
        int pix = pix0 + i;
        if (pix < NPIX)
            g_feats[((size_t)c*NPIX + pix)*CDIM + ch0 + tx] = tf32r(tile[tx][i]);
    }
}

__global__ void k_round(const float* __restrict__ W, float* __restrict__ out, int n) {
    int i = blockIdx.x * blockDim.x + threadIdx.x;
    if (i < n) out[i] = tf32r(W[i]);
}

__global__ void k_prep_oa(const float* __restrict__ tow, const float* __restrict__ taw,
                          const float* __restrict__ sow, const float* __restrict__ saw,
                          const float* __restrict__ tob, const float* __restrict__ tab,
                          const float* __restrict__ sob, const float* __restrict__ sab) {
    int idx = blockIdx.x * blockDim.x + threadIdx.x;
    int total = 2*NLAYERS*CDIM*128;
    if (idx < total) {
        int n = idx % 128;
        int k = (idx / 128) % CDIM;
        int l = (idx / (128*CDIM)) % NLAYERS;
        int s = idx / (128*CDIM*NLAYERS);
        const float* ow = s ? sow : tow;
        const float* aw = s ? saw : taw;
        float w = 0.f;
        if (n < 64)      w = ow[((size_t)l*CDIM + k)*64 + n];
        else if (n < 96) w = aw[((size_t)l*CDIM + k)*32 + (n - 64)];
        g_oaw[idx] = tf32r(w);
    }
    if (idx < 2*NLAYERS*128) {
        int j = idx % 128;
        int l = (idx / 128) % NLAYERS;
        int s = idx / (128*NLAYERS);
        const float* ob = s ? sob : tob;
        const float* ab = s ? sab : tab;
        float b = 0.f;
        if (j < 64)      b = ob[l*64 + j];
        else if (j < 96) b = ab[l*32 + (j - 64)];
        g_oab[idx] = b;
    }
}

__global__ void k_init_q(const float* __restrict__ src) {
    int i = blockIdx.x * blockDim.x + threadIdx.x;
    if (i >= NQ*CDIM) return;
    float v = src[i];
    g_q[i] = v;
    g_q_rnd[i] = tf32r(v);
}

// ---------------- samplers --------------------------------------------------------
__device__ __forceinline__ float bilin(const float* __restrict__ base, int H, int W,
                                       int stride, float ix, float iy) {
    float x0f = floorf(ix), y0f = floorf(iy);
    int x0 = (int)x0f, y0 = (int)y0f;
    float fx = ix - x0f, fy = iy - y0f;
    float out = 0.f;
    #pragma unroll
    for (int dy = 0; dy < 2; dy++) {
        int yi = y0 + dy;
        if (yi < 0 || yi >= H) continue;
        float wy = dy ? fy : 1.f - fy;
        #pragma unroll
        for (int dx = 0; dx < 2; dx++) {
            int xi = x0 + dx;
            if (xi < 0 || xi >= W) continue;
            float wx = dx ? fx : 1.f - fx;
            out += wy * wx * base[((size_t)yi*W + xi) * stride];
        }
    }
    return out;
}

__global__ void k_tsa_sample() {
    int n = blockIdx.x;
    int h = threadIdx.x >> 5;
    int lane = threadIdx.x & 31;
    const float* oa = &g_offattn[n*96];
    float lg0 = oa[64 + h*4 + 0], lg1 = oa[64 + h*4 + 1];
    float lg2 = oa[64 + h*4 + 2], lg3 = oa[64 + h*4 + 3];
    float mx = fmaxf(fmaxf(lg0, lg1), fmaxf(lg2, lg3));
    float e0 = expf(lg0-mx), e1 = expf(lg1-mx), e2 = expf(lg2-mx), e3 = expf(lg3-mx);
    float rse = 1.f / (e0+e1+e2+e3);
    float w[4] = {e0*rse, e1*rse, e2*rse, e3*rse};
    float refx = ((n & 127) + 0.5f);
    float refy = ((n >> 7)  + 0.5f);
    const float* base = g_v + h*HD + lane;
    float acc = 0.f;
    #pragma unroll
    for (int p = 0; p < 4; p++) {
        float ox = oa[(h*4 + p)*2 + 0];
        float oy = oa[(h*4 + p)*2 + 1];
        acc += w[p] * bilin(base, 128, 128, CDIM, refx + ox - 0.5f, refy + oy - 0.5f);
    }
    g_a[(size_t)n*CDIM + h*HD + lane] = tf32r(acc);
}

__global__ void k_sca_sample() {
    int n = blockIdx.x;
    int h = threadIdx.x >> 5;
    int lane = threadIdx.x & 31;
    const float* oa = &g_offattn[n*96];
    float lg0 = oa[64 + h*4 + 0], lg1 = oa[64 + h*4 + 1];
    float lg2 = oa[64 + h*4 + 2], lg3 = oa[64 + h*4 + 3];
    float mx = fmaxf(fmaxf(lg0, lg1), fmaxf(lg2, lg3));
    float e0 = expf(lg0-mx), e1 = expf(lg1-mx), e2 = expf(lg2-mx), e3 = expf(lg3-mx);
    float rse = 1.f / (e0+e1+e2+e3);
    float w[4], ox[4], oy[4];
    w[0] = e0*rse; w[1] = e1*rse; w[2] = e2*rse; w[3] = e3*rse;
    #pragma unroll
    for (int p = 0; p < 4; p++) {
        ox[p] = oa[(h*4 + p)*2 + 0];
        oy[p] = oa[(h*4 + p)*2 + 1];
    }
    float acc = 0.f;
    for (int c = 0; c < NCAM; c++) {
        const float* rc = &g_refcam[((size_t)(c*NQ + n))*NPTS*2];
        const float* vv = &g_valid[((size_t)(c*NQ + n))*NPTS];
        const float* base = g_vimg + (size_t)c*NPIX*CDIM + h*HD + lane;
        #pragma unroll
        for (int p = 0; p < 4; p++) {
            if (vv[p] == 0.f) continue;
            float ix = rc[p*2+0]*WF + ox[p] - 0.5f;
            float iy = rc[p*2+1]*HF + oy[p] - 0.5f;
            acc += w[p] * bilin(base, HF, WF, CDIM, ix, iy);
        }
    }
    g_a[(size_t)n*CDIM + h*HD + lane] = tf32r(acc / g_cnt[n]);
}

__global__ void k_out_t(float* __restrict__ out) {
    __shared__ float tile[32][33];
    int n0 = blockIdx.x * 32, c0 = blockIdx.y * 32;
    int tx = threadIdx.x, ty = threadIdx.y;
    for (int i = ty; i < 32; i += 8)
        tile[i][tx] = g_q[(size_t)(n0 + i)*CDIM + c0 + tx];
    __syncthreads();
    for (int i = ty; i < 32; i += 8)
        out[(size_t)(c0 + i)*NQ + n0 + tx] = tile[tx][i];
}

// ---------------- host --------------------------------------------------------
static void gemm128_s(cudaStream_t st, const float* A, const float* B,
                      const float* bias, float* out,
                      int M, int N, int K, int ldb, bool relu) {
    dim3 g((M + TBM - 1) / TBM, (ldb + TBN - 1) / TBN);
    if (relu) k_gemm128<1, false><<<g, 256, T_SMEM, st>>>(A, A, B, bias, out, M, N, K, ldb);
    else      k_gemm128<0, false><<<g, 256, T_SMEM, st>>>(A, A, B, bias, out, M, N, K, ldb);
}
static void gemm128(const float* A, const float* B, const float* bias, float* out,
                    int M, int N, int K, int ldb, bool relu) {
    gemm128_s(0, A, B, bias, out, M, N, K, ldb, relu);
}
static void gemm128_avg(const float* A, const float* A2, const float* B,
                        const float* bias, float* out, int M, int N, int K, int ldb) {
    dim3 g((M + TBM - 1) / TBM, (ldb + TBN - 1) / TBN);
    k_gemm128<0, true><<<g, 256, T_SMEM>>>(A, A2, B, bias, out, M, N, K, ldb);
}
static void gemm64(const float* A, const float* B, const float* bias, float* out,
                   int M, int N, int K, int ldb) {
    k_gemm64<<<M / SBM, 256, S_SMEM>>>(A, B, bias, out, M, N, K, ldb);
}
static void gemm_ln(const float* A, const float* W, const float* bias,
                    const float* resid, const float* gam, const float* bet,
                    float* outp, float* ornd, int M, int K) {
    k_gemm_ln<<<M / LM, 256, L_SMEM>>>(A, W, bias, resid, gam, bet, outp, ornd, M, K);
}

extern "C" void kernel_launch(void* const* d_in, const int* in_sizes, int n_in,
                              void* d_out, int out_size) {
    static bool init_done = false;
    static cudaStream_t s2;
    static cudaEvent_t ev_fork[NLAYERS], ev_join[NLAYERS];
    if (!init_done) {
        cudaFuncSetAttribute((const void*)k_gemm128<0, false>, cudaFuncAttributeMaxDynamicSharedMemorySize, T_SMEM);
        cudaFuncSetAttribute((const void*)k_gemm128<1, false>, cudaFuncAttributeMaxDynamicSharedMemorySize, T_SMEM);
        cudaFuncSetAttribute((const void*)k_gemm128<0, true>,  cudaFuncAttributeMaxDynamicSharedMemorySize, T_SMEM);
        cudaFuncSetAttribute((const void*)k_gemm64,            cudaFuncAttributeMaxDynamicSharedMemorySize, S_SMEM);
        cudaFuncSetAttribute((const void*)k_gemm_ln,           cudaFuncAttributeMaxDynamicSharedMemorySize, L_SMEM);
        cudaStreamCreateWithFlags(&s2, cudaStreamNonBlocking);
        for (int l = 0; l < NLAYERS; l++) {
            cudaEventCreateWithFlags(&ev_fork[l], cudaEventDisableTiming);
            cudaEventCreateWithFlags(&ev_join[l], cudaEventDisableTiming);
        }
        init_done = true;
    }

    const float* image_feats = (const float*)d_in[0];
    const float* intr        = (const float*)d_in[1];
    const float* extr        = (const float*)d_in[2];
    const float* prev        = (const float*)d_in[3];
    const float* bev         = (const float*)d_in[4];
    const float* tsa_vw = (const float*)d_in[5];
    const float* tsa_vb = (const float*)d_in[6];
    const float* tsa_pw = (const float*)d_in[11];
    const float* tsa_pb = (const float*)d_in[12];
    const float* sca_vw = (const float*)d_in[13];
    const float* sca_vb = (const float*)d_in[14];
    const float* sca_pw = (const float*)d_in[19];
    const float* sca_pb = (const float*)d_in[20];
    const float* ffn_w1 = (const float*)d_in[21];
    const float* ffn_b1 = (const float*)d_in[22];
    const float* ffn_w2 = (const float*)d_in[23];
    const float* ffn_b2 = (const float*)d_in[24];
    const float* ln1_g  = (const float*)d_in[25];
    const float* ln1_b  = (const float*)d_in[26];
    const float* ln2_g  = (const float*)d_in[27];
    const float* ln2_b  = (const float*)d_in[28];
    const float* ln3_g  = (const float*)d_in[29];
    const float* ln3_b  = (const float*)d_in[30];

    float *q_, *qr_, *a_, *hid_, *v_, *vimg_, *oa_, *feats_;
    float *tvw_, *tpw_, *svw_, *spw_, *f1w_, *f2w_, *oaw_, *oab_;
    cudaGetSymbolAddress((void**)&q_,    g_q);
    cudaGetSymbolAddress((void**)&qr_,   g_q_rnd);
    cudaGetSymbolAddress((void**)&a_,    g_a);
    cudaGetSymbolAddress((void**)&hid_,  g_hid);
    cudaGetSymbolAddress((void**)&v_,    g_v);
    cudaGetSymbolAddress((void**)&vimg_, g_vimg);
    cudaGetSymbolAddress((void**)&oa_,   g_offattn);
    cudaGetSymbolAddress((void**)&feats_, g_feats);
    cudaGetSymbolAddress((void**)&tvw_,  g_tvw);
    cudaGetSymbolAddress((void**)&tpw_,  g_tpw);
    cudaGetSymbolAddress((void**)&svw_,  g_svw);
    cudaGetSymbolAddress((void**)&spw_,  g_spw);
    cudaGetSymbolAddress((void**)&f1w_,  g_f1w);
    cudaGetSymbolAddress((void**)&f2w_,  g_f2w);
    cudaGetSymbolAddress((void**)&oaw_,  g_oaw);
    cudaGetSymbolAddress((void**)&oab_,  g_oab);

    const int WB = 256;
    {
        dim3 gt((NPIX + 31)/32, CDIM/32, NCAM);
        k_feats_t<<<gt, dim3(32, 8)>>>(image_feats);                      // 1
    }
    k_round<<<(NLAYERS*CDIM*CDIM + WB-1)/WB, WB>>>(sca_vw, svw_, NLAYERS*CDIM*CDIM);  // 2
    k_invert<<<1, NCAM>>>(extr);                                          // 3
    gemm128(feats_, svw_, sca_vb, vimg_, NFEAT, CDIM, CDIM, CDIM, false); // 4 (profile slot)
    k_geom<<<(NCAM*NQ*NPTS + 255)/256, 256>>>(intr);
    k_cnt<<<(NQ + 255)/256, 256>>>();
    k_round<<<(NLAYERS*CDIM*CDIM + WB-1)/WB, WB>>>(tsa_vw, tvw_, NLAYERS*CDIM*CDIM);
    k_round<<<(NLAYERS*CDIM*CDIM + WB-1)/WB, WB>>>(tsa_pw, tpw_, NLAYERS*CDIM*CDIM);
    k_round<<<(NLAYERS*CDIM*CDIM + WB-1)/WB, WB>>>(sca_pw, spw_, NLAYERS*CDIM*CDIM);
    k_round<<<(NLAYERS*CDIM*FFN + WB-1)/WB, WB>>>(ffn_w1, f1w_, NLAYERS*CDIM*FFN);
    k_round<<<(NLAYERS*FFN*CDIM + WB-1)/WB, WB>>>(ffn_w2, f2w_, NLAYERS*FFN*CDIM);
    k_prep_oa<<<(2*NLAYERS*CDIM*128 + WB-1)/WB, WB>>>(
        (const float*)d_in[7], (const float*)d_in[9],
        (const float*)d_in[15], (const float*)d_in[17],
        (const float*)d_in[8], (const float*)d_in[10],
        (const float*)d_in[16], (const float*)d_in[18]);
    k_init_q<<<(NQ*CDIM + 255)/256, 256>>>(bev);

    for (int l = 0; l < NLAYERS; l++) {
        size_t wo = (size_t)l*CDIM*CDIM;

        if (l > 0) {
            cudaEventRecord(ev_fork[l], 0);
            cudaStreamWaitEvent(s2, ev_fork[l], 0);
            gemm128_s(s2, feats_, svw_ + wo, sca_vb + l*CDIM, vimg_,
                      NFEAT, CDIM, CDIM, CDIM, false);
            cudaEventRecord(ev_join[l], s2);
        }

        // ---- TSA (main stream) ----
        gemm128_avg(q_, prev, tvw_ + wo, tsa_vb + l*CDIM, v_, NQ, CDIM, CDIM, CDIM);
        gemm64(qr_, oaw_ + (size_t)l*CDIM*128, oab_ + l*128, oa_, NQ, 96, CDIM, 128);
        k_tsa_sample<<<NQ, 256>>>();
        gemm_ln(a_, tpw_ + wo, tsa_pb + l*CDIM, q_, ln1_g + l*CDIM, ln1_b + l*CDIM,
                q_, qr_, NQ, CDIM);

        // ---- SCA ----
        gemm64(qr_, oaw_ + (size_t)(NLAYERS + l)*CDIM*128, oab_ + (NLAYERS + l)*128,
               oa_, NQ, 96, CDIM, 128);
        if (l > 0)
            cudaStreamWaitEvent(0, ev_join[l], 0);
        k_sca_sample<<<NQ, 256>>>();
        gemm_ln(a_, spw_ + wo, sca_pb + l*CDIM, q_, ln2_g + l*CDIM, ln2_b + l*CDIM,
                q_, qr_, NQ, CDIM);

        // ---- FFN ----
        gemm128(qr_, f1w_ + (size_t)l*CDIM*FFN, ffn_b1 + l*FFN, hid_, NQ, FFN, CDIM, FFN, true);
        gemm_ln(hid_, f2w_ + (size_t)l*FFN*CDIM, ffn_b2 + l*CDIM, q_,
                ln3_g + l*CDIM, ln3_b + l*CDIM, q_, qr_, NQ, FFN);
    }

    k_out_t<<<dim3(NQ/32, CDIM/32), dim3(32, 8)>>>((float*)d_out);
}

// round 13
// speedup vs baseline: 1.0253x; 1.0004x over previous
#include <cuda_runtime.h>
#include <math.h>
#include <stdint.h>
#include <mma.h>

using namespace nvcuda;

#define NQ      16384
#define CDIM    256
#define HEADS   8
#define HD      32
#define NPTS    4
#define NLAYERS 6
#define NCAM    6
#define HF      58
#define WF      100
#define NPIX    (HF*WF)
#define NFEAT   (NCAM*NPIX)
#define FFN     512

// ---------------- scratch ----------------------------------------------------
__device__ __align__(256) float g_q[NQ*CDIM];
__device__ __align__(256) float g_q_rnd[NQ*CDIM];
__device__ __align__(256) float g_a[NQ*CDIM];
__device__ __align__(256) float g_hid[NQ*FFN];
__device__ __align__(256) float g_v[NQ*CDIM];
__device__ __align__(256) float g_vimg[NFEAT*CDIM];
__device__ __align__(256) float g_offattn[NQ*96];
__device__ __align__(256) float g_feats[NFEAT*CDIM];
__device__ __align__(256) float g_refcam[NCAM*NQ*NPTS*2];
__device__ __align__(256) float g_valid[NCAM*NQ*NPTS];
__device__ __align__(256) float g_cnt[NQ];
__device__ __align__(256) float g_inv[NCAM*16];
__device__ __align__(256) float g_tvw[NLAYERS*CDIM*CDIM];
__device__ __align__(256) float g_tpw[NLAYERS*CDIM*CDIM];
__device__ __align__(256) float g_svw[NLAYERS*CDIM*CDIM];
__device__ __align__(256) float g_spw[NLAYERS*CDIM*CDIM];
__device__ __align__(256) float g_f1w[NLAYERS*CDIM*FFN];
__device__ __align__(256) float g_f2w[NLAYERS*FFN*CDIM];
__device__ __align__(256) float g_oaw[2*NLAYERS*CDIM*128];
__device__ __align__(256) float g_oab[2*NLAYERS*128];

// ---------------- helpers ------------------------------------------------------
__device__ __forceinline__ float tf32r(float x) {
    float o;
    asm("cvt.rna.tf32.f32 %0, %1;" : "=f"(o) : "f"(x));
    return o;
}
__device__ __forceinline__ void cp_async16(void* sp, const void* gp) {
    uint32_t s = (uint32_t)__cvta_generic_to_shared(sp);
    asm volatile("cp.async.cg.shared.global [%0], [%1], 16;\n" :: "r"(s), "l"(gp));
}
__device__ __forceinline__ void cp_commit() { asm volatile("cp.async.commit_group;\n" ::: "memory"); }
template<int N> __device__ __forceinline__ void cp_wait() {
    asm volatile("cp.async.wait_group %0;\n" :: "n"(N) : "memory");
}

// ---------------- big tf32 GEMM: 128x128 tile, BK=32, 2-stage (R9 config) ------
#define TBM 128
#define TBN 128
#define TBK 32
#define TLDA 40
#define TLDB 136
#define TA_ST (TBM*TLDA)
#define TB_ST (TBK*TLDB)
#define TLDC 132
#define T_SMEM ((2*(TA_ST+TB_ST))*4)   // 75776 B

template<int EPI, bool AVG>
__global__ __launch_bounds__(256, 2) void k_gemm128(
    const float* __restrict__ A, const float* __restrict__ A2,
    const float* __restrict__ B,
    const float* __restrict__ bias, float* __restrict__ out,
    int M, int N, int K, int ldb)
{
    extern __shared__ float sm[];
    float* As = sm;
    float* Bs = sm + 2*TA_ST;
    float* Cs = sm;

    int tid = threadIdx.x;
    int wid = tid >> 5;
    int wr = wid & 1;
    int wc = wid >> 1;
    int m0 = blockIdx.x * TBM;
    int n0 = blockIdx.y * TBN;

    wmma::fragment<wmma::accumulator, 16, 16, 8, float> c[4][2];
    #pragma unroll
    for (int i = 0; i < 4; i++)
        #pragma unroll
        for (int j = 0; j < 2; j++)
            wmma::fill_fragment(c[i][j], 0.f);

    auto load_st = [&](int t, int b) {
        int k0 = t * TBK;
        float* as = As + b*TA_ST;
        float* bs = Bs + b*TB_ST;
        #pragma unroll
        for (int i = 0; i < 4; i++) {
            int cid = tid + i*256;
            int r = cid >> 3, c4 = cid & 7;
            int m = m0 + r; if (m >= M) m = M - 1;
            if (AVG) {
                float4 v1 = *(const float4*)&A[(size_t)m*K + k0 + c4*4];
                float4 v2 = *(const float4*)&A2[(size_t)m*K + k0 + c4*4];
                float4 v;
                v.x = tf32r(0.5f*(v1.x + v2.x));
                v.y = tf32r(0.5f*(v1.y + v2.y));
                v.z = tf32r(0.5f*(v1.z + v2.z));
                v.w = tf32r(0.5f*(v1.w + v2.w));
                *(float4*)&as[r*TLDA + c4*4] = v;
            } else {
                cp_async16(&as[r*TLDA + c4*4], &A[(size_t)m*K + k0 + c4*4]);
            }
        }
        #pragma unroll
        for (int i = 0; i < 4; i++) {
            int cid = tid + i*256;
            int r = cid >> 5, c4 = cid & 31;
            cp_async16(&bs[r*TLDB + c4*4], &B[(size_t)(k0 + r)*ldb + n0 + c4*4]);
        }
        cp_commit();
    };

    int T = K / TBK;
    load_st(0, 0);
    for (int t = 0; t < T; t++) {
        int b = t & 1;
        if (t + 1 < T) {
            load_st(t + 1, b ^ 1);
            cp_wait<1>();
        } else {
            cp_wait<0>();
        }
        __syncthreads();
        const float* as = As + b*TA_ST;
        const float* bs = Bs + b*TB_ST;
        #pragma unroll
        for (int kk = 0; kk < TBK; kk += 8) {
            wmma::fragment<wmma::matrix_a, 16, 16, 8, wmma::precision::tf32, wmma::row_major> a[4];
            wmma::fragment<wmma::matrix_b, 16, 16, 8, wmma::precision::tf32, wmma::row_major> bfrag[2];
            #pragma unroll
            for (int i = 0; i < 4; i++)
                wmma::load_matrix_sync(a[i], &as[(wr*64 + i*16)*TLDA + kk], TLDA);
            #pragma unroll
            for (int j = 0; j < 2; j++)
                wmma::load_matrix_sync(bfrag[j], &bs[kk*TLDB + wc*32 + j*16], TLDB);
            #pragma unroll
            for (int i = 0; i < 4; i++)
                #pragma unroll
                for (int j = 0; j < 2; j++)
                    wmma::mma_sync(c[i][j], a[i], bfrag[j], c[i][j]);
        }
        __syncthreads();
    }

    int e4 = tid & 31, er = tid >> 5;
    int nn = n0 + e4*4;
    float4 bv = make_float4(0.f, 0.f, 0.f, 0.f);
    if (nn < N) bv = *(const float4*)&bias[nn];
    #pragma unroll
    for (int chunk = 0; chunk < 2; chunk++) {
        if (wr == chunk) {
            #pragma unroll
            for (int i = 0; i < 4; i++)
                #pragma unroll
                for (int j = 0; j < 2; j++)
                    wmma::store_matrix_sync(&Cs[(i*16)*TLDC + wc*32 + j*16],
                                            c[i][j], TLDC, wmma::mem_row_major);
        }
        __syncthreads();
        if (nn < N) {
            #pragma unroll
            for (int i = 0; i < 8; i++) {
                int r = er + i*8;
                int m = m0 + chunk*64 + r;
                if (m < M) {
                    float4 v = *(float4*)&Cs[r*TLDC + e4*4];
                    v.x += bv.x; v.y += bv.y; v.z += bv.z; v.w += bv.w;
                    if (EPI == 1) {
                        v.x = tf32r(fmaxf(v.x, 0.f)); v.y = tf32r(fmaxf(v.y, 0.f));
                        v.z = tf32r(fmaxf(v.z, 0.f)); v.w = tf32r(fmaxf(v.w, 0.f));
                    }
                    *(float4*)&out[(size_t)m*N + nn] = v;
                }
            }
        }
        __syncthreads();
    }
}

// ------- fused GEMM + residual + LN (N=256): 128-row tile, 512 threads ---------
// 16 warps: 4 warp-rows x 4 warp-cols, each 32x64. W loaded once per 128 rows.
#define LM 128
#define LBK 32
#define LLDA 40
#define LLDB 264
#define LA_ST (LM*LLDA)    // 5120 floats
#define LB_ST (LBK*LLDB)   // 8448 floats
#define LLDC 260
#define L_SMEM ((2*(LA_ST+LB_ST))*4)   // 108544 B

__global__ __launch_bounds__(512, 1) void k_gemm_ln(
    const float* __restrict__ A, const float* __restrict__ W,
    const float* __restrict__ bias, const float* __restrict__ resid,
    const float* __restrict__ gam, const float* __restrict__ bet,
    float* __restrict__ outp, float* __restrict__ ornd, int M, int K)
{
    extern __shared__ float sm[];
    float* As = sm;
    float* Bs = sm + 2*LA_ST;
    float* Cs = sm;

    int tid = threadIdx.x;
    int wid = tid >> 5;
    int lane = tid & 31;
    int wr = wid & 3;    // 4 warp-rows (32 rows each)
    int wc = wid >> 2;   // 4 warp-cols (64 cols each)
    int m0 = blockIdx.x * LM;

    wmma::fragment<wmma::accumulator, 16, 16, 8, float> c[2][4];
    #pragma unroll
    for (int i = 0; i < 2; i++)
        #pragma unroll
        for (int j = 0; j < 4; j++)
            wmma::fill_fragment(c[i][j], 0.f);

    auto load_st = [&](int t, int b) {
        int k0 = t * LBK;
        float* as = As + b*LA_ST;
        float* bs = Bs + b*LB_ST;
        #pragma unroll
        for (int i = 0; i < 2; i++) {
            int cid = tid + i*512;
            int r = cid >> 3, c4 = cid & 7;
            cp_async16(&as[r*LLDA + c4*4], &A[(size_t)(m0 + r)*K + k0 + c4*4]);
        }
        #pragma unroll
        for (int i = 0; i < 4; i++) {
            int cid = tid + i*512;
            int r = cid >> 6, c4 = cid & 63;
            cp_async16(&bs[r*LLDB + c4*4], &W[(size_t)(k0 + r)*CDIM + c4*4]);
        }
        cp_commit();
    };

    int T = K / LBK;
    load_st(0, 0);
    for (int t = 0; t < T; t++) {
        int b = t & 1;
        if (t + 1 < T) {
            load_st(t + 1, b ^ 1);
            cp_wait<1>();
        } else {
            cp_wait<0>();
        }
        __syncthreads();
        const float* as = As + b*LA_ST;
        const float* bs = Bs + b*LB_ST;
        #pragma unroll
        for (int kk = 0; kk < LBK; kk += 8) {
            wmma::fragment<wmma::matrix_a, 16, 16, 8, wmma::precision::tf32, wmma::row_major> a[2];
            wmma::fragment<wmma::matrix_b, 16, 16, 8, wmma::precision::tf32, wmma::row_major> bfrag[4];
            #pragma unroll
            for (int i = 0; i < 2; i++)
                wmma::load_matrix_sync(a[i], &as[(wr*32 + i*16)*LLDA + kk], LLDA);
            #pragma unroll
            for (int j = 0; j < 4; j++)
                wmma::load_matrix_sync(bfrag[j], &bs[kk*LLDB + wc*64 + j*16], LLDB);
            #pragma unroll
            for (int i = 0; i < 2; i++)
                #pragma unroll
                for (int j = 0; j < 4; j++)
                    wmma::mma_sync(c[i][j], a[i], bfrag[j], c[i][j]);
        }
        __syncthreads();
    }

    // chunked LN epilogue: 64 rows at a time (Cs = 64x260 fits pipeline smem)
    float4 bv0 = *(const float4*)&bias[lane*8];
    float4 bv1 = *(const float4*)&bias[lane*8 + 4];
    float4 gv0 = *(const float4*)&gam[lane*8];
    float4 gv1 = *(const float4*)&gam[lane*8 + 4];
    float4 tv0 = *(const float4*)&bet[lane*8];
    float4 tv1 = *(const float4*)&bet[lane*8 + 4];

    #pragma unroll
    for (int chunk = 0; chunk < 2; chunk++) {
        // warps with wr in {2*chunk, 2*chunk+1} own rows [chunk*64, chunk*64+64)
        if ((wr >> 1) == chunk) {
            #pragma unroll
            for (int i = 0; i < 2; i++)
                #pragma unroll
                for (int j = 0; j < 4; j++)
                    wmma::store_matrix_sync(&Cs[((wr & 1)*32 + i*16)*LLDC + wc*64 + j*16],
                                            c[i][j], LLDC, wmma::mem_row_major);
        }
        __syncthreads();
        // 16 warps x 4 rows = 64 rows
        #pragma unroll
        for (int i = 0; i < 4; i++) {
            int r = wid*4 + i;            // 0..63 within chunk
            int m = m0 + chunk*64 + r;
            float4 c0 = *(float4*)&Cs[r*LLDC + lane*8];
            float4 c1 = *(float4*)&Cs[r*LLDC + lane*8 + 4];
            float4 q0 = *(const float4*)&resid[(size_t)m*CDIM + lane*8];
            float4 q1 = *(const float4*)&resid[(size_t)m*CDIM + lane*8 + 4];
            float x0 = q0.x + c0.x + bv0.x, x1 = q0.y + c0.y + bv0.y;
            float x2 = q0.z + c0.z + bv0.z, x3 = q0.w + c0.w + bv0.w;
            float x4 = q1.x + c1.x + bv1.x, x5 = q1.y + c1.y + bv1.y;
            float x6 = q1.z + c1.z + bv1.z, x7 = q1.w + c1.w + bv1.w;
            float s = x0+x1+x2+x3+x4+x5+x6+x7;
            #pragma unroll
            for (int o = 16; o > 0; o >>= 1) s += __shfl_xor_sync(0xffffffffu, s, o);
            float mean = s * (1.f/CDIM);
            float d0 = x0-mean, d1 = x1-mean, d2 = x2-mean, d3 = x3-mean;
            float d4 = x4-mean, d5 = x5-mean, d6 = x6-mean, d7 = x7-mean;
            float sq = d0*d0+d1*d1+d2*d2+d3*d3+d4*d4+d5*d5+d6*d6+d7*d7;
            #pragma unroll
            for (int o = 16; o > 0; o >>= 1) sq += __shfl_xor_sync(0xffffffffu, sq, o);
            float rstd = rsqrtf(sq * (1.f/CDIM) + 1e-5f);
            float o0 = d0*rstd*gv0.x + tv0.x, o1 = d1*rstd*gv0.y + tv0.y;
            float o2 = d2*rstd*gv0.z + tv0.z, o3 = d3*rstd*gv0.w + tv0.w;
            float o4 = d4*rstd*gv1.x + tv1.x, o5 = d5*rstd*gv1.y + tv1.y;
            float o6 = d6*rstd*gv1.z + tv1.z, o7 = d7*rstd*gv1.w + tv1.w;
            *(float4*)&outp[(size_t)m*CDIM + lane*8]     = make_float4(o0, o1, o2, o3);
            *(float4*)&outp[(size_t)m*CDIM + lane*8 + 4] = make_float4(o4, o5, o6, o7);
            *(float4*)&ornd[(size_t)m*CDIM + lane*8]     = make_float4(tf32r(o0), tf32r(o1), tf32r(o2), tf32r(o3));
            *(float4*)&ornd[(size_t)m*CDIM + lane*8 + 4] = make_float4(tf32r(o4), tf32r(o5), tf32r(o6), tf32r(o7));
        }
        __syncthreads();
    }
}

// ---------------- geometry / prep ------------------------------------------------
__global__ void k_invert(const float* __restrict__ extr) {
    int c = threadIdx.x;
    if (c >= NCAM) return;
    float a[4][8];
    for (int i = 0; i < 4; i++)
        for (int j = 0; j < 4; j++) {
            a[i][j] = extr[c*16 + i*4 + j];
            a[i][j+4] = (i == j) ? 1.f : 0.f;
        }
    for (int col = 0; col < 4; col++) {
        int piv = col;
        for (int r = col+1; r < 4; r++)
            if (fabsf(a[r][col]) > fabsf(a[piv][col])) piv = r;
        if (piv != col)
            for (int j = 0; j < 8; j++) { float t = a[col][j]; a[col][j] = a[piv][j]; a[piv][j] = t; }
        float d = 1.f / a[col][col];
        for (int j = 0; j < 8; j++) a[col][j] *= d;
        for (int r = 0; r < 4; r++) {
            if (r == col) continue;
            float f = a[r][col];
            for (int j = 0; j < 8; j++) a[r][j] -= f * a[col][j];
        }
    }
    for (int i = 0; i < 4; i++)
        for (int j = 0; j < 4; j++)
            g_inv[c*16 + i*4 + j] = a[i][j+4];
}

__global__ void k_geom(const float* __restrict__ intr) {
    int idx = blockIdx.x * blockDim.x + threadIdx.x;
    if (idx >= NCAM*NQ*NPTS) return;
    int p = idx % NPTS;
    int n = (idx / NPTS) % NQ;
    int c = idx / (NPTS * NQ);
    float gx = ((n & 127) + 0.5f) / 128.f;
    float gy = ((n >> 7)  + 0.5f) / 128.f;
    float xm = -51.2f + gx * 102.4f;
    float ym = -51.2f + gy * 102.4f;
    float zm = -5.0f + (p + 0.5f) * 2.0f;
    const float* Mi = &g_inv[c*16];
    float px = Mi[0]*xm + Mi[1]*ym + Mi[2]*zm  + Mi[3];
    float py = Mi[4]*xm + Mi[5]*ym + Mi[6]*zm  + Mi[7];
    float pz = Mi[8]*xm + Mi[9]*ym + Mi[10]*zm + Mi[11];
    const float* I = &intr[c*9];
    float ix = I[0]*px + I[1]*py + I[2]*pz;
    float iy = I[3]*px + I[4]*py + I[5]*pz;
    float iz = I[6]*px + I[7]*py + I[8]*pz;
    float zc = fmaxf(iz, 1e-5f);
    float un = ix / (zc * WF);
    float vn = iy / (zc * HF);
    float val = (iz > 1e-5f && un >= 0.f && un <= 1.f && vn >= 0.f && vn <= 1.f) ? 1.f : 0.f;
    g_refcam[idx*2+0] = un;
    g_refcam[idx*2+1] = vn;
    g_valid[idx] = val;
}

__global__ void k_cnt() {
    int n = blockIdx.x * blockDim.x + threadIdx.x;
    if (n >= NQ) return;
    float s = 0.f;
    for (int c = 0; c < NCAM; c++)
        for (int p = 0; p < NPTS; p++)
            s += g_valid[(c*NQ + n)*NPTS + p];
    g_cnt[n] = fmaxf(s, 1.f);
}

__global__ void k_feats_t(const float* __restrict__ in) {
    __shared__ float tile[32][33];
    int pix0 = blockIdx.x * 32, ch0 = blockIdx.y * 32, c = blockIdx.z;
    int tx = threadIdx.x, ty = threadIdx.y;
    for (int i = ty; i < 32; i += 8) {
        int pix = pix0 + tx;
        tile[i][tx] = (pix < NPIX) ? in[((size_t)c*CDIM + ch0 + i)*NPIX + pix] : 0.f;
    }
    __syncthreads();
    for (int i = ty; i < 32; i += 8) {
        int pix = pix0 + i;
        if (pix < NPIX)
            g_feats[((size_t)c*NPIX + pix)*CDIM + ch0 + tx] = tf32r(tile[tx][i]);
    }
}

__global__ void k_round(const float* __restrict__ W, float* __restrict__ out, int n) {
    int i = blockIdx.x * blockDim.x + threadIdx.x;
    if (i < n) out[i] = tf32r(W[i]);
}

__global__ void k_prep_oa(const float* __restrict__ tow, const float* __restrict__ taw,
                          const float* __restrict__ sow, const float* __restrict__ saw,
                          const float* __restrict__ tob, const float* __restrict__ tab,
                          const float* __restrict__ sob, const float* __restrict__ sab) {
    int idx = blockIdx.x * blockDim.x + threadIdx.x;
    int total = 2*NLAYERS*CDIM*128;
    if (idx < total) {
        int n = idx % 128;
        int k = (idx / 128) % CDIM;
        int l = (idx / (128*CDIM)) % NLAYERS;
        int s = idx / (128*CDIM*NLAYERS);
        const float* ow = s ? sow : tow;
        const float* aw = s ? saw : taw;
        float w = 0.f;
        if (n < 64)      w = ow[((size_t)l*CDIM + k)*64 + n];
        else if (n < 96) w = aw[((size_t)l*CDIM + k)*32 + (n - 64)];
        g_oaw[idx] = tf32r(w);
    }
    if (idx < 2*NLAYERS*128) {
        int j = idx % 128;
        int l = (idx / 128) % NLAYERS;
        int s = idx / (128*NLAYERS);
        const float* ob = s ? sob : tob;
        const float* ab = s ? sab : tab;
        float b = 0.f;
        if (j < 64)      b = ob[l*64 + j];
        else if (j < 96) b = ab[l*32 + (j - 64)];
        g_oab[idx] = b;
    }
}

__global__ void k_init_q(const float* __restrict__ src) {
    int i = blockIdx.x * blockDim.x + threadIdx.x;
    if (i >= NQ*CDIM) return;
    float v = src[i];
    g_q[i] = v;
    g_q_rnd[i] = tf32r(v);
}

// ---------------- samplers --------------------------------------------------------
__device__ __forceinline__ float bilin(const float* __restrict__ base, int H, int W,
                                       int stride, float ix, float iy) {
    float x0f = floorf(ix), y0f = floorf(iy);
    int x0 = (int)x0f, y0 = (int)y0f;
    float fx = ix - x0f, fy = iy - y0f;
    float out = 0.f;
    #pragma unroll
    for (int dy = 0; dy < 2; dy++) {
        int yi = y0 + dy;
        if (yi < 0 || yi >= H) continue;
        float wy = dy ? fy : 1.f - fy;
        #pragma unroll
        for (int dx = 0; dx < 2; dx++) {
            int xi = x0 + dx;
            if (xi < 0 || xi >= W) continue;
            float wx = dx ? fx : 1.f - fx;
            out += wy * wx * base[((size_t)yi*W + xi) * stride];
        }
    }
    return out;
}

__global__ void k_tsa_sample() {
    int n = blockIdx.x;
    int h = threadIdx.x >> 5;
    int lane = threadIdx.x & 31;
    const float* oa = &g_offattn[n*96];
    float lg0 = oa[64 + h*4 + 0], lg1 = oa[64 + h*4 + 1];
    float lg2 = oa[64 + h*4 + 2], lg3 = oa[64 + h*4 + 3];
    float mx = fmaxf(fmaxf(lg0, lg1), fmaxf(lg2, lg3));
    float e0 = expf(lg0-mx), e1 = expf(lg1-mx), e2 = expf(lg2-mx), e3 = expf(lg3-mx);
    float rse = 1.f / (e0+e1+e2+e3);
    float w[4] = {e0*rse, e1*rse, e2*rse, e3*rse};
    float refx = ((n & 127) + 0.5f);
    float refy = ((n >> 7)  + 0.5f);
    const float* base = g_v + h*HD + lane;
    float acc = 0.f;
    #pragma unroll
    for (int p = 0; p < 4; p++) {
        float ox = oa[(h*4 + p)*2 + 0];
        float oy = oa[(h*4 + p)*2 + 1];
        acc += w[p] * bilin(base, 128, 128, CDIM, refx + ox - 0.5f, refy + oy - 0.5f);
    }
    g_a[(size_t)n*CDIM + h*HD + lane] = tf32r(acc);
}

__global__ void k_sca_sample() {
    int n = blockIdx.x;
    int h = threadIdx.x >> 5;
    int lane = threadIdx.x & 31;
    const float* oa = &g_offattn[n*96];
    float lg0 = oa[64 + h*4 + 0], lg1 = oa[64 + h*4 + 1];
    float lg2 = oa[64 + h*4 + 2], lg3 = oa[64 + h*4 + 3];
    float mx = fmaxf(fmaxf(lg0, lg1), fmaxf(lg2, lg3));
    float e0 = expf(lg0-mx), e1 = expf(lg1-mx), e2 = expf(lg2-mx), e3 = expf(lg3-mx);
    float rse = 1.f / (e0+e1+e2+e3);
    float w[4], ox[4], oy[4];
    w[0] = e0*rse; w[1] = e1*rse; w[2] = e2*rse; w[3] = e3*rse;
    #pragma unroll
    for (int p = 0; p < 4; p++) {
        ox[p] = oa[(h*4 + p)*2 + 0];
        oy[p] = oa[(h*4 + p)*2 + 1];
    }
    float acc = 0.f;
    for (int c = 0; c < NCAM; c++) {
        const float* rc = &g_refcam[((size_t)(c*NQ + n))*NPTS*2];
        const float* vv = &g_valid[((size_t)(c*NQ + n))*NPTS];
        const float* base = g_vimg + (size_t)c*NPIX*CDIM + h*HD + lane;
        #pragma unroll
        for (int p = 0; p < 4; p++) {
            if (vv[p] == 0.f) continue;
            float ix = rc[p*2+0]*WF + ox[p] - 0.5f;
            float iy = rc[p*2+1]*HF + oy[p] - 0.5f;
            acc += w[p] * bilin(base, HF, WF, CDIM, ix, iy);
        }
    }
    g_a[(size_t)n*CDIM + h*HD + lane] = tf32r(acc / g_cnt[n]);
}

__global__ void k_out_t(float* __restrict__ out) {
    __shared__ float tile[32][33];
    int n0 = blockIdx.x * 32, c0 = blockIdx.y * 32;
    int tx = threadIdx.x, ty = threadIdx.y;
    for (int i = ty; i < 32; i += 8)
        tile[i][tx] = g_q[(size_t)(n0 + i)*CDIM + c0 + tx];
    __syncthreads();
    for (int i = ty; i < 32; i += 8)
        out[(size_t)(c0 + i)*NQ + n0 + tx] = tile[tx][i];
}

// ---------------- host --------------------------------------------------------
static void gemm128_s(cudaStream_t st, const float* A, const float* B,
                      const float* bias, float* out,
                      int M, int N, int K, int ldb, bool relu) {
    dim3 g((M + TBM - 1) / TBM, (ldb + TBN - 1) / TBN);
    if (relu) k_gemm128<1, false><<<g, 256, T_SMEM, st>>>(A, A, B, bias, out, M, N, K, ldb);
    else      k_gemm128<0, false><<<g, 256, T_SMEM, st>>>(A, A, B, bias, out, M, N, K, ldb);
}
static void gemm128(const float* A, const float* B, const float* bias, float* out,
                    int M, int N, int K, int ldb, bool relu) {
    gemm128_s(0, A, B, bias, out, M, N, K, ldb, relu);
}
static void gemm128_avg(const float* A, const float* A2, const float* B,
                        const float* bias, float* out, int M, int N, int K, int ldb) {
    dim3 g((M + TBM - 1) / TBM, (ldb + TBN - 1) / TBN);
    k_gemm128<0, true><<<g, 256, T_SMEM>>>(A, A2, B, bias, out, M, N, K, ldb);
}
static void gemm_ln(const float* A, const float* W, const float* bias,
                    const float* resid, const float* gam, const float* bet,
                    float* outp, float* ornd, int M, int K) {
    k_gemm_ln<<<M / LM, 512, L_SMEM>>>(A, W, bias, resid, gam, bet, outp, ornd, M, K);
}

extern "C" void kernel_launch(void* const* d_in, const int* in_sizes, int n_in,
                              void* d_out, int out_size) {
    static bool init_done = false;
    static cudaStream_t s2;
    static cudaEvent_t ev_fork[NLAYERS], ev_join[NLAYERS];
    if (!init_done) {
        cudaFuncSetAttribute((const void*)k_gemm128<0, false>, cudaFuncAttributeMaxDynamicSharedMemorySize, T_SMEM);
        cudaFuncSetAttribute((const void*)k_gemm128<1, false>, cudaFuncAttributeMaxDynamicSharedMemorySize, T_SMEM);
        cudaFuncSetAttribute((const void*)k_gemm128<0, true>,  cudaFuncAttributeMaxDynamicSharedMemorySize, T_SMEM);
        cudaFuncSetAttribute((const void*)k_gemm_ln,           cudaFuncAttributeMaxDynamicSharedMemorySize, L_SMEM);
        cudaStreamCreateWithFlags(&s2, cudaStreamNonBlocking);
        for (int l = 0; l < NLAYERS; l++) {
            cudaEventCreateWithFlags(&ev_fork[l], cudaEventDisableTiming);
            cudaEventCreateWithFlags(&ev_join[l], cudaEventDisableTiming);
        }
        init_done = true;
    }

    const float* image_feats = (const float*)d_in[0];
    const float* intr        = (const float*)d_in[1];
    const float* extr        = (const float*)d_in[2];
    const float* prev        = (const float*)d_in[3];
    const float* bev         = (const float*)d_in[4];
    const float* tsa_vw = (const float*)d_in[5];
    const float* tsa_vb = (const float*)d_in[6];
    const float* tsa_pw = (const float*)d_in[11];
    const float* tsa_pb = (const float*)d_in[12];
    const float* sca_vw = (const float*)d_in[13];
    const float* sca_vb = (const float*)d_in[14];
    const float* sca_pw = (const float*)d_in[19];
    const float* sca_pb = (const float*)d_in[20];
    const float* ffn_w1 = (const float*)d_in[21];
    const float* ffn_b1 = (const float*)d_in[22];
    const float* ffn_w2 = (const float*)d_in[23];
    const float* ffn_b2 = (const float*)d_in[24];
    const float* ln1_g  = (const float*)d_in[25];
    const float* ln1_b  = (const float*)d_in[26];
    const float* ln2_g  = (const float*)d_in[27];
    const float* ln2_b  = (const float*)d_in[28];
    const float* ln3_g  = (const float*)d_in[29];
    const float* ln3_b  = (const float*)d_in[30];

    float *q_, *qr_, *a_, *hid_, *v_, *vimg_, *oa_, *feats_;
    float *tvw_, *tpw_, *svw_, *spw_, *f1w_, *f2w_, *oaw_, *oab_;
    cudaGetSymbolAddress((void**)&q_,    g_q);
    cudaGetSymbolAddress((void**)&qr_,   g_q_rnd);
    cudaGetSymbolAddress((void**)&a_,    g_a);
    cudaGetSymbolAddress((void**)&hid_,  g_hid);
    cudaGetSymbolAddress((void**)&v_,    g_v);
    cudaGetSymbolAddress((void**)&vimg_, g_vimg);
    cudaGetSymbolAddress((void**)&oa_,   g_offattn);
    cudaGetSymbolAddress((void**)&feats_, g_feats);
    cudaGetSymbolAddress((void**)&tvw_,  g_tvw);
    cudaGetSymbolAddress((void**)&tpw_,  g_tpw);
    cudaGetSymbolAddress((void**)&svw_,  g_svw);
    cudaGetSymbolAddress((void**)&spw_,  g_spw);
    cudaGetSymbolAddress((void**)&f1w_,  g_f1w);
    cudaGetSymbolAddress((void**)&f2w_,  g_f2w);
    cudaGetSymbolAddress((void**)&oaw_,  g_oaw);
    cudaGetSymbolAddress((void**)&oab_,  g_oab);

    const int WB = 256;
    {
        dim3 gt((NPIX + 31)/32, CDIM/32, NCAM);
        k_feats_t<<<gt, dim3(32, 8)>>>(image_feats);
    }
    k_round<<<(NLAYERS*CDIM*CDIM + WB-1)/WB, WB>>>(sca_vw, svw_, NLAYERS*CDIM*CDIM);
    k_invert<<<1, NCAM>>>(extr);
    gemm128(feats_, svw_, sca_vb, vimg_, NFEAT, CDIM, CDIM, CDIM, false);
    k_geom<<<(NCAM*NQ*NPTS + 255)/256, 256>>>(intr);
    k_cnt<<<(NQ + 255)/256, 256>>>();
    k_round<<<(NLAYERS*CDIM*CDIM + WB-1)/WB, WB>>>(tsa_vw, tvw_, NLAYERS*CDIM*CDIM);
    k_round<<<(NLAYERS*CDIM*CDIM + WB-1)/WB, WB>>>(tsa_pw, tpw_, NLAYERS*CDIM*CDIM);
    k_round<<<(NLAYERS*CDIM*CDIM + WB-1)/WB, WB>>>(sca_pw, spw_, NLAYERS*CDIM*CDIM);
    k_round<<<(NLAYERS*CDIM*FFN + WB-1)/WB, WB>>>(ffn_w1, f1w_, NLAYERS*CDIM*FFN);
    k_round<<<(NLAYERS*FFN*CDIM + WB-1)/WB, WB>>>(ffn_w2, f2w_, NLAYERS*FFN*CDIM);
    k_prep_oa<<<(2*NLAYERS*CDIM*128 + WB-1)/WB, WB>>>(
        (const float*)d_in[7], (const float*)d_in[9],
        (const float*)d_in[15], (const float*)d_in[17],
        (const float*)d_in[8], (const float*)d_in[10],
        (const float*)d_in[16], (const float*)d_in[18]);
    k_init_q<<<(NQ*CDIM + 255)/256, 256>>>(bev);

    for (int l = 0; l < NLAYERS; l++) {
        size_t wo = (size_t)l*CDIM*CDIM;

        if (l > 0) {
            cudaEventRecord(ev_fork[l], 0);
            cudaStreamWaitEvent(s2, ev_fork[l], 0);
            gemm128_s(s2, feats_, svw_ + wo, sca_vb + l*CDIM, vimg_,
                      NFEAT, CDIM, CDIM, CDIM, false);
            cudaEventRecord(ev_join[l], s2);
        }

        // ---- TSA (main stream) ----
        gemm128_avg(q_, prev, tvw_ + wo, tsa_vb + l*CDIM, v_, NQ, CDIM, CDIM, CDIM);
        gemm128(qr_, oaw_ + (size_t)l*CDIM*128, oab_ + l*128, oa_, NQ, 96, CDIM, 128, false);
        k_tsa_sample<<<NQ, 256>>>();
        gemm_ln(a_, tpw_ + wo, tsa_pb + l*CDIM, q_, ln1_g + l*CDIM, ln1_b + l*CDIM,
                q_, qr_, NQ, CDIM);

        // ---- SCA ----
        gemm128(qr_, oaw_ + (size_t)(NLAYERS + l)*CDIM*128, oab_ + (NLAYERS + l)*128,
                oa_, NQ, 96, CDIM, 128, false);
        if (l > 0)
            cudaStreamWaitEvent(0, ev_join[l], 0);
        k_sca_sample<<<NQ, 256>>>();
        gemm_ln(a_, spw_ + wo, sca_pb + l*CDIM, q_, ln2_g + l*CDIM, ln2_b + l*CDIM,
                q_, qr_, NQ, CDIM);

        // ---- FFN ----
        gemm128(qr_, f1w_ + (size_t)l*CDIM*FFN, ffn_b1 + l*FFN, hid_, NQ, FFN, CDIM, FFN, true);
        gemm_ln(hid_, f2w_ + (size_t)l*FFN*CDIM, ffn_b2 + l*CDIM, q_,
                ln3_g + l*CDIM, ln3_b + l*CDIM, q_, qr_, NQ, FFN);
    }

    k_out_t<<<dim3(NQ/32, CDIM/32), dim3(32, 8)>>>((float*)d_out);
}

// round 14
// speedup vs baseline: 1.0326x; 1.0071x over previous
#include <cuda_runtime.h>
#include <math.h>
#include <stdint.h>
#include <mma.h>

using namespace nvcuda;

#define NQ      16384
#define CDIM    256
#define HEADS   8
#define HD      32
#define NPTS    4
#define NLAYERS 6
#define NCAM    6
#define HF      58
#define WF      100
#define NPIX    (HF*WF)
#define NFEAT   (NCAM*NPIX)
#define FFN     512

// ---------------- scratch ----------------------------------------------------
__device__ __align__(256) float g_q[NQ*CDIM];
__device__ __align__(256) float g_q_rnd[NQ*CDIM];
__device__ __align__(256) float g_a[NQ*CDIM];
__device__ __align__(256) float g_hid[NQ*FFN];
__device__ __align__(256) float g_v[NQ*CDIM];
__device__ __align__(256) float g_vimg[NFEAT*CDIM];
__device__ __align__(256) float g_offattn[NQ*96];
__device__ __align__(256) float g_feats[NFEAT*CDIM];
__device__ __align__(256) float g_refcam[NCAM*NQ*NPTS*2];
__device__ __align__(256) float g_valid[NCAM*NQ*NPTS];
__device__ __align__(256) float g_cnt[NQ];
__device__ __align__(256) float g_inv[NCAM*16];
__device__ __align__(256) float g_tvw[NLAYERS*CDIM*CDIM];
__device__ __align__(256) float g_tpw[NLAYERS*CDIM*CDIM];
__device__ __align__(256) float g_svw[NLAYERS*CDIM*CDIM];
__device__ __align__(256) float g_spw[NLAYERS*CDIM*CDIM];
__device__ __align__(256) float g_f1w[NLAYERS*CDIM*FFN];
__device__ __align__(256) float g_f2w[NLAYERS*FFN*CDIM];
__device__ __align__(256) float g_oaw[2*NLAYERS*CDIM*128];
__device__ __align__(256) float g_oab[2*NLAYERS*128];

// ---------------- helpers ------------------------------------------------------
__device__ __forceinline__ float tf32r(float x) {
    float o;
    asm("cvt.rna.tf32.f32 %0, %1;" : "=f"(o) : "f"(x));
    return o;
}
__device__ __forceinline__ void cp_async16(void* sp, const void* gp) {
    uint32_t s = (uint32_t)__cvta_generic_to_shared(sp);
    asm volatile("cp.async.cg.shared.global [%0], [%1], 16;\n" :: "r"(s), "l"(gp));
}
__device__ __forceinline__ void cp_commit() { asm volatile("cp.async.commit_group;\n" ::: "memory"); }
template<int N> __device__ __forceinline__ void cp_wait() {
    asm volatile("cp.async.wait_group %0;\n" :: "n"(N) : "memory");
}

// ---------------- big tf32 GEMM: 128x128 tile, BK=32, 2-stage (R9 config) ------
#define TBM 128
#define TBN 128
#define TBK 32
#define TLDA 40
#define TLDB 136
#define TA_ST (TBM*TLDA)
#define TB_ST (TBK*TLDB)
#define TLDC 132
#define T_SMEM ((2*(TA_ST+TB_ST))*4)   // 75776 B

template<int EPI, bool AVG>
__global__ __launch_bounds__(256, 2) void k_gemm128(
    const float* __restrict__ A, const float* __restrict__ A2,
    const float* __restrict__ B,
    const float* __restrict__ bias, float* __restrict__ out,
    int M, int N, int K, int ldb)
{
    extern __shared__ float sm[];
    float* As = sm;
    float* Bs = sm + 2*TA_ST;
    float* Cs = sm;

    int tid = threadIdx.x;
    int wid = tid >> 5;
    int wr = wid & 1;
    int wc = wid >> 1;
    int m0 = blockIdx.x * TBM;
    int n0 = blockIdx.y * TBN;

    wmma::fragment<wmma::accumulator, 16, 16, 8, float> c[4][2];
    #pragma unroll
    for (int i = 0; i < 4; i++)
        #pragma unroll
        for (int j = 0; j < 2; j++)
            wmma::fill_fragment(c[i][j], 0.f);

    auto load_st = [&](int t, int b) {
        int k0 = t * TBK;
        float* as = As + b*TA_ST;
        float* bs = Bs + b*TB_ST;
        #pragma unroll
        for (int i = 0; i < 4; i++) {
            int cid = tid + i*256;
            int r = cid >> 3, c4 = cid & 7;
            int m = m0 + r; if (m >= M) m = M - 1;
            if (AVG) {
                float4 v1 = *(const float4*)&A[(size_t)m*K + k0 + c4*4];
                float4 v2 = *(const float4*)&A2[(size_t)m*K + k0 + c4*4];
                float4 v;
                v.x = tf32r(0.5f*(v1.x + v2.x));
                v.y = tf32r(0.5f*(v1.y + v2.y));
                v.z = tf32r(0.5f*(v1.z + v2.z));
                v.w = tf32r(0.5f*(v1.w + v2.w));
                *(float4*)&as[r*TLDA + c4*4] = v;
            } else {
                cp_async16(&as[r*TLDA + c4*4], &A[(size_t)m*K + k0 + c4*4]);
            }
        }
        #pragma unroll
        for (int i = 0; i < 4; i++) {
            int cid = tid + i*256;
            int r = cid >> 5, c4 = cid & 31;
            cp_async16(&bs[r*TLDB + c4*4], &B[(size_t)(k0 + r)*ldb + n0 + c4*4]);
        }
        cp_commit();
    };

    int T = K / TBK;
    load_st(0, 0);
    for (int t = 0; t < T; t++) {
        int b = t & 1;
        if (t + 1 < T) {
            load_st(t + 1, b ^ 1);
            cp_wait<1>();
        } else {
            cp_wait<0>();
        }
        __syncthreads();
        const float* as = As + b*TA_ST;
        const float* bs = Bs + b*TB_ST;
        #pragma unroll
        for (int kk = 0; kk < TBK; kk += 8) {
            wmma::fragment<wmma::matrix_a, 16, 16, 8, wmma::precision::tf32, wmma::row_major> a[4];
            wmma::fragment<wmma::matrix_b, 16, 16, 8, wmma::precision::tf32, wmma::row_major> bfrag[2];
            #pragma unroll
            for (int i = 0; i < 4; i++)
                wmma::load_matrix_sync(a[i], &as[(wr*64 + i*16)*TLDA + kk], TLDA);
            #pragma unroll
            for (int j = 0; j < 2; j++)
                wmma::load_matrix_sync(bfrag[j], &bs[kk*TLDB + wc*32 + j*16], TLDB);
            #pragma unroll
            for (int i = 0; i < 4; i++)
                #pragma unroll
                for (int j = 0; j < 2; j++)
                    wmma::mma_sync(c[i][j], a[i], bfrag[j], c[i][j]);
        }
        __syncthreads();
    }

    int e4 = tid & 31, er = tid >> 5;
    int nn = n0 + e4*4;
    float4 bv = make_float4(0.f, 0.f, 0.f, 0.f);
    if (nn < N) bv = *(const float4*)&bias[nn];
    #pragma unroll
    for (int chunk = 0; chunk < 2; chunk++) {
        if (wr == chunk) {
            #pragma unroll
            for (int i = 0; i < 4; i++)
                #pragma unroll
                for (int j = 0; j < 2; j++)
                    wmma::store_matrix_sync(&Cs[(i*16)*TLDC + wc*32 + j*16],
                                            c[i][j], TLDC, wmma::mem_row_major);
        }
        __syncthreads();
        if (nn < N) {
            #pragma unroll
            for (int i = 0; i < 8; i++) {
                int r = er + i*8;
                int m = m0 + chunk*64 + r;
                if (m < M) {
                    float4 v = *(float4*)&Cs[r*TLDC + e4*4];
                    v.x += bv.x; v.y += bv.y; v.z += bv.z; v.w += bv.w;
                    if (EPI == 1) {
                        v.x = tf32r(fmaxf(v.x, 0.f)); v.y = tf32r(fmaxf(v.y, 0.f));
                        v.z = tf32r(fmaxf(v.z, 0.f)); v.w = tf32r(fmaxf(v.w, 0.f));
                    }
                    *(float4*)&out[(size_t)m*N + nn] = v;
                }
            }
        }
        __syncthreads();
    }
}

// ---------------- fused GEMM + residual + LN (N=256), R9 config ----------------
#define LM 64
#define LBK 32
#define LLDA 40
#define LLDB 264
#define LA_ST (LM*LLDA)
#define LB_ST (LBK*LLDB)
#define LLDC 260
#define L_SMEM ((2*(LA_ST+LB_ST))*4)   // 88064 B

__global__ __launch_bounds__(256, 2) void k_gemm_ln(
    const float* __restrict__ A, const float* __restrict__ W,
    const float* __restrict__ bias, const float* __restrict__ resid,
    const float* __restrict__ gam, const float* __restrict__ bet,
    float* __restrict__ outp, float* __restrict__ ornd, int M, int K)
{
    extern __shared__ float sm[];
    float* As = sm;
    float* Bs = sm + 2*LA_ST;
    float* Cs = sm;

    int tid = threadIdx.x;
    int wid = tid >> 5;
    int lane = tid & 31;
    int wr = wid & 1;
    int wc = wid >> 1;
    int m0 = blockIdx.x * LM;

    wmma::fragment<wmma::accumulator, 16, 16, 8, float> c[2][4];
    #pragma unroll
    for (int i = 0; i < 2; i++)
        #pragma unroll
        for (int j = 0; j < 4; j++)
            wmma::fill_fragment(c[i][j], 0.f);

    auto load_st = [&](int t, int b) {
        int k0 = t * LBK;
        float* as = As + b*LA_ST;
        float* bs = Bs + b*LB_ST;
        #pragma unroll
        for (int i = 0; i < 2; i++) {
            int cid = tid + i*256;
            int r = cid >> 3, c4 = cid & 7;
            cp_async16(&as[r*LLDA + c4*4], &A[(size_t)(m0 + r)*K + k0 + c4*4]);
        }
        #pragma unroll
        for (int i = 0; i < 8; i++) {
            int cid = tid + i*256;
            int r = cid >> 6, c4 = cid & 63;
            cp_async16(&bs[r*LLDB + c4*4], &W[(size_t)(k0 + r)*CDIM + c4*4]);
        }
        cp_commit();
    };

    int T = K / LBK;
    load_st(0, 0);
    for (int t = 0; t < T; t++) {
        int b = t & 1;
        if (t + 1 < T) {
            load_st(t + 1, b ^ 1);
            cp_wait<1>();
        } else {
            cp_wait<0>();
        }
        __syncthreads();
        const float* as = As + b*LA_ST;
        const float* bs = Bs + b*LB_ST;
        #pragma unroll
        for (int kk = 0; kk < LBK; kk += 8) {
            wmma::fragment<wmma::matrix_a, 16, 16, 8, wmma::precision::tf32, wmma::row_major> a[2];
            wmma::fragment<wmma::matrix_b, 16, 16, 8, wmma::precision::tf32, wmma::row_major> bfrag[4];
            #pragma unroll
            for (int i = 0; i < 2; i++)
                wmma::load_matrix_sync(a[i], &as[(wr*32 + i*16)*LLDA + kk], LLDA);
            #pragma unroll
            for (int j = 0; j < 4; j++)
                wmma::load_matrix_sync(bfrag[j], &bs[kk*LLDB + wc*64 + j*16], LLDB);
            #pragma unroll
            for (int i = 0; i < 2; i++)
                #pragma unroll
                for (int j = 0; j < 4; j++)
                    wmma::mma_sync(c[i][j], a[i], bfrag[j], c[i][j]);
        }
        __syncthreads();
    }

    #pragma unroll
    for (int i = 0; i < 2; i++)
        #pragma unroll
        for (int j = 0; j < 4; j++)
            wmma::store_matrix_sync(&Cs[(wr*32 + i*16)*LLDC + wc*64 + j*16],
                                    c[i][j], LLDC, wmma::mem_row_major);
    __syncthreads();

    float4 bv0 = *(const float4*)&bias[lane*8];
    float4 bv1 = *(const float4*)&bias[lane*8 + 4];
    float4 gv0 = *(const float4*)&gam[lane*8];
    float4 gv1 = *(const float4*)&gam[lane*8 + 4];
    float4 tv0 = *(const float4*)&bet[lane*8];
    float4 tv1 = *(const float4*)&bet[lane*8 + 4];

    #pragma unroll
    for (int i = 0; i < 8; i++) {
        int r = wid*8 + i;
        int m = m0 + r;
        float4 c0 = *(float4*)&Cs[r*LLDC + lane*8];
        float4 c1 = *(float4*)&Cs[r*LLDC + lane*8 + 4];
        float4 q0 = *(const float4*)&resid[(size_t)m*CDIM + lane*8];
        float4 q1 = *(const float4*)&resid[(size_t)m*CDIM + lane*8 + 4];
        float x0 = q0.x + c0.x + bv0.x, x1 = q0.y + c0.y + bv0.y;
        float x2 = q0.z + c0.z + bv0.z, x3 = q0.w + c0.w + bv0.w;
        float x4 = q1.x + c1.x + bv1.x, x5 = q1.y + c1.y + bv1.y;
        float x6 = q1.z + c1.z + bv1.z, x7 = q1.w + c1.w + bv1.w;
        float s = x0+x1+x2+x3+x4+x5+x6+x7;
        #pragma unroll
        for (int o = 16; o > 0; o >>= 1) s += __shfl_xor_sync(0xffffffffu, s, o);
        float mean = s * (1.f/CDIM);
        float d0 = x0-mean, d1 = x1-mean, d2 = x2-mean, d3 = x3-mean;
        float d4 = x4-mean, d5 = x5-mean, d6 = x6-mean, d7 = x7-mean;
        float sq = d0*d0+d1*d1+d2*d2+d3*d3+d4*d4+d5*d5+d6*d6+d7*d7;
        #pragma unroll
        for (int o = 16; o > 0; o >>= 1) sq += __shfl_xor_sync(0xffffffffu, sq, o);
        float rstd = rsqrtf(sq * (1.f/CDIM) + 1e-5f);
        float o0 = d0*rstd*gv0.x + tv0.x, o1 = d1*rstd*gv0.y + tv0.y;
        float o2 = d2*rstd*gv0.z + tv0.z, o3 = d3*rstd*gv0.w + tv0.w;
        float o4 = d4*rstd*gv1.x + tv1.x, o5 = d5*rstd*gv1.y + tv1.y;
        float o6 = d6*rstd*gv1.z + tv1.z, o7 = d7*rstd*gv1.w + tv1.w;
        *(float4*)&outp[(size_t)m*CDIM + lane*8]     = make_float4(o0, o1, o2, o3);
        *(float4*)&outp[(size_t)m*CDIM + lane*8 + 4] = make_float4(o4, o5, o6, o7);
        *(float4*)&ornd[(size_t)m*CDIM + lane*8]     = make_float4(tf32r(o0), tf32r(o1), tf32r(o2), tf32r(o3));
        *(float4*)&ornd[(size_t)m*CDIM + lane*8 + 4] = make_float4(tf32r(o4), tf32r(o5), tf32r(o6), tf32r(o7));
    }
}

// ---------------- geometry / prep ------------------------------------------------
__global__ void k_invert(const float* __restrict__ extr) {
    int c = threadIdx.x;
    if (c >= NCAM) return;
    float a[4][8];
    for (int i = 0; i < 4; i++)
        for (int j = 0; j < 4; j++) {
            a[i][j] = extr[c*16 + i*4 + j];
            a[i][j+4] = (i == j) ? 1.f : 0.f;
        }
    for (int col = 0; col < 4; col++) {
        int piv = col;
        for (int r = col+1; r < 4; r++)
            if (fabsf(a[r][col]) > fabsf(a[piv][col])) piv = r;
        if (piv != col)
            for (int j = 0; j < 8; j++) { float t = a[col][j]; a[col][j] = a[piv][j]; a[piv][j] = t; }
        float d = 1.f / a[col][col];
        for (int j = 0; j < 8; j++) a[col][j] *= d;
        for (int r = 0; r < 4; r++) {
            if (r == col) continue;
            float f = a[r][col];
            for (int j = 0; j < 8; j++) a[r][j] -= f * a[col][j];
        }
    }
    for (int i = 0; i < 4; i++)
        for (int j = 0; j < 4; j++)
            g_inv[c*16 + i*4 + j] = a[i][j+4];
}

__global__ void k_geom(const float* __restrict__ intr) {
    int idx = blockIdx.x * blockDim.x + threadIdx.x;
    if (idx >= NCAM*NQ*NPTS) return;
    int p = idx % NPTS;
    int n = (idx / NPTS) % NQ;
    int c = idx / (NPTS * NQ);
    float gx = ((n & 127) + 0.5f) / 128.f;
    float gy = ((n >> 7)  + 0.5f) / 128.f;
    float xm = -51.2f + gx * 102.4f;
    float ym = -51.2f + gy * 102.4f;
    float zm = -5.0f + (p + 0.5f) * 2.0f;
    const float* Mi = &g_inv[c*16];
    float px = Mi[0]*xm + Mi[1]*ym + Mi[2]*zm  + Mi[3];
    float py = Mi[4]*xm + Mi[5]*ym + Mi[6]*zm  + Mi[7];
    float pz = Mi[8]*xm + Mi[9]*ym + Mi[10]*zm + Mi[11];
    const float* I = &intr[c*9];
    float ix = I[0]*px + I[1]*py + I[2]*pz;
    float iy = I[3]*px + I[4]*py + I[5]*pz;
    float iz = I[6]*px + I[7]*py + I[8]*pz;
    float zc = fmaxf(iz, 1e-5f);
    float un = ix / (zc * WF);
    float vn = iy / (zc * HF);
    float val = (iz > 1e-5f && un >= 0.f && un <= 1.f && vn >= 0.f && vn <= 1.f) ? 1.f : 0.f;
    g_refcam[idx*2+0] = un;
    g_refcam[idx*2+1] = vn;
    g_valid[idx] = val;
}

__global__ void k_cnt() {
    int n = blockIdx.x * blockDim.x + threadIdx.x;
    if (n >= NQ) return;
    float s = 0.f;
    for (int c = 0; c < NCAM; c++)
        for (int p = 0; p < NPTS; p++)
            s += g_valid[(c*NQ + n)*NPTS + p];
    g_cnt[n] = fmaxf(s, 1.f);
}

__global__ void k_feats_t(const float* __restrict__ in) {
    __shared__ float tile[32][33];
    int pix0 = blockIdx.x * 32, ch0 = blockIdx.y * 32, c = blockIdx.z;
    int tx = threadIdx.x, ty = threadIdx.y;
    for (int i = ty; i < 32; i += 8) {
        int pix = pix0 + tx;
        tile[i][tx] = (pix < NPIX) ? in[((size_t)c*CDIM + ch0 + i)*NPIX + pix] : 0.f;
    }
    __syncthreads();
    for (int i = ty; i < 32; i += 8) {
        int pix = pix0 + i;
        if (pix < NPIX)
            g_feats[((size_t)c*NPIX + pix)*CDIM + ch0 + tx] = tf32r(tile[tx][i]);
    }
}

__global__ void k_round(const float* __restrict__ W, float* __restrict__ out, int n) {
    int i = blockIdx.x * blockDim.x + threadIdx.x;
    if (i < n) out[i] = tf32r(W[i]);
}

__global__ void k_prep_oa(const float* __restrict__ tow, const float* __restrict__ taw,
                          const float* __restrict__ sow, const float* __restrict__ saw,
                          const float* __restrict__ tob, const float* __restrict__ tab,
                          const float* __restrict__ sob, const float* __restrict__ sab) {
    int idx = blockIdx.x * blockDim.x + threadIdx.x;
    int total = 2*NLAYERS*CDIM*128;
    if (idx < total) {
        int n = idx % 128;
        int k = (idx / 128) % CDIM;
        int l = (idx / (128*CDIM)) % NLAYERS;
        int s = idx / (128*CDIM*NLAYERS);
        const float* ow = s ? sow : tow;
        const float* aw = s ? saw : taw;
        float w = 0.f;
        if (n < 64)      w = ow[((size_t)l*CDIM + k)*64 + n];
        else if (n < 96) w = aw[((size_t)l*CDIM + k)*32 + (n - 64)];
        g_oaw[idx] = tf32r(w);
    }
    if (idx < 2*NLAYERS*128) {
        int j = idx % 128;
        int l = (idx / 128) % NLAYERS;
        int s = idx / (128*NLAYERS);
        const float* ob = s ? sob : tob;
        const float* ab = s ? sab : tab;
        float b = 0.f;
        if (j < 64)      b = ob[l*64 + j];
        else if (j < 96) b = ab[l*32 + (j - 64)];
        g_oab[idx] = b;
    }
}

__global__ void k_init_q(const float* __restrict__ src) {
    int i = blockIdx.x * blockDim.x + threadIdx.x;
    if (i >= NQ*CDIM) return;
    float v = src[i];
    g_q[i] = v;
    g_q_rnd[i] = tf32r(v);
}

// ---------------- samplers --------------------------------------------------------
__device__ __forceinline__ float bilin(const float* __restrict__ base, int H, int W,
                                       int stride, float ix, float iy) {
    float x0f = floorf(ix), y0f = floorf(iy);
    int x0 = (int)x0f, y0 = (int)y0f;
    float fx = ix - x0f, fy = iy - y0f;
    float out = 0.f;
    #pragma unroll
    for (int dy = 0; dy < 2; dy++) {
        int yi = y0 + dy;
        if (yi < 0 || yi >= H) continue;
        float wy = dy ? fy : 1.f - fy;
        #pragma unroll
        for (int dx = 0; dx < 2; dx++) {
            int xi = x0 + dx;
            if (xi < 0 || xi >= W) continue;
            float wx = dx ? fx : 1.f - fx;
            out += wy * wx * base[((size_t)yi*W + xi) * stride];
        }
    }
    return out;
}

__global__ void k_tsa_sample() {
    int n = blockIdx.x;
    int h = threadIdx.x >> 5;
    int lane = threadIdx.x & 31;
    const float* oa = &g_offattn[n*96];
    float lg0 = oa[64 + h*4 + 0], lg1 = oa[64 + h*4 + 1];
    float lg2 = oa[64 + h*4 + 2], lg3 = oa[64 + h*4 + 3];
    float mx = fmaxf(fmaxf(lg0, lg1), fmaxf(lg2, lg3));
    float e0 = expf(lg0-mx), e1 = expf(lg1-mx), e2 = expf(lg2-mx), e3 = expf(lg3-mx);
    float rse = 1.f / (e0+e1+e2+e3);
    float w[4] = {e0*rse, e1*rse, e2*rse, e3*rse};
    float refx = ((n & 127) + 0.5f);
    float refy = ((n >> 7)  + 0.5f);
    const float* base = g_v + h*HD + lane;
    float acc = 0.f;
    #pragma unroll
    for (int p = 0; p < 4; p++) {
        float ox = oa[(h*4 + p)*2 + 0];
        float oy = oa[(h*4 + p)*2 + 1];
        acc += w[p] * bilin(base, 128, 128, CDIM, refx + ox - 0.5f, refy + oy - 0.5f);
    }
    g_a[(size_t)n*CDIM + h*HD + lane] = tf32r(acc);
}

__global__ void k_sca_sample() {
    int n = blockIdx.x;
    int h = threadIdx.x >> 5;
    int lane = threadIdx.x & 31;
    const float* oa = &g_offattn[n*96];
    float lg0 = oa[64 + h*4 + 0], lg1 = oa[64 + h*4 + 1];
    float lg2 = oa[64 + h*4 + 2], lg3 = oa[64 + h*4 + 3];
    float mx = fmaxf(fmaxf(lg0, lg1), fmaxf(lg2, lg3));
    float e0 = expf(lg0-mx), e1 = expf(lg1-mx), e2 = expf(lg2-mx), e3 = expf(lg3-mx);
    float rse = 1.f / (e0+e1+e2+e3);
    float w[4], ox[4], oy[4];
    w[0] = e0*rse; w[1] = e1*rse; w[2] = e2*rse; w[3] = e3*rse;
    #pragma unroll
    for (int p = 0; p < 4; p++) {
        ox[p] = oa[(h*4 + p)*2 + 0];
        oy[p] = oa[(h*4 + p)*2 + 1];
    }
    float acc = 0.f;
    for (int c = 0; c < NCAM; c++) {
        const float* rc = &g_refcam[((size_t)(c*NQ + n))*NPTS*2];
        const float* vv = &g_valid[((size_t)(c*NQ + n))*NPTS];
        const float* base = g_vimg + (size_t)c*NPIX*CDIM + h*HD + lane;
        #pragma unroll
        for (int p = 0; p < 4; p++) {
            if (vv[p] == 0.f) continue;
            float ix = rc[p*2+0]*WF + ox[p] - 0.5f;
            float iy = rc[p*2+1]*HF + oy[p] - 0.5f;
            acc += w[p] * bilin(base, HF, WF, CDIM, ix, iy);
        }
    }
    g_a[(size_t)n*CDIM + h*HD + lane] = tf32r(acc / g_cnt[n]);
}

__global__ void k_out_t(float* __restrict__ out) {
    __shared__ float tile[32][33];
    int n0 = blockIdx.x * 32, c0 = blockIdx.y * 32;
    int tx = threadIdx.x, ty = threadIdx.y;
    for (int i = ty; i < 32; i += 8)
        tile[i][tx] = g_q[(size_t)(n0 + i)*CDIM + c0 + tx];
    __syncthreads();
    for (int i = ty; i < 32; i += 8)
        out[(size_t)(c0 + i)*NQ + n0 + tx] = tile[tx][i];
}

// ---------------- host --------------------------------------------------------
static void gemm128_s(cudaStream_t st, const float* A, const float* B,
                      const float* bias, float* out,
                      int M, int N, int K, int ldb, bool relu) {
    dim3 g((M + TBM - 1) / TBM, (ldb + TBN - 1) / TBN);
    if (relu) k_gemm128<1, false><<<g, 256, T_SMEM, st>>>(A, A, B, bias, out, M, N, K, ldb);
    else      k_gemm128<0, false><<<g, 256, T_SMEM, st>>>(A, A, B, bias, out, M, N, K, ldb);
}
static void gemm128(const float* A, const float* B, const float* bias, float* out,
                    int M, int N, int K, int ldb, bool relu) {
    gemm128_s(0, A, B, bias, out, M, N, K, ldb, relu);
}
static void gemm128_avg(const float* A, const float* A2, const float* B,
                        const float* bias, float* out, int M, int N, int K, int ldb) {
    dim3 g((M + TBM - 1) / TBM, (ldb + TBN - 1) / TBN);
    k_gemm128<0, true><<<g, 256, T_SMEM>>>(A, A2, B, bias, out, M, N, K, ldb);
}
static void gemm_ln(const float* A, const float* W, const float* bias,
                    const float* resid, const float* gam, const float* bet,
                    float* outp, float* ornd, int M, int K) {
    k_gemm_ln<<<M / LM, 256, L_SMEM>>>(A, W, bias, resid, gam, bet, outp, ornd, M, K);
}

extern "C" void kernel_launch(void* const* d_in, const int* in_sizes, int n_in,
                              void* d_out, int out_size) {
    static bool init_done = false;
    static cudaStream_t s2, s3;
    static cudaEvent_t ev_fork[NLAYERS], ev_join[NLAYERS];
    static cudaEvent_t ev_oaf[NLAYERS], ev_oaj[NLAYERS];
    static cudaEvent_t ev_begin, ev_setup;
    if (!init_done) {
        cudaFuncSetAttribute((const void*)k_gemm128<0, false>, cudaFuncAttributeMaxDynamicSharedMemorySize, T_SMEM);
        cudaFuncSetAttribute((const void*)k_gemm128<1, false>, cudaFuncAttributeMaxDynamicSharedMemorySize, T_SMEM);
        cudaFuncSetAttribute((const void*)k_gemm128<0, true>,  cudaFuncAttributeMaxDynamicSharedMemorySize, T_SMEM);
        cudaFuncSetAttribute((const void*)k_gemm_ln,           cudaFuncAttributeMaxDynamicSharedMemorySize, L_SMEM);
        cudaStreamCreateWithFlags(&s2, cudaStreamNonBlocking);
        cudaStreamCreateWithFlags(&s3, cudaStreamNonBlocking);
        for (int l = 0; l < NLAYERS; l++) {
            cudaEventCreateWithFlags(&ev_fork[l], cudaEventDisableTiming);
            cudaEventCreateWithFlags(&ev_join[l], cudaEventDisableTiming);
            cudaEventCreateWithFlags(&ev_oaf[l],  cudaEventDisableTiming);
            cudaEventCreateWithFlags(&ev_oaj[l],  cudaEventDisableTiming);
        }
        cudaEventCreateWithFlags(&ev_begin, cudaEventDisableTiming);
        cudaEventCreateWithFlags(&ev_setup, cudaEventDisableTiming);
        init_done = true;
    }

    const float* image_feats = (const float*)d_in[0];
    const float* intr        = (const float*)d_in[1];
    const float* extr        = (const float*)d_in[2];
    const float* prev        = (const float*)d_in[3];
    const float* bev         = (const float*)d_in[4];
    const float* tsa_vw = (const float*)d_in[5];
    const float* tsa_vb = (const float*)d_in[6];
    const float* tsa_pw = (const float*)d_in[11];
    const float* tsa_pb = (const float*)d_in[12];
    const float* sca_vw = (const float*)d_in[13];
    const float* sca_vb = (const float*)d_in[14];
    const float* sca_pw = (const float*)d_in[19];
    const float* sca_pb = (const float*)d_in[20];
    const float* ffn_w1 = (const float*)d_in[21];
    const float* ffn_b1 = (const float*)d_in[22];
    const float* ffn_w2 = (const float*)d_in[23];
    const float* ffn_b2 = (const float*)d_in[24];
    const float* ln1_g  = (const float*)d_in[25];
    const float* ln1_b  = (const float*)d_in[26];
    const float* ln2_g  = (const float*)d_in[27];
    const float* ln2_b  = (const float*)d_in[28];
    const float* ln3_g  = (const float*)d_in[29];
    const float* ln3_b  = (const float*)d_in[30];

    float *q_, *qr_, *a_, *hid_, *v_, *vimg_, *oa_, *feats_;
    float *tvw_, *tpw_, *svw_, *spw_, *f1w_, *f2w_, *oaw_, *oab_;
    cudaGetSymbolAddress((void**)&q_,    g_q);
    cudaGetSymbolAddress((void**)&qr_,   g_q_rnd);
    cudaGetSymbolAddress((void**)&a_,    g_a);
    cudaGetSymbolAddress((void**)&hid_,  g_hid);
    cudaGetSymbolAddress((void**)&v_,    g_v);
    cudaGetSymbolAddress((void**)&vimg_, g_vimg);
    cudaGetSymbolAddress((void**)&oa_,   g_offattn);
    cudaGetSymbolAddress((void**)&feats_, g_feats);
    cudaGetSymbolAddress((void**)&tvw_,  g_tvw);
    cudaGetSymbolAddress((void**)&tpw_,  g_tpw);
    cudaGetSymbolAddress((void**)&svw_,  g_svw);
    cudaGetSymbolAddress((void**)&spw_,  g_spw);
    cudaGetSymbolAddress((void**)&f1w_,  g_f1w);
    cudaGetSymbolAddress((void**)&f2w_,  g_f2w);
    cudaGetSymbolAddress((void**)&oaw_,  g_oaw);
    cudaGetSymbolAddress((void**)&oab_,  g_oab);

    const int WB = 256;

    // ---- setup: weight prep forked onto s3, geometry/feats on main -------------
    cudaEventRecord(ev_begin, 0);
    cudaStreamWaitEvent(s3, ev_begin, 0);
    k_round<<<(NLAYERS*CDIM*CDIM + WB-1)/WB, WB, 0, s3>>>(tsa_vw, tvw_, NLAYERS*CDIM*CDIM);
    k_round<<<(NLAYERS*CDIM*CDIM + WB-1)/WB, WB, 0, s3>>>(tsa_pw, tpw_, NLAYERS*CDIM*CDIM);
    k_round<<<(NLAYERS*CDIM*CDIM + WB-1)/WB, WB, 0, s3>>>(sca_pw, spw_, NLAYERS*CDIM*CDIM);
    k_round<<<(NLAYERS*CDIM*FFN + WB-1)/WB, WB, 0, s3>>>(ffn_w1, f1w_, NLAYERS*CDIM*FFN);
    k_round<<<(NLAYERS*FFN*CDIM + WB-1)/WB, WB, 0, s3>>>(ffn_w2, f2w_, NLAYERS*FFN*CDIM);
    k_prep_oa<<<(2*NLAYERS*CDIM*128 + WB-1)/WB, WB, 0, s3>>>(
        (const float*)d_in[7], (const float*)d_in[9],
        (const float*)d_in[15], (const float*)d_in[17],
        (const float*)d_in[8], (const float*)d_in[10],
        (const float*)d_in[16], (const float*)d_in[18]);
    cudaEventRecord(ev_setup, s3);

    {
        dim3 gt((NPIX + 31)/32, CDIM/32, NCAM);
        k_feats_t<<<gt, dim3(32, 8)>>>(image_feats);
    }
    k_round<<<(NLAYERS*CDIM*CDIM + WB-1)/WB, WB>>>(sca_vw, svw_, NLAYERS*CDIM*CDIM);
    k_invert<<<1, NCAM>>>(extr);
    gemm128(feats_, svw_, sca_vb, vimg_, NFEAT, CDIM, CDIM, CDIM, false);  // layer-0 vimg
    k_geom<<<(NCAM*NQ*NPTS + 255)/256, 256>>>(intr);
    k_cnt<<<(NQ + 255)/256, 256>>>();
    k_init_q<<<(NQ*CDIM + 255)/256, 256>>>(bev);
    cudaStreamWaitEvent(0, ev_setup, 0);   // tvw/tpw/spw/f1w/f2w/oaw ready

    for (int l = 0; l < NLAYERS; l++) {
        size_t wo = (size_t)l*CDIM*CDIM;

        // fork A: next vimg on s2 (layers 1..5)
        if (l > 0) {
            cudaEventRecord(ev_fork[l], 0);
            cudaStreamWaitEvent(s2, ev_fork[l], 0);
            gemm128_s(s2, feats_, svw_ + wo, sca_vb + l*CDIM, vimg_,
                      NFEAT, CDIM, CDIM, CDIM, false);
            cudaEventRecord(ev_join[l], s2);
        }

        // fork B: TSA oa GEMM on s3, concurrent with TSA value GEMM on main.
        // ordered after prev layer's sca_sample/ln3 (WAR on g_offattn, RAW on q_rnd).
        cudaEventRecord(ev_oaf[l], 0);
        cudaStreamWaitEvent(s3, ev_oaf[l], 0);
        gemm128_s(s3, qr_, oaw_ + (size_t)l*CDIM*128, oab_ + l*128, oa_,
                  NQ, 96, CDIM, 128, false);
        cudaEventRecord(ev_oaj[l], s3);

        // ---- TSA (main) ----
        gemm128_avg(q_, prev, tvw_ + wo, tsa_vb + l*CDIM, v_, NQ, CDIM, CDIM, CDIM);
        cudaStreamWaitEvent(0, ev_oaj[l], 0);
        k_tsa_sample<<<NQ, 256>>>();
        gemm_ln(a_, tpw_ + wo, tsa_pb + l*CDIM, q_, ln1_g + l*CDIM, ln1_b + l*CDIM,
                q_, qr_, NQ, CDIM);

        // ---- SCA ----
        gemm128(qr_, oaw_ + (size_t)(NLAYERS + l)*CDIM*128, oab_ + (NLAYERS + l)*128,
                oa_, NQ, 96, CDIM, 128, false);
        if (l > 0)
            cudaStreamWaitEvent(0, ev_join[l], 0);
        k_sca_sample<<<NQ, 256>>>();
        gemm_ln(a_, spw_ + wo, sca_pb + l*CDIM, q_, ln2_g + l*CDIM, ln2_b + l*CDIM,
                q_, qr_, NQ, CDIM);

        // ---- FFN ----
        gemm128(qr_, f1w_ + (size_t)l*CDIM*FFN, ffn_b1 + l*FFN, hid_, NQ, FFN, CDIM, FFN, true);
        gemm_ln(hid_, f2w_ + (size_t)l*FFN*CDIM, ffn_b2 + l*CDIM, q_,
                ln3_g + l*CDIM, ln3_b + l*CDIM, q_, qr_, NQ, FFN);
    }

    k_out_t<<<dim3(NQ/32, CDIM/32), dim3(32, 8)>>>((float*)d_out);
}

// round 15
// speedup vs baseline: 1.7785x; 1.7223x over previous
#include <cuda_runtime.h>
#include <cuda_fp16.h>
#include <math.h>
#include <stdint.h>
#include <mma.h>

using namespace nvcuda;
typedef __half hf;

#define NQ      16384
#define CDIM    256
#define HEADS   8
#define HD      32
#define NPTS    4
#define NLAYERS 6
#define NCAM    6
#define HF      58
#define WF      100
#define NPIX    (HF*WF)
#define NFEAT   (NCAM*NPIX)
#define FFN     512

// ---------------- scratch ----------------------------------------------------
__device__ __align__(256) float g_q[NQ*CDIM];
__device__ __align__(256) hf    g_q_rnd[NQ*CDIM];
__device__ __align__(256) hf    g_a[NQ*CDIM];
__device__ __align__(256) hf    g_hid[NQ*FFN];
__device__ __align__(256) float g_v[NQ*CDIM];
__device__ __align__(256) float g_vimg[NFEAT*CDIM];
__device__ __align__(256) float g_offattn[NQ*96];
__device__ __align__(256) hf    g_feats[NFEAT*CDIM];
__device__ __align__(256) float g_refcam[NCAM*NQ*NPTS*2];
__device__ __align__(256) float g_valid[NCAM*NQ*NPTS];
__device__ __align__(256) float g_cnt[NQ];
__device__ __align__(256) float g_inv[NCAM*16];
__device__ __align__(256) hf    g_tvw[NLAYERS*CDIM*CDIM];
__device__ __align__(256) hf    g_tpw[NLAYERS*CDIM*CDIM];
__device__ __align__(256) hf    g_svw[NLAYERS*CDIM*CDIM];
__device__ __align__(256) hf    g_spw[NLAYERS*CDIM*CDIM];
__device__ __align__(256) hf    g_f1w[NLAYERS*CDIM*FFN];
__device__ __align__(256) hf    g_f2w[NLAYERS*FFN*CDIM];
__device__ __align__(256) hf    g_oaw[2*NLAYERS*CDIM*128];
__device__ __align__(256) float g_oab[2*NLAYERS*128];

// ---------------- helpers ------------------------------------------------------
__device__ __forceinline__ void cp_async16(void* sp, const void* gp) {
    uint32_t s = (uint32_t)__cvta_generic_to_shared(sp);
    asm volatile("cp.async.cg.shared.global [%0], [%1], 16;\n" :: "r"(s), "l"(gp));
}
__device__ __forceinline__ void cp_commit() { asm volatile("cp.async.commit_group;\n" ::: "memory"); }
template<int N> __device__ __forceinline__ void cp_wait() {
    asm volatile("cp.async.wait_group %0;\n" :: "n"(N) : "memory");
}

// ---------------- fp16 GEMM: 128x128 tile, BK=64, 2-stage ----------------------
#define TBM 128
#define TBN 128
#define TBK 64
#define TLDA 80     // halves (64 + 16 pad; 160B rows, 32B-aligned)
#define TLDB 144    // halves (128 + 16 pad; 288B rows)
#define TA_ST (TBM*TLDA)   // 10240 halves
#define TB_ST (TBK*TLDB)   // 9216 halves
#define TLDC 132
#define T_SMEM ((2*(TA_ST+TB_ST))*2)   // 77824 B

template<int EPI, bool AVG>
__global__ __launch_bounds__(256, 2) void k_gemm128(
    const hf* __restrict__ Ah, const float* __restrict__ Af1, const float* __restrict__ Af2,
    const hf* __restrict__ B,
    const float* __restrict__ bias, float* __restrict__ outf, hf* __restrict__ outh,
    int M, int N, int K, int ldb)
{
    extern __shared__ char smraw[];
    hf* As = (hf*)smraw;
    hf* Bs = As + 2*TA_ST;
    float* Cs = (float*)smraw;

    int tid = threadIdx.x;
    int wid = tid >> 5;
    int wr = wid & 1;
    int wc = wid >> 1;
    int m0 = blockIdx.x * TBM;
    int n0 = blockIdx.y * TBN;

    wmma::fragment<wmma::accumulator, 16, 16, 16, float> c[4][2];
    #pragma unroll
    for (int i = 0; i < 4; i++)
        #pragma unroll
        for (int j = 0; j < 2; j++)
            wmma::fill_fragment(c[i][j], 0.f);

    auto load_st = [&](int t, int b) {
        int k0 = t * TBK;
        hf* as = As + b*TA_ST;
        hf* bs = Bs + b*TB_ST;
        #pragma unroll
        for (int i = 0; i < 4; i++) {
            int cid = tid + i*256;
            int r = cid >> 3, c8 = cid & 7;
            int m = m0 + r; if (m >= M) m = M - 1;
            if (AVG) {
                const float* p1 = &Af1[(size_t)m*K + k0 + c8*8];
                const float* p2 = &Af2[(size_t)m*K + k0 + c8*8];
                float4 a0 = *(const float4*)p1, a1 = *(const float4*)(p1+4);
                float4 b0 = *(const float4*)p2, b1 = *(const float4*)(p2+4);
                half2 h0 = __floats2half2_rn(0.5f*(a0.x+b0.x), 0.5f*(a0.y+b0.y));
                half2 h1 = __floats2half2_rn(0.5f*(a0.z+b0.z), 0.5f*(a0.w+b0.w));
                half2 h2 = __floats2half2_rn(0.5f*(a1.x+b1.x), 0.5f*(a1.y+b1.y));
                half2 h3 = __floats2half2_rn(0.5f*(a1.z+b1.z), 0.5f*(a1.w+b1.w));
                half2* dst = (half2*)&as[r*TLDA + c8*8];
                dst[0] = h0; dst[1] = h1; dst[2] = h2; dst[3] = h3;
            } else {
                cp_async16(&as[r*TLDA + c8*8], &Ah[(size_t)m*K + k0 + c8*8]);
            }
        }
        #pragma unroll
        for (int i = 0; i < 4; i++) {
            int cid = tid + i*256;
            int r = cid >> 4, c8 = cid & 15;
            cp_async16(&bs[r*TLDB + c8*8], &B[(size_t)(k0 + r)*ldb + n0 + c8*8]);
        }
        cp_commit();
    };

    int T = K / TBK;
    load_st(0, 0);
    for (int t = 0; t < T; t++) {
        int b = t & 1;
        if (t + 1 < T) {
            load_st(t + 1, b ^ 1);
            cp_wait<1>();
        } else {
            cp_wait<0>();
        }
        __syncthreads();
        const hf* as = As + b*TA_ST;
        const hf* bs = Bs + b*TB_ST;
        #pragma unroll
        for (int kk = 0; kk < TBK; kk += 16) {
            wmma::fragment<wmma::matrix_a, 16, 16, 16, hf, wmma::row_major> a[4];
            wmma::fragment<wmma::matrix_b, 16, 16, 16, hf, wmma::row_major> bfrag[2];
            #pragma unroll
            for (int i = 0; i < 4; i++)
                wmma::load_matrix_sync(a[i], &as[(wr*64 + i*16)*TLDA + kk], TLDA);
            #pragma unroll
            for (int j = 0; j < 2; j++)
                wmma::load_matrix_sync(bfrag[j], &bs[kk*TLDB + wc*32 + j*16], TLDB);
            #pragma unroll
            for (int i = 0; i < 4; i++)
                #pragma unroll
                for (int j = 0; j < 2; j++)
                    wmma::mma_sync(c[i][j], a[i], bfrag[j], c[i][j]);
        }
        __syncthreads();
    }

    // chunked epilogue (64 rows at a time; Cs = 64x132 fp32 fits pipeline smem)
    int e4 = tid & 31, er = tid >> 5;
    int nn = n0 + e4*4;
    float4 bv = make_float4(0.f, 0.f, 0.f, 0.f);
    if (nn < N) bv = *(const float4*)&bias[nn];
    #pragma unroll
    for (int chunk = 0; chunk < 2; chunk++) {
        if (wr == chunk) {
            #pragma unroll
            for (int i = 0; i < 4; i++)
                #pragma unroll
                for (int j = 0; j < 2; j++)
                    wmma::store_matrix_sync(&Cs[(i*16)*TLDC + wc*32 + j*16],
                                            c[i][j], TLDC, wmma::mem_row_major);
        }
        __syncthreads();
        if (nn < N) {
            #pragma unroll
            for (int i = 0; i < 8; i++) {
                int r = er + i*8;
                int m = m0 + chunk*64 + r;
                if (m < M) {
                    float4 v = *(float4*)&Cs[r*TLDC + e4*4];
                    v.x += bv.x; v.y += bv.y; v.z += bv.z; v.w += bv.w;
                    if (EPI == 1) {
                        half2* dst = (half2*)&outh[(size_t)m*N + nn];
                        dst[0] = __floats2half2_rn(fmaxf(v.x, 0.f), fmaxf(v.y, 0.f));
                        dst[1] = __floats2half2_rn(fmaxf(v.z, 0.f), fmaxf(v.w, 0.f));
                    } else {
                        *(float4*)&outf[(size_t)m*N + nn] = v;
                    }
                }
            }
        }
        __syncthreads();
    }
}

// ---------------- fused fp16 GEMM + residual + LN (N=256), BK=32 ---------------
#define LM 64
#define LBK 32
#define LLDA 48     // halves (96B rows)
#define LLDB 272    // halves (544B rows)
#define LA_ST (LM*LLDA)    // 3072 halves
#define LB_ST (LBK*LLDB)   // 8704 halves
#define LLDC 260
#define L_SMEM (LM*LLDC*4) // 66560 B (>= pipe 47104 B)

__global__ __launch_bounds__(256, 2) void k_gemm_ln(
    const hf* __restrict__ A, const hf* __restrict__ W,
    const float* __restrict__ bias, const float* __restrict__ resid,
    const float* __restrict__ gam, const float* __restrict__ bet,
    float* __restrict__ outp, hf* __restrict__ ornd, int M, int K)
{
    extern __shared__ char smraw[];
    hf* As = (hf*)smraw;
    hf* Bs = As + 2*LA_ST;
    float* Cs = (float*)smraw;

    int tid = threadIdx.x;
    int wid = tid >> 5;
    int lane = tid & 31;
    int wr = wid & 1;
    int wc = wid >> 1;
    int m0 = blockIdx.x * LM;

    wmma::fragment<wmma::accumulator, 16, 16, 16, float> c[2][4];
    #pragma unroll
    for (int i = 0; i < 2; i++)
        #pragma unroll
        for (int j = 0; j < 4; j++)
            wmma::fill_fragment(c[i][j], 0.f);

    auto load_st = [&](int t, int b) {
        int k0 = t * LBK;
        hf* as = As + b*LA_ST;
        hf* bs = Bs + b*LB_ST;
        {
            int r = tid >> 2, c8 = tid & 3;   // 64 rows x 4 chunks
            cp_async16(&as[r*LLDA + c8*8], &A[(size_t)(m0 + r)*K + k0 + c8*8]);
        }
        #pragma unroll
        for (int i = 0; i < 4; i++) {
            int cid = tid + i*256;
            int r = cid >> 5, c8 = cid & 31;  // 32 rows x 32 chunks
            cp_async16(&bs[r*LLDB + c8*8], &W[(size_t)(k0 + r)*CDIM + c8*8]);
        }
        cp_commit();
    };

    int T = K / LBK;
    load_st(0, 0);
    for (int t = 0; t < T; t++) {
        int b = t & 1;
        if (t + 1 < T) {
            load_st(t + 1, b ^ 1);
            cp_wait<1>();
        } else {
            cp_wait<0>();
        }
        __syncthreads();
        const hf* as = As + b*LA_ST;
        const hf* bs = Bs + b*LB_ST;
        #pragma unroll
        for (int kk = 0; kk < LBK; kk += 16) {
            wmma::fragment<wmma::matrix_a, 16, 16, 16, hf, wmma::row_major> a[2];
            wmma::fragment<wmma::matrix_b, 16, 16, 16, hf, wmma::row_major> bfrag[4];
            #pragma unroll
            for (int i = 0; i < 2; i++)
                wmma::load_matrix_sync(a[i], &as[(wr*32 + i*16)*LLDA + kk], LLDA);
            #pragma unroll
            for (int j = 0; j < 4; j++)
                wmma::load_matrix_sync(bfrag[j], &bs[kk*LLDB + wc*64 + j*16], LLDB);
            #pragma unroll
            for (int i = 0; i < 2; i++)
                #pragma unroll
                for (int j = 0; j < 4; j++)
                    wmma::mma_sync(c[i][j], a[i], bfrag[j], c[i][j]);
        }
        __syncthreads();
    }

    #pragma unroll
    for (int i = 0; i < 2; i++)
        #pragma unroll
        for (int j = 0; j < 4; j++)
            wmma::store_matrix_sync(&Cs[(wr*32 + i*16)*LLDC + wc*64 + j*16],
                                    c[i][j], LLDC, wmma::mem_row_major);
    __syncthreads();

    float4 bv0 = *(const float4*)&bias[lane*8];
    float4 bv1 = *(const float4*)&bias[lane*8 + 4];
    float4 gv0 = *(const float4*)&gam[lane*8];
    float4 gv1 = *(const float4*)&gam[lane*8 + 4];
    float4 tv0 = *(const float4*)&bet[lane*8];
    float4 tv1 = *(const float4*)&bet[lane*8 + 4];

    #pragma unroll
    for (int i = 0; i < 8; i++) {
        int r = wid*8 + i;
        int m = m0 + r;
        float4 c0 = *(float4*)&Cs[r*LLDC + lane*8];
        float4 c1 = *(float4*)&Cs[r*LLDC + lane*8 + 4];
        float4 q0 = *(const float4*)&resid[(size_t)m*CDIM + lane*8];
        float4 q1 = *(const float4*)&resid[(size_t)m*CDIM + lane*8 + 4];
        float x0 = q0.x + c0.x + bv0.x, x1 = q0.y + c0.y + bv0.y;
        float x2 = q0.z + c0.z + bv0.z, x3 = q0.w + c0.w + bv0.w;
        float x4 = q1.x + c1.x + bv1.x, x5 = q1.y + c1.y + bv1.y;
        float x6 = q1.z + c1.z + bv1.z, x7 = q1.w + c1.w + bv1.w;
        float s = x0+x1+x2+x3+x4+x5+x6+x7;
        #pragma unroll
        for (int o = 16; o > 0; o >>= 1) s += __shfl_xor_sync(0xffffffffu, s, o);
        float mean = s * (1.f/CDIM);
        float d0 = x0-mean, d1 = x1-mean, d2 = x2-mean, d3 = x3-mean;
        float d4 = x4-mean, d5 = x5-mean, d6 = x6-mean, d7 = x7-mean;
        float sq = d0*d0+d1*d1+d2*d2+d3*d3+d4*d4+d5*d5+d6*d6+d7*d7;
        #pragma unroll
        for (int o = 16; o > 0; o >>= 1) sq += __shfl_xor_sync(0xffffffffu, sq, o);
        float rstd = rsqrtf(sq * (1.f/CDIM) + 1e-5f);
        float o0 = d0*rstd*gv0.x + tv0.x, o1 = d1*rstd*gv0.y + tv0.y;
        float o2 = d2*rstd*gv0.z + tv0.z, o3 = d3*rstd*gv0.w + tv0.w;
        float o4 = d4*rstd*gv1.x + tv1.x, o5 = d5*rstd*gv1.y + tv1.y;
        float o6 = d6*rstd*gv1.z + tv1.z, o7 = d7*rstd*gv1.w + tv1.w;
        *(float4*)&outp[(size_t)m*CDIM + lane*8]     = make_float4(o0, o1, o2, o3);
        *(float4*)&outp[(size_t)m*CDIM + lane*8 + 4] = make_float4(o4, o5, o6, o7);
        half2* dst = (half2*)&ornd[(size_t)m*CDIM + lane*8];
        dst[0] = __floats2half2_rn(o0, o1);
        dst[1] = __floats2half2_rn(o2, o3);
        dst[2] = __floats2half2_rn(o4, o5);
        dst[3] = __floats2half2_rn(o6, o7);
    }
}

// ---------------- geometry / prep ------------------------------------------------
__global__ void k_invert(const float* __restrict__ extr) {
    int c = threadIdx.x;
    if (c >= NCAM) return;
    float a[4][8];
    for (int i = 0; i < 4; i++)
        for (int j = 0; j < 4; j++) {
            a[i][j] = extr[c*16 + i*4 + j];
            a[i][j+4] = (i == j) ? 1.f : 0.f;
        }
    for (int col = 0; col < 4; col++) {
        int piv = col;
        for (int r = col+1; r < 4; r++)
            if (fabsf(a[r][col]) > fabsf(a[piv][col])) piv = r;
        if (piv != col)
            for (int j = 0; j < 8; j++) { float t = a[col][j]; a[col][j] = a[piv][j]; a[piv][j] = t; }
        float d = 1.f / a[col][col];
        for (int j = 0; j < 8; j++) a[col][j] *= d;
        for (int r = 0; r < 4; r++) {
            if (r == col) continue;
            float f = a[r][col];
            for (int j = 0; j < 8; j++) a[r][j] -= f * a[col][j];
        }
    }
    for (int i = 0; i < 4; i++)
        for (int j = 0; j < 4; j++)
            g_inv[c*16 + i*4 + j] = a[i][j+4];
}

__global__ void k_geom(const float* __restrict__ intr) {
    int idx = blockIdx.x * blockDim.x + threadIdx.x;
    if (idx >= NCAM*NQ*NPTS) return;
    int p = idx % NPTS;
    int n = (idx / NPTS) % NQ;
    int c = idx / (NPTS * NQ);
    float gx = ((n & 127) + 0.5f) / 128.f;
    float gy = ((n >> 7)  + 0.5f) / 128.f;
    float xm = -51.2f + gx * 102.4f;
    float ym = -51.2f + gy * 102.4f;
    float zm = -5.0f + (p + 0.5f) * 2.0f;
    const float* Mi = &g_inv[c*16];
    float px = Mi[0]*xm + Mi[1]*ym + Mi[2]*zm  + Mi[3];
    float py = Mi[4]*xm + Mi[5]*ym + Mi[6]*zm  + Mi[7];
    float pz = Mi[8]*xm + Mi[9]*ym + Mi[10]*zm + Mi[11];
    const float* I = &intr[c*9];
    float ix = I[0]*px + I[1]*py + I[2]*pz;
    float iy = I[3]*px + I[4]*py + I[5]*pz;
    float iz = I[6]*px + I[7]*py + I[8]*pz;
    float zc = fmaxf(iz, 1e-5f);
    float un = ix / (zc * WF);
    float vn = iy / (zc * HF);
    float val = (iz > 1e-5f && un >= 0.f && un <= 1.f && vn >= 0.f && vn <= 1.f) ? 1.f : 0.f;
    g_refcam[idx*2+0] = un;
    g_refcam[idx*2+1] = vn;
    g_valid[idx] = val;
}

__global__ void k_cnt() {
    int n = blockIdx.x * blockDim.x + threadIdx.x;
    if (n >= NQ) return;
    float s = 0.f;
    for (int c = 0; c < NCAM; c++)
        for (int p = 0; p < NPTS; p++)
            s += g_valid[(c*NQ + n)*NPTS + p];
    g_cnt[n] = fmaxf(s, 1.f);
}

__global__ void k_feats_t(const float* __restrict__ in) {
    __shared__ float tile[32][33];
    int pix0 = blockIdx.x * 32, ch0 = blockIdx.y * 32, c = blockIdx.z;
    int tx = threadIdx.x, ty = threadIdx.y;
    for (int i = ty; i < 32; i += 8) {
        int pix = pix0 + tx;
        tile[i][tx] = (pix < NPIX) ? in[((size_t)c*CDIM + ch0 + i)*NPIX + pix] : 0.f;
    }
    __syncthreads();
    for (int i = ty; i < 32; i += 8) {
        int pix = pix0 + i;
        if (pix < NPIX)
            g_feats[((size_t)c*NPIX + pix)*CDIM + ch0 + tx] = __float2half(tile[tx][i]);
    }
}

__global__ void k_round(const float* __restrict__ W, hf* __restrict__ out, int n) {
    int i = blockIdx.x * blockDim.x + threadIdx.x;
    if (i < n) out[i] = __float2half(W[i]);
}

__global__ void k_prep_oa(const float* __restrict__ tow, const float* __restrict__ taw,
                          const float* __restrict__ sow, const float* __restrict__ saw,
                          const float* __restrict__ tob, const float* __restrict__ tab,
                          const float* __restrict__ sob, const float* __restrict__ sab) {
    int idx = blockIdx.x * blockDim.x + threadIdx.x;
    int total = 2*NLAYERS*CDIM*128;
    if (idx < total) {
        int n = idx % 128;
        int k = (idx / 128) % CDIM;
        int l = (idx / (128*CDIM)) % NLAYERS;
        int s = idx / (128*CDIM*NLAYERS);
        const float* ow = s ? sow : tow;
        const float* aw = s ? saw : taw;
        float w = 0.f;
        if (n < 64)      w = ow[((size_t)l*CDIM + k)*64 + n];
        else if (n < 96) w = aw[((size_t)l*CDIM + k)*32 + (n - 64)];
        g_oaw[idx] = __float2half(w);
    }
    if (idx < 2*NLAYERS*128) {
        int j = idx % 128;
        int l = (idx / 128) % NLAYERS;
        int s = idx / (128*NLAYERS);
        const float* ob = s ? sob : tob;
        const float* ab = s ? sab : tab;
        float b = 0.f;
        if (j < 64)      b = ob[l*64 + j];
        else if (j < 96) b = ab[l*32 + (j - 64)];
        g_oab[idx] = b;
    }
}

__global__ void k_init_q(const float* __restrict__ src) {
    int i = blockIdx.x * blockDim.x + threadIdx.x;
    if (i >= NQ*CDIM) return;
    float v = src[i];
    g_q[i] = v;
    g_q_rnd[i] = __float2half(v);
}

// ---------------- samplers --------------------------------------------------------
__device__ __forceinline__ float bilin(const float* __restrict__ base, int H, int W,
                                       int stride, float ix, float iy) {
    float x0f = floorf(ix), y0f = floorf(iy);
    int x0 = (int)x0f, y0 = (int)y0f;
    float fx = ix - x0f, fy = iy - y0f;
    float out = 0.f;
    #pragma unroll
    for (int dy = 0; dy < 2; dy++) {
        int yi = y0 + dy;
        if (yi < 0 || yi >= H) continue;
        float wy = dy ? fy : 1.f - fy;
        #pragma unroll
        for (int dx = 0; dx < 2; dx++) {
            int xi = x0 + dx;
            if (xi < 0 || xi >= W) continue;
            float wx = dx ? fx : 1.f - fx;
            out += wy * wx * base[((size_t)yi*W + xi) * stride];
        }
    }
    return out;
}

__global__ void k_tsa_sample() {
    int n = blockIdx.x;
    int h = threadIdx.x >> 5;
    int lane = threadIdx.x & 31;
    const float* oa = &g_offattn[n*96];
    float lg0 = oa[64 + h*4 + 0], lg1 = oa[64 + h*4 + 1];
    float lg2 = oa[64 + h*4 + 2], lg3 = oa[64 + h*4 + 3];
    float mx = fmaxf(fmaxf(lg0, lg1), fmaxf(lg2, lg3));
    float e0 = expf(lg0-mx), e1 = expf(lg1-mx), e2 = expf(lg2-mx), e3 = expf(lg3-mx);
    float rse = 1.f / (e0+e1+e2+e3);
    float w[4] = {e0*rse, e1*rse, e2*rse, e3*rse};
    float refx = ((n & 127) + 0.5f);
    float refy = ((n >> 7)  + 0.5f);
    const float* base = g_v + h*HD + lane;
    float acc = 0.f;
    #pragma unroll
    for (int p = 0; p < 4; p++) {
        float ox = oa[(h*4 + p)*2 + 0];
        float oy = oa[(h*4 + p)*2 + 1];
        acc += w[p] * bilin(base, 128, 128, CDIM, refx + ox - 0.5f, refy + oy - 0.5f);
    }
    g_a[(size_t)n*CDIM + h*HD + lane] = __float2half(acc);
}

__global__ void k_sca_sample() {
    int n = blockIdx.x;
    int h = threadIdx.x >> 5;
    int lane = threadIdx.x & 31;
    const float* oa = &g_offattn[n*96];
    float lg0 = oa[64 + h*4 + 0], lg1 = oa[64 + h*4 + 1];
    float lg2 = oa[64 + h*4 + 2], lg3 = oa[64 + h*4 + 3];
    float mx = fmaxf(fmaxf(lg0, lg1), fmaxf(lg2, lg3));
    float e0 = expf(lg0-mx), e1 = expf(lg1-mx), e2 = expf(lg2-mx), e3 = expf(lg3-mx);
    float rse = 1.f / (e0+e1+e2+e3);
    float w[4], ox[4], oy[4];
    w[0] = e0*rse; w[1] = e1*rse; w[2] = e2*rse; w[3] = e3*rse;
    #pragma unroll
    for (int p = 0; p < 4; p++) {
        ox[p] = oa[(h*4 + p)*2 + 0];
        oy[p] = oa[(h*4 + p)*2 + 1];
    }
    float acc = 0.f;
    for (int c = 0; c < NCAM; c++) {
        const float* rc = &g_refcam[((size_t)(c*NQ + n))*NPTS*2];
        const float* vv = &g_valid[((size_t)(c*NQ + n))*NPTS];
        const float* base = g_vimg + (size_t)c*NPIX*CDIM + h*HD + lane;
        #pragma unroll
        for (int p = 0; p < 4; p++) {
            if (vv[p] == 0.f) continue;
            float ix = rc[p*2+0]*WF + ox[p] - 0.5f;
            float iy = rc[p*2+1]*HF + oy[p] - 0.5f;
            acc += w[p] * bilin(base, HF, WF, CDIM, ix, iy);
        }
    }
    g_a[(size_t)n*CDIM + h*HD + lane] = __float2half(acc / g_cnt[n]);
}

__global__ void k_out_t(float* __restrict__ out) {
    __shared__ float tile[32][33];
    int n0 = blockIdx.x * 32, c0 = blockIdx.y * 32;
    int tx = threadIdx.x, ty = threadIdx.y;
    for (int i = ty; i < 32; i += 8)
        tile[i][tx] = g_q[(size_t)(n0 + i)*CDIM + c0 + tx];
    __syncthreads();
    for (int i = ty; i < 32; i += 8)
        out[(size_t)(c0 + i)*NQ + n0 + tx] = tile[tx][i];
}

// ---------------- host --------------------------------------------------------
static void gemm128_s(cudaStream_t st, const hf* A, const hf* B,
                      const float* bias, float* outf, hf* outh,
                      int M, int N, int K, int ldb, bool relu) {
    dim3 g((M + TBM - 1) / TBM, (ldb + TBN - 1) / TBN);
    if (relu) k_gemm128<1, false><<<g, 256, T_SMEM, st>>>(A, nullptr, nullptr, B, bias, outf, outh, M, N, K, ldb);
    else      k_gemm128<0, false><<<g, 256, T_SMEM, st>>>(A, nullptr, nullptr, B, bias, outf, outh, M, N, K, ldb);
}
static void gemm128_avg(const float* A1, const float* A2, const hf* B,
                        const float* bias, float* outf, int M, int N, int K, int ldb) {
    dim3 g((M + TBM - 1) / TBM, (ldb + TBN - 1) / TBN);
    k_gemm128<0, true><<<g, 256, T_SMEM>>>(nullptr, A1, A2, B, bias, outf, nullptr, M, N, K, ldb);
}
static void gemm_ln(const hf* A, const hf* W, const float* bias,
                    const float* resid, const float* gam, const float* bet,
                    float* outp, hf* ornd, int M, int K) {
    k_gemm_ln<<<M / LM, 256, L_SMEM>>>(A, W, bias, resid, gam, bet, outp, ornd, M, K);
}

extern "C" void kernel_launch(void* const* d_in, const int* in_sizes, int n_in,
                              void* d_out, int out_size) {
    static bool init_done = false;
    static cudaStream_t s2, s3;
    static cudaEvent_t ev_fork[NLAYERS], ev_join[NLAYERS];
    static cudaEvent_t ev_oaf[NLAYERS], ev_oaj[NLAYERS];
    static cudaEvent_t ev_begin, ev_setup;
    if (!init_done) {
        cudaFuncSetAttribute((const void*)k_gemm128<0, false>, cudaFuncAttributeMaxDynamicSharedMemorySize, T_SMEM);
        cudaFuncSetAttribute((const void*)k_gemm128<1, false>, cudaFuncAttributeMaxDynamicSharedMemorySize, T_SMEM);
        cudaFuncSetAttribute((const void*)k_gemm128<0, true>,  cudaFuncAttributeMaxDynamicSharedMemorySize, T_SMEM);
        cudaFuncSetAttribute((const void*)k_gemm_ln,           cudaFuncAttributeMaxDynamicSharedMemorySize, L_SMEM);
        cudaStreamCreateWithFlags(&s2, cudaStreamNonBlocking);
        cudaStreamCreateWithFlags(&s3, cudaStreamNonBlocking);
        for (int l = 0; l < NLAYERS; l++) {
            cudaEventCreateWithFlags(&ev_fork[l], cudaEventDisableTiming);
            cudaEventCreateWithFlags(&ev_join[l], cudaEventDisableTiming);
            cudaEventCreateWithFlags(&ev_oaf[l],  cudaEventDisableTiming);
            cudaEventCreateWithFlags(&ev_oaj[l],  cudaEventDisableTiming);
        }
        cudaEventCreateWithFlags(&ev_begin, cudaEventDisableTiming);
        cudaEventCreateWithFlags(&ev_setup, cudaEventDisableTiming);
        init_done = true;
    }

    const float* image_feats = (const float*)d_in[0];
    const float* intr        = (const float*)d_in[1];
    const float* extr        = (const float*)d_in[2];
    const float* prev        = (const float*)d_in[3];
    const float* bev         = (const float*)d_in[4];
    const float* tsa_vw = (const float*)d_in[5];
    const float* tsa_vb = (const float*)d_in[6];
    const float* tsa_pw = (const float*)d_in[11];
    const float* tsa_pb = (const float*)d_in[12];
    const float* sca_vw = (const float*)d_in[13];
    const float* sca_vb = (const float*)d_in[14];
    const float* sca_pw = (const float*)d_in[19];
    const float* sca_pb = (const float*)d_in[20];
    const float* ffn_w1 = (const float*)d_in[21];
    const float* ffn_b1 = (const float*)d_in[22];
    const float* ffn_w2 = (const float*)d_in[23];
    const float* ffn_b2 = (const float*)d_in[24];
    const float* ln1_g  = (const float*)d_in[25];
    const float* ln1_b  = (const float*)d_in[26];
    const float* ln2_g  = (const float*)d_in[27];
    const float* ln2_b  = (const float*)d_in[28];
    const float* ln3_g  = (const float*)d_in[29];
    const float* ln3_b  = (const float*)d_in[30];

    float *q_, *v_, *vimg_, *oa_, *oab_;
    hf *qr_, *a_, *hid_, *feats_;
    hf *tvw_, *tpw_, *svw_, *spw_, *f1w_, *f2w_, *oaw_;
    cudaGetSymbolAddress((void**)&q_,    g_q);
    cudaGetSymbolAddress((void**)&qr_,   g_q_rnd);
    cudaGetSymbolAddress((void**)&a_,    g_a);
    cudaGetSymbolAddress((void**)&hid_,  g_hid);
    cudaGetSymbolAddress((void**)&v_,    g_v);
    cudaGetSymbolAddress((void**)&vimg_, g_vimg);
    cudaGetSymbolAddress((void**)&oa_,   g_offattn);
    cudaGetSymbolAddress((void**)&feats_, g_feats);
    cudaGetSymbolAddress((void**)&tvw_,  g_tvw);
    cudaGetSymbolAddress((void**)&tpw_,  g_tpw);
    cudaGetSymbolAddress((void**)&svw_,  g_svw);
    cudaGetSymbolAddress((void**)&spw_,  g_spw);
    cudaGetSymbolAddress((void**)&f1w_,  g_f1w);
    cudaGetSymbolAddress((void**)&f2w_,  g_f2w);
    cudaGetSymbolAddress((void**)&oaw_,  g_oaw);
    cudaGetSymbolAddress((void**)&oab_,  g_oab);

    const int WB = 256;

    // ---- setup: weight prep on s3, geometry/feats on main ----
    cudaEventRecord(ev_begin, 0);
    cudaStreamWaitEvent(s3, ev_begin, 0);
    k_round<<<(NLAYERS*CDIM*CDIM + WB-1)/WB, WB, 0, s3>>>(tsa_vw, tvw_, NLAYERS*CDIM*CDIM);
    k_round<<<(NLAYERS*CDIM*CDIM + WB-1)/WB, WB, 0, s3>>>(tsa_pw, tpw_, NLAYERS*CDIM*CDIM);
    k_round<<<(NLAYERS*CDIM*CDIM + WB-1)/WB, WB, 0, s3>>>(sca_pw, spw_, NLAYERS*CDIM*CDIM);
    k_round<<<(NLAYERS*CDIM*FFN + WB-1)/WB, WB, 0, s3>>>(ffn_w1, f1w_, NLAYERS*CDIM*FFN);
    k_round<<<(NLAYERS*FFN*CDIM + WB-1)/WB, WB, 0, s3>>>(ffn_w2, f2w_, NLAYERS*FFN*CDIM);
    k_prep_oa<<<(2*NLAYERS*CDIM*128 + WB-1)/WB, WB, 0, s3>>>(
        (const float*)d_in[7], (const float*)d_in[9],
        (const float*)d_in[15], (const float*)d_in[17],
        (const float*)d_in[8], (const float*)d_in[10],
        (const float*)d_in[16], (const float*)d_in[18]);
    cudaEventRecord(ev_setup, s3);

    {
        dim3 gt((NPIX + 31)/32, CDIM/32, NCAM);
        k_feats_t<<<gt, dim3(32, 8)>>>(image_feats);
    }
    k_round<<<(NLAYERS*CDIM*CDIM + WB-1)/WB, WB>>>(sca_vw, svw_, NLAYERS*CDIM*CDIM);
    k_invert<<<1, NCAM>>>(extr);
    gemm128_s(0, feats_, svw_, sca_vb, vimg_, nullptr, NFEAT, CDIM, CDIM, CDIM, false);  // layer-0 vimg
    k_geom<<<(NCAM*NQ*NPTS + 255)/256, 256>>>(intr);
    k_cnt<<<(NQ + 255)/256, 256>>>();
    k_init_q<<<(NQ*CDIM + 255)/256, 256>>>(bev);
    cudaStreamWaitEvent(0, ev_setup, 0);

    for (int l = 0; l < NLAYERS; l++) {
        size_t wo = (size_t)l*CDIM*CDIM;

        // fork A: next vimg on s2
        if (l > 0) {
            cudaEventRecord(ev_fork[l], 0);
            cudaStreamWaitEvent(s2, ev_fork[l], 0);
            gemm128_s(s2, feats_, svw_ + wo, sca_vb + l*CDIM, vimg_, nullptr,
                      NFEAT, CDIM, CDIM, CDIM, false);
            cudaEventRecord(ev_join[l], s2);
        }

        // fork B: TSA oa GEMM on s3
        cudaEventRecord(ev_oaf[l], 0);
        cudaStreamWaitEvent(s3, ev_oaf[l], 0);
        gemm128_s(s3, qr_, oaw_ + (size_t)l*CDIM*128, oab_ + l*128, oa_, nullptr,
                  NQ, 96, CDIM, 128, false);
        cudaEventRecord(ev_oaj[l], s3);

        // ---- TSA (main) ----
        gemm128_avg(q_, prev, tvw_ + wo, tsa_vb + l*CDIM, v_, NQ, CDIM, CDIM, CDIM);
        cudaStreamWaitEvent(0, ev_oaj[l], 0);
        k_tsa_sample<<<NQ, 256>>>();
        gemm_ln(a_, tpw_ + wo, tsa_pb + l*CDIM, q_, ln1_g + l*CDIM, ln1_b + l*CDIM,
                q_, qr_, NQ, CDIM);

        // ---- SCA ----
        gemm128_s(0, qr_, oaw_ + (size_t)(NLAYERS + l)*CDIM*128, oab_ + (NLAYERS + l)*128,
                  oa_, nullptr, NQ, 96, CDIM, 128, false);
        if (l > 0)
            cudaStreamWaitEvent(0, ev_join[l], 0);
        k_sca_sample<<<NQ, 256>>>();
        gemm_ln(a_, spw_ + wo, sca_pb + l*CDIM, q_, ln2_g + l*CDIM, ln2_b + l*CDIM,
                q_, qr_, NQ, CDIM);

        // ---- FFN ----
        gemm128_s(0, qr_, f1w_ + (size_t)l*CDIM*FFN, ffn_b1 + l*FFN, nullptr, hid_,
                  NQ, FFN, CDIM, FFN, true);
        gemm_ln(hid_, f2w_ + (size_t)l*FFN*CDIM, ffn_b2 + l*CDIM, q_,
                ln3_g + l*CDIM, ln3_b + l*CDIM, q_, qr_, NQ, FFN);
    }

    k_out_t<<<dim3(NQ/32, CDIM/32), dim3(32, 8)>>>((float*)d_out);
}

// round 16
// speedup vs baseline: 1.8123x; 1.0190x over previous
#include <cuda_runtime.h>
#include <cuda_fp16.h>
#include <math.h>
#include <stdint.h>
#include <mma.h>

using namespace nvcuda;
typedef __half hf;

#define NQ      16384
#define CDIM    256
#define HEADS   8
#define HD      32
#define NPTS    4
#define NLAYERS 6
#define NCAM    6
#define HF      58
#define WF      100
#define NPIX    (HF*WF)
#define NFEAT   (NCAM*NPIX)
#define FFN     512

// ---------------- scratch ----------------------------------------------------
__device__ __align__(256) float g_q[NQ*CDIM];
__device__ __align__(256) hf    g_q_rnd[NQ*CDIM];
__device__ __align__(256) hf    g_a[NQ*CDIM];
__device__ __align__(256) hf    g_hid[NQ*FFN];
__device__ __align__(256) hf    g_v[NQ*CDIM];
__device__ __align__(256) hf    g_vimg[NFEAT*CDIM];
__device__ __align__(256) float g_offattn[NQ*96];
__device__ __align__(256) hf    g_feats[NFEAT*CDIM];
__device__ __align__(256) float g_refcam[NCAM*NQ*NPTS*2];
__device__ __align__(256) float g_valid[NCAM*NQ*NPTS];
__device__ __align__(256) float g_cnt[NQ];
__device__ __align__(256) float g_inv[NCAM*16];
__device__ __align__(256) hf    g_tvw[NLAYERS*CDIM*CDIM];
__device__ __align__(256) hf    g_tpw[NLAYERS*CDIM*CDIM];
__device__ __align__(256) hf    g_svw[NLAYERS*CDIM*CDIM];
__device__ __align__(256) hf    g_spw[NLAYERS*CDIM*CDIM];
__device__ __align__(256) hf    g_f1w[NLAYERS*CDIM*FFN];
__device__ __align__(256) hf    g_f2w[NLAYERS*FFN*CDIM];
__device__ __align__(256) hf    g_oaw[2*NLAYERS*CDIM*128];
__device__ __align__(256) float g_oab[2*NLAYERS*128];

// ---------------- helpers ------------------------------------------------------
__device__ __forceinline__ void cp_async16(void* sp, const void* gp) {
    uint32_t s = (uint32_t)__cvta_generic_to_shared(sp);
    asm volatile("cp.async.cg.shared.global [%0], [%1], 16;\n" :: "r"(s), "l"(gp));
}
__device__ __forceinline__ void cp_commit() { asm volatile("cp.async.commit_group;\n" ::: "memory"); }
template<int N> __device__ __forceinline__ void cp_wait() {
    asm volatile("cp.async.wait_group %0;\n" :: "n"(N) : "memory");
}

// ---------------- fp16 GEMM: 128x128 tile, BK=64, 2-stage ----------------------
// EPI 0: bias -> fp32 out. EPI 1: bias+relu -> half out. EPI 2: bias -> half out.
#define TBM 128
#define TBN 128
#define TBK 64
#define TLDA 80
#define TLDB 144
#define TA_ST (TBM*TLDA)
#define TB_ST (TBK*TLDB)
#define TLDC 132
#define T_SMEM ((2*(TA_ST+TB_ST))*2)   // 77824 B

template<int EPI, bool AVG>
__global__ __launch_bounds__(256, 2) void k_gemm128(
    const hf* __restrict__ Ah, const float* __restrict__ Af1, const float* __restrict__ Af2,
    const hf* __restrict__ B,
    const float* __restrict__ bias, float* __restrict__ outf, hf* __restrict__ outh,
    int M, int N, int K, int ldb)
{
    extern __shared__ char smraw[];
    hf* As = (hf*)smraw;
    hf* Bs = As + 2*TA_ST;
    float* Cs = (float*)smraw;

    int tid = threadIdx.x;
    int wid = tid >> 5;
    int wr = wid & 1;
    int wc = wid >> 1;
    int m0 = blockIdx.x * TBM;
    int n0 = blockIdx.y * TBN;

    wmma::fragment<wmma::accumulator, 16, 16, 16, float> c[4][2];
    #pragma unroll
    for (int i = 0; i < 4; i++)
        #pragma unroll
        for (int j = 0; j < 2; j++)
            wmma::fill_fragment(c[i][j], 0.f);

    auto load_st = [&](int t, int b) {
        int k0 = t * TBK;
        hf* as = As + b*TA_ST;
        hf* bs = Bs + b*TB_ST;
        #pragma unroll
        for (int i = 0; i < 4; i++) {
            int cid = tid + i*256;
            int r = cid >> 3, c8 = cid & 7;
            int m = m0 + r; if (m >= M) m = M - 1;
            if (AVG) {
                const float* p1 = &Af1[(size_t)m*K + k0 + c8*8];
                const float* p2 = &Af2[(size_t)m*K + k0 + c8*8];
                float4 a0 = *(const float4*)p1, a1 = *(const float4*)(p1+4);
                float4 b0 = *(const float4*)p2, b1 = *(const float4*)(p2+4);
                half2* dst = (half2*)&as[r*TLDA + c8*8];
                dst[0] = __floats2half2_rn(0.5f*(a0.x+b0.x), 0.5f*(a0.y+b0.y));
                dst[1] = __floats2half2_rn(0.5f*(a0.z+b0.z), 0.5f*(a0.w+b0.w));
                dst[2] = __floats2half2_rn(0.5f*(a1.x+b1.x), 0.5f*(a1.y+b1.y));
                dst[3] = __floats2half2_rn(0.5f*(a1.z+b1.z), 0.5f*(a1.w+b1.w));
            } else {
                cp_async16(&as[r*TLDA + c8*8], &Ah[(size_t)m*K + k0 + c8*8]);
            }
        }
        #pragma unroll
        for (int i = 0; i < 4; i++) {
            int cid = tid + i*256;
            int r = cid >> 4, c8 = cid & 15;
            cp_async16(&bs[r*TLDB + c8*8], &B[(size_t)(k0 + r)*ldb + n0 + c8*8]);
        }
        cp_commit();
    };

    int T = K / TBK;
    load_st(0, 0);
    for (int t = 0; t < T; t++) {
        int b = t & 1;
        if (t + 1 < T) {
            load_st(t + 1, b ^ 1);
            cp_wait<1>();
        } else {
            cp_wait<0>();
        }
        __syncthreads();
        const hf* as = As + b*TA_ST;
        const hf* bs = Bs + b*TB_ST;
        #pragma unroll
        for (int kk = 0; kk < TBK; kk += 16) {
            wmma::fragment<wmma::matrix_a, 16, 16, 16, hf, wmma::row_major> a[4];
            wmma::fragment<wmma::matrix_b, 16, 16, 16, hf, wmma::row_major> bfrag[2];
            #pragma unroll
            for (int i = 0; i < 4; i++)
                wmma::load_matrix_sync(a[i], &as[(wr*64 + i*16)*TLDA + kk], TLDA);
            #pragma unroll
            for (int j = 0; j < 2; j++)
                wmma::load_matrix_sync(bfrag[j], &bs[kk*TLDB + wc*32 + j*16], TLDB);
            #pragma unroll
            for (int i = 0; i < 4; i++)
                #pragma unroll
                for (int j = 0; j < 2; j++)
                    wmma::mma_sync(c[i][j], a[i], bfrag[j], c[i][j]);
        }
        __syncthreads();
    }

    int e4 = tid & 31, er = tid >> 5;
    int nn = n0 + e4*4;
    float4 bv = make_float4(0.f, 0.f, 0.f, 0.f);
    if (nn < N) bv = *(const float4*)&bias[nn];
    #pragma unroll
    for (int chunk = 0; chunk < 2; chunk++) {
        if (wr == chunk) {
            #pragma unroll
            for (int i = 0; i < 4; i++)
                #pragma unroll
                for (int j = 0; j < 2; j++)
                    wmma::store_matrix_sync(&Cs[(i*16)*TLDC + wc*32 + j*16],
                                            c[i][j], TLDC, wmma::mem_row_major);
        }
        __syncthreads();
        if (nn < N) {
            #pragma unroll
            for (int i = 0; i < 8; i++) {
                int r = er + i*8;
                int m = m0 + chunk*64 + r;
                if (m < M) {
                    float4 v = *(float4*)&Cs[r*TLDC + e4*4];
                    v.x += bv.x; v.y += bv.y; v.z += bv.z; v.w += bv.w;
                    if (EPI == 0) {
                        *(float4*)&outf[(size_t)m*N + nn] = v;
                    } else if (EPI == 1) {
                        half2* dst = (half2*)&outh[(size_t)m*N + nn];
                        dst[0] = __floats2half2_rn(fmaxf(v.x, 0.f), fmaxf(v.y, 0.f));
                        dst[1] = __floats2half2_rn(fmaxf(v.z, 0.f), fmaxf(v.w, 0.f));
                    } else {
                        half2* dst = (half2*)&outh[(size_t)m*N + nn];
                        dst[0] = __floats2half2_rn(v.x, v.y);
                        dst[1] = __floats2half2_rn(v.z, v.w);
                    }
                }
            }
        }
        __syncthreads();
    }
}

// ---------------- fused fp16 GEMM + residual + LN (N=256), BK=32 ---------------
#define LM 64
#define LBK 32
#define LLDA 48
#define LLDB 272
#define LA_ST (LM*LLDA)
#define LB_ST (LBK*LLDB)
#define LLDC 260
#define L_SMEM (LM*LLDC*4)

__global__ __launch_bounds__(256, 2) void k_gemm_ln(
    const hf* __restrict__ A, const hf* __restrict__ W,
    const float* __restrict__ bias, const float* __restrict__ resid,
    const float* __restrict__ gam, const float* __restrict__ bet,
    float* __restrict__ outp, hf* __restrict__ ornd, int M, int K)
{
    extern __shared__ char smraw[];
    hf* As = (hf*)smraw;
    hf* Bs = As + 2*LA_ST;
    float* Cs = (float*)smraw;

    int tid = threadIdx.x;
    int wid = tid >> 5;
    int lane = tid & 31;
    int wr = wid & 1;
    int wc = wid >> 1;
    int m0 = blockIdx.x * LM;

    wmma::fragment<wmma::accumulator, 16, 16, 16, float> c[2][4];
    #pragma unroll
    for (int i = 0; i < 2; i++)
        #pragma unroll
        for (int j = 0; j < 4; j++)
            wmma::fill_fragment(c[i][j], 0.f);

    auto load_st = [&](int t, int b) {
        int k0 = t * LBK;
        hf* as = As + b*LA_ST;
        hf* bs = Bs + b*LB_ST;
        {
            int r = tid >> 2, c8 = tid & 3;
            cp_async16(&as[r*LLDA + c8*8], &A[(size_t)(m0 + r)*K + k0 + c8*8]);
        }
        #pragma unroll
        for (int i = 0; i < 4; i++) {
            int cid = tid + i*256;
            int r = cid >> 5, c8 = cid & 31;
            cp_async16(&bs[r*LLDB + c8*8], &W[(size_t)(k0 + r)*CDIM + c8*8]);
        }
        cp_commit();
    };

    int T = K / LBK;
    load_st(0, 0);
    for (int t = 0; t < T; t++) {
        int b = t & 1;
        if (t + 1 < T) {
            load_st(t + 1, b ^ 1);
            cp_wait<1>();
        } else {
            cp_wait<0>();
        }
        __syncthreads();
        const hf* as = As + b*LA_ST;
        const hf* bs = Bs + b*LB_ST;
        #pragma unroll
        for (int kk = 0; kk < LBK; kk += 16) {
            wmma::fragment<wmma::matrix_a, 16, 16, 16, hf, wmma::row_major> a[2];
            wmma::fragment<wmma::matrix_b, 16, 16, 16, hf, wmma::row_major> bfrag[4];
            #pragma unroll
            for (int i = 0; i < 2; i++)
                wmma::load_matrix_sync(a[i], &as[(wr*32 + i*16)*LLDA + kk], LLDA);
            #pragma unroll
            for (int j = 0; j < 4; j++)
                wmma::load_matrix_sync(bfrag[j], &bs[kk*LLDB + wc*64 + j*16], LLDB);
            #pragma unroll
            for (int i = 0; i < 2; i++)
                #pragma unroll
                for (int j = 0; j < 4; j++)
                    wmma::mma_sync(c[i][j], a[i], bfrag[j], c[i][j]);
        }
        __syncthreads();
    }

    #pragma unroll
    for (int i = 0; i < 2; i++)
        #pragma unroll
        for (int j = 0; j < 4; j++)
            wmma::store_matrix_sync(&Cs[(wr*32 + i*16)*LLDC + wc*64 + j*16],
                                    c[i][j], LLDC, wmma::mem_row_major);
    __syncthreads();

    float4 bv0 = *(const float4*)&bias[lane*8];
    float4 bv1 = *(const float4*)&bias[lane*8 + 4];
    float4 gv0 = *(const float4*)&gam[lane*8];
    float4 gv1 = *(const float4*)&gam[lane*8 + 4];
    float4 tv0 = *(const float4*)&bet[lane*8];
    float4 tv1 = *(const float4*)&bet[lane*8 + 4];

    #pragma unroll
    for (int i = 0; i < 8; i++) {
        int r = wid*8 + i;
        int m = m0 + r;
        float4 c0 = *(float4*)&Cs[r*LLDC + lane*8];
        float4 c1 = *(float4*)&Cs[r*LLDC + lane*8 + 4];
        float4 q0 = *(const float4*)&resid[(size_t)m*CDIM + lane*8];
        float4 q1 = *(const float4*)&resid[(size_t)m*CDIM + lane*8 + 4];
        float x0 = q0.x + c0.x + bv0.x, x1 = q0.y + c0.y + bv0.y;
        float x2 = q0.z + c0.z + bv0.z, x3 = q0.w + c0.w + bv0.w;
        float x4 = q1.x + c1.x + bv1.x, x5 = q1.y + c1.y + bv1.y;
        float x6 = q1.z + c1.z + bv1.z, x7 = q1.w + c1.w + bv1.w;
        float s = x0+x1+x2+x3+x4+x5+x6+x7;
        #pragma unroll
        for (int o = 16; o > 0; o >>= 1) s += __shfl_xor_sync(0xffffffffu, s, o);
        float mean = s * (1.f/CDIM);
        float d0 = x0-mean, d1 = x1-mean, d2 = x2-mean, d3 = x3-mean;
        float d4 = x4-mean, d5 = x5-mean, d6 = x6-mean, d7 = x7-mean;
        float sq = d0*d0+d1*d1+d2*d2+d3*d3+d4*d4+d5*d5+d6*d6+d7*d7;
        #pragma unroll
        for (int o = 16; o > 0; o >>= 1) sq += __shfl_xor_sync(0xffffffffu, sq, o);
        float rstd = rsqrtf(sq * (1.f/CDIM) + 1e-5f);
        float o0 = d0*rstd*gv0.x + tv0.x, o1 = d1*rstd*gv0.y + tv0.y;
        float o2 = d2*rstd*gv0.z + tv0.z, o3 = d3*rstd*gv0.w + tv0.w;
        float o4 = d4*rstd*gv1.x + tv1.x, o5 = d5*rstd*gv1.y + tv1.y;
        float o6 = d6*rstd*gv1.z + tv1.z, o7 = d7*rstd*gv1.w + tv1.w;
        *(float4*)&outp[(size_t)m*CDIM + lane*8]     = make_float4(o0, o1, o2, o3);
        *(float4*)&outp[(size_t)m*CDIM + lane*8 + 4] = make_float4(o4, o5, o6, o7);
        half2* dst = (half2*)&ornd[(size_t)m*CDIM + lane*8];
        dst[0] = __floats2half2_rn(o0, o1);
        dst[1] = __floats2half2_rn(o2, o3);
        dst[2] = __floats2half2_rn(o4, o5);
        dst[3] = __floats2half2_rn(o6, o7);
    }
}

// ---------------- geometry / prep ------------------------------------------------
__global__ void k_invert(const float* __restrict__ extr) {
    int c = threadIdx.x;
    if (c >= NCAM) return;
    float a[4][8];
    for (int i = 0; i < 4; i++)
        for (int j = 0; j < 4; j++) {
            a[i][j] = extr[c*16 + i*4 + j];
            a[i][j+4] = (i == j) ? 1.f : 0.f;
        }
    for (int col = 0; col < 4; col++) {
        int piv = col;
        for (int r = col+1; r < 4; r++)
            if (fabsf(a[r][col]) > fabsf(a[piv][col])) piv = r;
        if (piv != col)
            for (int j = 0; j < 8; j++) { float t = a[col][j]; a[col][j] = a[piv][j]; a[piv][j] = t; }
        float d = 1.f / a[col][col];
        for (int j = 0; j < 8; j++) a[col][j] *= d;
        for (int r = 0; r < 4; r++) {
            if (r == col) continue;
            float f = a[r][col];
            for (int j = 0; j < 8; j++) a[r][j] -= f * a[col][j];
        }
    }
    for (int i = 0; i < 4; i++)
        for (int j = 0; j < 4; j++)
            g_inv[c*16 + i*4 + j] = a[i][j+4];
}

__global__ void k_geom(const float* __restrict__ intr) {
    int idx = blockIdx.x * blockDim.x + threadIdx.x;
    if (idx >= NCAM*NQ*NPTS) return;
    int p = idx % NPTS;
    int n = (idx / NPTS) % NQ;
    int c = idx / (NPTS * NQ);
    float gx = ((n & 127) + 0.5f) / 128.f;
    float gy = ((n >> 7)  + 0.5f) / 128.f;
    float xm = -51.2f + gx * 102.4f;
    float ym = -51.2f + gy * 102.4f;
    float zm = -5.0f + (p + 0.5f) * 2.0f;
    const float* Mi = &g_inv[c*16];
    float px = Mi[0]*xm + Mi[1]*ym + Mi[2]*zm  + Mi[3];
    float py = Mi[4]*xm + Mi[5]*ym + Mi[6]*zm  + Mi[7];
    float pz = Mi[8]*xm + Mi[9]*ym + Mi[10]*zm + Mi[11];
    const float* I = &intr[c*9];
    float ix = I[0]*px + I[1]*py + I[2]*pz;
    float iy = I[3]*px + I[4]*py + I[5]*pz;
    float iz = I[6]*px + I[7]*py + I[8]*pz;
    float zc = fmaxf(iz, 1e-5f);
    float un = ix / (zc * WF);
    float vn = iy / (zc * HF);
    float val = (iz > 1e-5f && un >= 0.f && un <= 1.f && vn >= 0.f && vn <= 1.f) ? 1.f : 0.f;
    g_refcam[idx*2+0] = un;
    g_refcam[idx*2+1] = vn;
    g_valid[idx] = val;
}

__global__ void k_cnt() {
    int n = blockIdx.x * blockDim.x + threadIdx.x;
    if (n >= NQ) return;
    float s = 0.f;
    for (int c = 0; c < NCAM; c++)
        for (int p = 0; p < NPTS; p++)
            s += g_valid[(c*NQ + n)*NPTS + p];
    g_cnt[n] = fmaxf(s, 1.f);
}

__global__ void k_feats_t(const float* __restrict__ in) {
    __shared__ float tile[32][33];
    int pix0 = blockIdx.x * 32, ch0 = blockIdx.y * 32, c = blockIdx.z;
    int tx = threadIdx.x, ty = threadIdx.y;
    for (int i = ty; i < 32; i += 8) {
        int pix = pix0 + tx;
        tile[i][tx] = (pix < NPIX) ? in[((size_t)c*CDIM + ch0 + i)*NPIX + pix] : 0.f;
    }
    __syncthreads();
    for (int i = ty; i < 32; i += 8) {
        int pix = pix0 + i;
        if (pix < NPIX)
            g_feats[((size_t)c*NPIX + pix)*CDIM + ch0 + tx] = __float2half(tile[tx][i]);
    }
}

__global__ void k_round(const float* __restrict__ W, hf* __restrict__ out, int n) {
    int i = blockIdx.x * blockDim.x + threadIdx.x;
    if (i < n) out[i] = __float2half(W[i]);
}

__global__ void k_prep_oa(const float* __restrict__ tow, const float* __restrict__ taw,
                          const float* __restrict__ sow, const float* __restrict__ saw,
                          const float* __restrict__ tob, const float* __restrict__ tab,
                          const float* __restrict__ sob, const float* __restrict__ sab) {
    int idx = blockIdx.x * blockDim.x + threadIdx.x;
    int total = 2*NLAYERS*CDIM*128;
    if (idx < total) {
        int n = idx % 128;
        int k = (idx / 128) % CDIM;
        int l = (idx / (128*CDIM)) % NLAYERS;
        int s = idx / (128*CDIM*NLAYERS);
        const float* ow = s ? sow : tow;
        const float* aw = s ? saw : taw;
        float w = 0.f;
        if (n < 64)      w = ow[((size_t)l*CDIM + k)*64 + n];
        else if (n < 96) w = aw[((size_t)l*CDIM + k)*32 + (n - 64)];
        g_oaw[idx] = __float2half(w);
    }
    if (idx < 2*NLAYERS*128) {
        int j = idx % 128;
        int l = (idx / 128) % NLAYERS;
        int s = idx / (128*NLAYERS);
        const float* ob = s ? sob : tob;
        const float* ab = s ? sab : tab;
        float b = 0.f;
        if (j < 64)      b = ob[l*64 + j];
        else if (j < 96) b = ab[l*32 + (j - 64)];
        g_oab[idx] = b;
    }
}

__global__ void k_init_q(const float* __restrict__ src) {
    int i = blockIdx.x * blockDim.x + threadIdx.x;
    if (i >= NQ*CDIM) return;
    float v = src[i];
    g_q[i] = v;
    g_q_rnd[i] = __float2half(v);
}

// ---------------- samplers (half values) -------------------------------------------
__device__ __forceinline__ float bilin_h(const hf* __restrict__ base, int H, int W,
                                         int stride, float ix, float iy) {
    float x0f = floorf(ix), y0f = floorf(iy);
    int x0 = (int)x0f, y0 = (int)y0f;
    float fx = ix - x0f, fy = iy - y0f;
    float out = 0.f;
    #pragma unroll
    for (int dy = 0; dy < 2; dy++) {
        int yi = y0 + dy;
        if (yi < 0 || yi >= H) continue;
        float wy = dy ? fy : 1.f - fy;
        #pragma unroll
        for (int dx = 0; dx < 2; dx++) {
            int xi = x0 + dx;
            if (xi < 0 || xi >= W) continue;
            float wx = dx ? fx : 1.f - fx;
            out += wy * wx * __half2float(base[((size_t)yi*W + xi) * stride]);
        }
    }
    return out;
}

__global__ void k_tsa_sample() {
    int n = blockIdx.x;
    int h = threadIdx.x >> 5;
    int lane = threadIdx.x & 31;
    const float* oa = &g_offattn[n*96];
    float lg0 = oa[64 + h*4 + 0], lg1 = oa[64 + h*4 + 1];
    float lg2 = oa[64 + h*4 + 2], lg3 = oa[64 + h*4 + 3];
    float mx = fmaxf(fmaxf(lg0, lg1), fmaxf(lg2, lg3));
    float e0 = expf(lg0-mx), e1 = expf(lg1-mx), e2 = expf(lg2-mx), e3 = expf(lg3-mx);
    float rse = 1.f / (e0+e1+e2+e3);
    float w[4] = {e0*rse, e1*rse, e2*rse, e3*rse};
    float refx = ((n & 127) + 0.5f);
    float refy = ((n >> 7)  + 0.5f);
    const hf* base = g_v + h*HD + lane;
    float acc = 0.f;
    #pragma unroll
    for (int p = 0; p < 4; p++) {
        float ox = oa[(h*4 + p)*2 + 0];
        float oy = oa[(h*4 + p)*2 + 1];
        acc += w[p] * bilin_h(base, 128, 128, CDIM, refx + ox - 0.5f, refy + oy - 0.5f);
    }
    g_a[(size_t)n*CDIM + h*HD + lane] = __float2half(acc);
}

__global__ void k_sca_sample() {
    int n = blockIdx.x;
    int h = threadIdx.x >> 5;
    int lane = threadIdx.x & 31;
    const float* oa = &g_offattn[n*96];
    float lg0 = oa[64 + h*4 + 0], lg1 = oa[64 + h*4 + 1];
    float lg2 = oa[64 + h*4 + 2], lg3 = oa[64 + h*4 + 3];
    float mx = fmaxf(fmaxf(lg0, lg1), fmaxf(lg2, lg3));
    float e0 = expf(lg0-mx), e1 = expf(lg1-mx), e2 = expf(lg2-mx), e3 = expf(lg3-mx);
    float rse = 1.f / (e0+e1+e2+e3);
    float w[4], ox[4], oy[4];
    w[0] = e0*rse; w[1] = e1*rse; w[2] = e2*rse; w[3] = e3*rse;
    #pragma unroll
    for (int p = 0; p < 4; p++) {
        ox[p] = oa[(h*4 + p)*2 + 0];
        oy[p] = oa[(h*4 + p)*2 + 1];
    }
    float acc = 0.f;
    for (int c = 0; c < NCAM; c++) {
        const float* rc = &g_refcam[((size_t)(c*NQ + n))*NPTS*2];
        const float* vv = &g_valid[((size_t)(c*NQ + n))*NPTS];
        const hf* base = g_vimg + (size_t)c*NPIX*CDIM + h*HD + lane;
        #pragma unroll
        for (int p = 0; p < 4; p++) {
            if (vv[p] == 0.f) continue;
            float ix = rc[p*2+0]*WF + ox[p] - 0.5f;
            float iy = rc[p*2+1]*HF + oy[p] - 0.5f;
            acc += w[p] * bilin_h(base, HF, WF, CDIM, ix, iy);
        }
    }
    g_a[(size_t)n*CDIM + h*HD + lane] = __float2half(acc / g_cnt[n]);
}

__global__ void k_out_t(float* __restrict__ out) {
    __shared__ float tile[32][33];
    int n0 = blockIdx.x * 32, c0 = blockIdx.y * 32;
    int tx = threadIdx.x, ty = threadIdx.y;
    for (int i = ty; i < 32; i += 8)
        tile[i][tx] = g_q[(size_t)(n0 + i)*CDIM + c0 + tx];
    __syncthreads();
    for (int i = ty; i < 32; i += 8)
        out[(size_t)(c0 + i)*NQ + n0 + tx] = tile[tx][i];
}

// ---------------- host --------------------------------------------------------
static void gemm128_f(cudaStream_t st, const hf* A, const hf* B,
                      const float* bias, float* outf,
                      int M, int N, int K, int ldb) {
    dim3 g((M + TBM - 1) / TBM, (ldb + TBN - 1) / TBN);
    k_gemm128<0, false><<<g, 256, T_SMEM, st>>>(A, nullptr, nullptr, B, bias, outf, nullptr, M, N, K, ldb);
}
static void gemm128_relu(cudaStream_t st, const hf* A, const hf* B,
                         const float* bias, hf* outh,
                         int M, int N, int K, int ldb) {
    dim3 g((M + TBM - 1) / TBM, (ldb + TBN - 1) / TBN);
    k_gemm128<1, false><<<g, 256, T_SMEM, st>>>(A, nullptr, nullptr, B, bias, nullptr, outh, M, N, K, ldb);
}
static void gemm128_h(cudaStream_t st, const hf* A, const hf* B,
                      const float* bias, hf* outh,
                      int M, int N, int K, int ldb) {
    dim3 g((M + TBM - 1) / TBM, (ldb + TBN - 1) / TBN);
    k_gemm128<2, false><<<g, 256, T_SMEM, st>>>(A, nullptr, nullptr, B, bias, nullptr, outh, M, N, K, ldb);
}
static void gemm128_avg_h(const float* A1, const float* A2, const hf* B,
                          const float* bias, hf* outh, int M, int N, int K, int ldb) {
    dim3 g((M + TBM - 1) / TBM, (ldb + TBN - 1) / TBN);
    k_gemm128<2, true><<<g, 256, T_SMEM>>>(nullptr, A1, A2, B, bias, nullptr, outh, M, N, K, ldb);
}
static void gemm_ln(const hf* A, const hf* W, const float* bias,
                    const float* resid, const float* gam, const float* bet,
                    float* outp, hf* ornd, int M, int K) {
    k_gemm_ln<<<M / LM, 256, L_SMEM>>>(A, W, bias, resid, gam, bet, outp, ornd, M, K);
}

extern "C" void kernel_launch(void* const* d_in, const int* in_sizes, int n_in,
                              void* d_out, int out_size) {
    static bool init_done = false;
    static cudaStream_t s2, s3;
    static cudaEvent_t ev_fork[NLAYERS], ev_join[NLAYERS];
    static cudaEvent_t ev_oaf[NLAYERS], ev_oaj[NLAYERS];
    static cudaEvent_t ev_begin, ev_setup;
    if (!init_done) {
        cudaFuncSetAttribute((const void*)k_gemm128<0, false>, cudaFuncAttributeMaxDynamicSharedMemorySize, T_SMEM);
        cudaFuncSetAttribute((const void*)k_gemm128<1, false>, cudaFuncAttributeMaxDynamicSharedMemorySize, T_SMEM);
        cudaFuncSetAttribute((const void*)k_gemm128<2, false>, cudaFuncAttributeMaxDynamicSharedMemorySize, T_SMEM);
        cudaFuncSetAttribute((const void*)k_gemm128<2, true>,  cudaFuncAttributeMaxDynamicSharedMemorySize, T_SMEM);
        cudaFuncSetAttribute((const void*)k_gemm_ln,           cudaFuncAttributeMaxDynamicSharedMemorySize, L_SMEM);
        cudaStreamCreateWithFlags(&s2, cudaStreamNonBlocking);
        cudaStreamCreateWithFlags(&s3, cudaStreamNonBlocking);
        for (int l = 0; l < NLAYERS; l++) {
            cudaEventCreateWithFlags(&ev_fork[l], cudaEventDisableTiming);
            cudaEventCreateWithFlags(&ev_join[l], cudaEventDisableTiming);
            cudaEventCreateWithFlags(&ev_oaf[l],  cudaEventDisableTiming);
            cudaEventCreateWithFlags(&ev_oaj[l],  cudaEventDisableTiming);
        }
        cudaEventCreateWithFlags(&ev_begin, cudaEventDisableTiming);
        cudaEventCreateWithFlags(&ev_setup, cudaEventDisableTiming);
        init_done = true;
    }

    const float* image_feats = (const float*)d_in[0];
    const float* intr        = (const float*)d_in[1];
    const float* extr        = (const float*)d_in[2];
    const float* prev        = (const float*)d_in[3];
    const float* bev         = (const float*)d_in[4];
    const float* tsa_vw = (const float*)d_in[5];
    const float* tsa_vb = (const float*)d_in[6];
    const float* tsa_pw = (const float*)d_in[11];
    const float* tsa_pb = (const float*)d_in[12];
    const float* sca_vw = (const float*)d_in[13];
    const float* sca_vb = (const float*)d_in[14];
    const float* sca_pw = (const float*)d_in[19];
    const float* sca_pb = (const float*)d_in[20];
    const float* ffn_w1 = (const float*)d_in[21];
    const float* ffn_b1 = (const float*)d_in[22];
    const float* ffn_w2 = (const float*)d_in[23];
    const float* ffn_b2 = (const float*)d_in[24];
    const float* ln1_g  = (const float*)d_in[25];
    const float* ln1_b  = (const float*)d_in[26];
    const float* ln2_g  = (const float*)d_in[27];
    const float* ln2_b  = (const float*)d_in[28];
    const float* ln3_g  = (const float*)d_in[29];
    const float* ln3_b  = (const float*)d_in[30];

    float *q_, *oa_, *oab_;
    hf *qr_, *a_, *hid_, *feats_, *v_, *vimg_;
    hf *tvw_, *tpw_, *svw_, *spw_, *f1w_, *f2w_, *oaw_;
    cudaGetSymbolAddress((void**)&q_,    g_q);
    cudaGetSymbolAddress((void**)&qr_,   g_q_rnd);
    cudaGetSymbolAddress((void**)&a_,    g_a);
    cudaGetSymbolAddress((void**)&hid_,  g_hid);
    cudaGetSymbolAddress((void**)&v_,    g_v);
    cudaGetSymbolAddress((void**)&vimg_, g_vimg);
    cudaGetSymbolAddress((void**)&oa_,   g_offattn);
    cudaGetSymbolAddress((void**)&feats_, g_feats);
    cudaGetSymbolAddress((void**)&tvw_,  g_tvw);
    cudaGetSymbolAddress((void**)&tpw_,  g_tpw);
    cudaGetSymbolAddress((void**)&svw_,  g_svw);
    cudaGetSymbolAddress((void**)&spw_,  g_spw);
    cudaGetSymbolAddress((void**)&f1w_,  g_f1w);
    cudaGetSymbolAddress((void**)&f2w_,  g_f2w);
    cudaGetSymbolAddress((void**)&oaw_,  g_oaw);
    cudaGetSymbolAddress((void**)&oab_,  g_oab);

    const int WB = 256;

    cudaEventRecord(ev_begin, 0);
    cudaStreamWaitEvent(s3, ev_begin, 0);
    k_round<<<(NLAYERS*CDIM*CDIM + WB-1)/WB, WB, 0, s3>>>(tsa_vw, tvw_, NLAYERS*CDIM*CDIM);
    k_round<<<(NLAYERS*CDIM*CDIM + WB-1)/WB, WB, 0, s3>>>(tsa_pw, tpw_, NLAYERS*CDIM*CDIM);
    k_round<<<(NLAYERS*CDIM*CDIM + WB-1)/WB, WB, 0, s3>>>(sca_pw, spw_, NLAYERS*CDIM*CDIM);
    k_round<<<(NLAYERS*CDIM*FFN + WB-1)/WB, WB, 0, s3>>>(ffn_w1, f1w_, NLAYERS*CDIM*FFN);
    k_round<<<(NLAYERS*FFN*CDIM + WB-1)/WB, WB, 0, s3>>>(ffn_w2, f2w_, NLAYERS*FFN*CDIM);
    k_prep_oa<<<(2*NLAYERS*CDIM*128 + WB-1)/WB, WB, 0, s3>>>(
        (const float*)d_in[7], (const float*)d_in[9],
        (const float*)d_in[15], (const float*)d_in[17],
        (const float*)d_in[8], (const float*)d_in[10],
        (const float*)d_in[16], (const float*)d_in[18]);
    cudaEventRecord(ev_setup, s3);

    {
        dim3 gt((NPIX + 31)/32, CDIM/32, NCAM);
        k_feats_t<<<gt, dim3(32, 8)>>>(image_feats);
    }
    k_round<<<(NLAYERS*CDIM*CDIM + WB-1)/WB, WB>>>(sca_vw, svw_, NLAYERS*CDIM*CDIM);
    k_invert<<<1, NCAM>>>(extr);
    gemm128_h(0, feats_, svw_, sca_vb, vimg_, NFEAT, CDIM, CDIM, CDIM);  // layer-0 vimg
    k_geom<<<(NCAM*NQ*NPTS + 255)/256, 256>>>(intr);
    k_cnt<<<(NQ + 255)/256, 256>>>();
    k_init_q<<<(NQ*CDIM + 255)/256, 256>>>(bev);
    cudaStreamWaitEvent(0, ev_setup, 0);

    for (int l = 0; l < NLAYERS; l++) {
        size_t wo = (size_t)l*CDIM*CDIM;

        if (l > 0) {
            cudaEventRecord(ev_fork[l], 0);
            cudaStreamWaitEvent(s2, ev_fork[l], 0);
            gemm128_h(s2, feats_, svw_ + wo, sca_vb + l*CDIM, vimg_,
                      NFEAT, CDIM, CDIM, CDIM);
            cudaEventRecord(ev_join[l], s2);
        }

        cudaEventRecord(ev_oaf[l], 0);
        cudaStreamWaitEvent(s3, ev_oaf[l], 0);
        gemm128_f(s3, qr_, oaw_ + (size_t)l*CDIM*128, oab_ + l*128, oa_,
                  NQ, 96, CDIM, 128);
        cudaEventRecord(ev_oaj[l], s3);

        // ---- TSA (main) ----
        gemm128_avg_h(q_, prev, tvw_ + wo, tsa_vb + l*CDIM, v_, NQ, CDIM, CDIM, CDIM);
        cudaStreamWaitEvent(0, ev_oaj[l], 0);
        k_tsa_sample<<<NQ, 256>>>();
        gemm_ln(a_, tpw_ + wo, tsa_pb + l*CDIM, q_, ln1_g + l*CDIM, ln1_b + l*CDIM,
                q_, qr_, NQ, CDIM);

        // ---- SCA ----
        gemm128_f(0, qr_, oaw_ + (size_t)(NLAYERS + l)*CDIM*128, oab_ + (NLAYERS + l)*128,
                  oa_, NQ, 96, CDIM, 128);
        if (l > 0)
            cudaStreamWaitEvent(0, ev_join[l], 0);
        k_sca_sample<<<NQ, 256>>>();
        gemm_ln(a_, spw_ + wo, sca_pb + l*CDIM, q_, ln2_g + l*CDIM, ln2_b + l*CDIM,
                q_, qr_, NQ, CDIM);

        // ---- FFN ----
        gemm128_relu(0, qr_, f1w_ + (size_t)l*CDIM*FFN, ffn_b1 + l*FFN, hid_,
                     NQ, FFN, CDIM, FFN);
        gemm_ln(hid_, f2w_ + (size_t)l*FFN*CDIM, ffn_b2 + l*CDIM, q_,
                ln3_g + l*CDIM, ln3_b + l*CDIM, q_, qr_, NQ, FFN);
    }

    k_out_t<<<dim3(NQ/32, CDIM/32), dim3(32, 8)>>>((float*)d_out);
}

// round 17
// speedup vs baseline: 2.2865x; 1.2616x over previous
#include <cuda_runtime.h>
#include <cuda_fp16.h>
#include <math.h>
#include <stdint.h>
#include <mma.h>

using namespace nvcuda;
typedef __half hf;

#define NQ      16384
#define CDIM    256
#define HEADS   8
#define HD      32
#define NPTS    4
#define NLAYERS 6
#define NCAM    6
#define HF      58
#define WF      100
#define NPIX    (HF*WF)
#define NFEAT   (NCAM*NPIX)
#define FFN     512

// ---------------- scratch ----------------------------------------------------
__device__ __align__(256) float g_q[NQ*CDIM];
__device__ __align__(256) hf    g_q_rnd[NQ*CDIM];
__device__ __align__(256) hf    g_a[NQ*CDIM];
__device__ __align__(256) hf    g_hid[NQ*FFN];
__device__ __align__(256) hf    g_v[NQ*CDIM];
__device__ __align__(256) hf    g_vimg[NFEAT*CDIM];
__device__ __align__(256) float g_offattn[NQ*96];
__device__ __align__(256) hf    g_feats[NFEAT*CDIM];
__device__ __align__(256) float g_refcam[NCAM*NQ*NPTS*2];
__device__ __align__(256) float g_valid[NCAM*NQ*NPTS];
__device__ __align__(256) float g_cnt[NQ];
__device__ __align__(256) float g_inv[NCAM*16];
__device__ __align__(256) hf    g_tvw[NLAYERS*CDIM*CDIM];
__device__ __align__(256) hf    g_tpw[NLAYERS*CDIM*CDIM];
__device__ __align__(256) hf    g_svw[NLAYERS*CDIM*CDIM];
__device__ __align__(256) hf    g_spw[NLAYERS*CDIM*CDIM];
__device__ __align__(256) hf    g_f1w[NLAYERS*CDIM*FFN];
__device__ __align__(256) hf    g_f2w[NLAYERS*FFN*CDIM];
__device__ __align__(256) hf    g_oaw[2*NLAYERS*CDIM*128];
__device__ __align__(256) float g_oab[2*NLAYERS*128];

// ---------------- helpers ------------------------------------------------------
__device__ __forceinline__ void cp_async16(void* sp, const void* gp) {
    uint32_t s = (uint32_t)__cvta_generic_to_shared(sp);
    asm volatile("cp.async.cg.shared.global [%0], [%1], 16;\n" :: "r"(s), "l"(gp));
}
__device__ __forceinline__ void cp_commit() { asm volatile("cp.async.commit_group;\n" ::: "memory"); }
template<int N> __device__ __forceinline__ void cp_wait() {
    asm volatile("cp.async.wait_group %0;\n" :: "n"(N) : "memory");
}

// ---------------- fp16 GEMM: 128x128 tile, BK=64, 2-stage ----------------------
#define TBM 128
#define TBN 128
#define TBK 64
#define TLDA 80
#define TLDB 144
#define TA_ST (TBM*TLDA)
#define TB_ST (TBK*TLDB)
#define TLDC 132
#define T_SMEM ((2*(TA_ST+TB_ST))*2)

template<int EPI, bool AVG>
__global__ __launch_bounds__(256, 2) void k_gemm128(
    const hf* __restrict__ Ah, const float* __restrict__ Af1, const float* __restrict__ Af2,
    const hf* __restrict__ B,
    const float* __restrict__ bias, float* __restrict__ outf, hf* __restrict__ outh,
    int M, int N, int K, int ldb)
{
    extern __shared__ char smraw[];
    hf* As = (hf*)smraw;
    hf* Bs = As + 2*TA_ST;
    float* Cs = (float*)smraw;

    int tid = threadIdx.x;
    int wid = tid >> 5;
    int wr = wid & 1;
    int wc = wid >> 1;
    int m0 = blockIdx.x * TBM;
    int n0 = blockIdx.y * TBN;

    wmma::fragment<wmma::accumulator, 16, 16, 16, float> c[4][2];
    #pragma unroll
    for (int i = 0; i < 4; i++)
        #pragma unroll
        for (int j = 0; j < 2; j++)
            wmma::fill_fragment(c[i][j], 0.f);

    auto load_st = [&](int t, int b) {
        int k0 = t * TBK;
        hf* as = As + b*TA_ST;
        hf* bs = Bs + b*TB_ST;
        #pragma unroll
        for (int i = 0; i < 4; i++) {
            int cid = tid + i*256;
            int r = cid >> 3, c8 = cid & 7;
            int m = m0 + r; if (m >= M) m = M - 1;
            if (AVG) {
                const float* p1 = &Af1[(size_t)m*K + k0 + c8*8];
                const float* p2 = &Af2[(size_t)m*K + k0 + c8*8];
                float4 a0 = *(const float4*)p1, a1 = *(const float4*)(p1+4);
                float4 b0 = *(const float4*)p2, b1 = *(const float4*)(p2+4);
                half2* dst = (half2*)&as[r*TLDA + c8*8];
                dst[0] = __floats2half2_rn(0.5f*(a0.x+b0.x), 0.5f*(a0.y+b0.y));
                dst[1] = __floats2half2_rn(0.5f*(a0.z+b0.z), 0.5f*(a0.w+b0.w));
                dst[2] = __floats2half2_rn(0.5f*(a1.x+b1.x), 0.5f*(a1.y+b1.y));
                dst[3] = __floats2half2_rn(0.5f*(a1.z+b1.z), 0.5f*(a1.w+b1.w));
            } else {
                cp_async16(&as[r*TLDA + c8*8], &Ah[(size_t)m*K + k0 + c8*8]);
            }
        }
        #pragma unroll
        for (int i = 0; i < 4; i++) {
            int cid = tid + i*256;
            int r = cid >> 4, c8 = cid & 15;
            cp_async16(&bs[r*TLDB + c8*8], &B[(size_t)(k0 + r)*ldb + n0 + c8*8]);
        }
        cp_commit();
    };

    int T = K / TBK;
    load_st(0, 0);
    for (int t = 0; t < T; t++) {
        int b = t & 1;
        if (t + 1 < T) {
            load_st(t + 1, b ^ 1);
            cp_wait<1>();
        } else {
            cp_wait<0>();
        }
        __syncthreads();
        const hf* as = As + b*TA_ST;
        const hf* bs = Bs + b*TB_ST;
        #pragma unroll
        for (int kk = 0; kk < TBK; kk += 16) {
            wmma::fragment<wmma::matrix_a, 16, 16, 16, hf, wmma::row_major> a[4];
            wmma::fragment<wmma::matrix_b, 16, 16, 16, hf, wmma::row_major> bfrag[2];
            #pragma unroll
            for (int i = 0; i < 4; i++)
                wmma::load_matrix_sync(a[i], &as[(wr*64 + i*16)*TLDA + kk], TLDA);
            #pragma unroll
            for (int j = 0; j < 2; j++)
                wmma::load_matrix_sync(bfrag[j], &bs[kk*TLDB + wc*32 + j*16], TLDB);
            #pragma unroll
            for (int i = 0; i < 4; i++)
                #pragma unroll
                for (int j = 0; j < 2; j++)
                    wmma::mma_sync(c[i][j], a[i], bfrag[j], c[i][j]);
        }
        __syncthreads();
    }

    int e4 = tid & 31, er = tid >> 5;
    int nn = n0 + e4*4;
    float4 bv = make_float4(0.f, 0.f, 0.f, 0.f);
    if (nn < N) bv = *(const float4*)&bias[nn];
    #pragma unroll
    for (int chunk = 0; chunk < 2; chunk++) {
        if (wr == chunk) {
            #pragma unroll
            for (int i = 0; i < 4; i++)
                #pragma unroll
                for (int j = 0; j < 2; j++)
                    wmma::store_matrix_sync(&Cs[(i*16)*TLDC + wc*32 + j*16],
                                            c[i][j], TLDC, wmma::mem_row_major);
        }
        __syncthreads();
        if (nn < N) {
            #pragma unroll
            for (int i = 0; i < 8; i++) {
                int r = er + i*8;
                int m = m0 + chunk*64 + r;
                if (m < M) {
                    float4 v = *(float4*)&Cs[r*TLDC + e4*4];
                    v.x += bv.x; v.y += bv.y; v.z += bv.z; v.w += bv.w;
                    if (EPI == 0) {
                        *(float4*)&outf[(size_t)m*N + nn] = v;
                    } else if (EPI == 1) {
                        half2* dst = (half2*)&outh[(size_t)m*N + nn];
                        dst[0] = __floats2half2_rn(fmaxf(v.x, 0.f), fmaxf(v.y, 0.f));
                        dst[1] = __floats2half2_rn(fmaxf(v.z, 0.f), fmaxf(v.w, 0.f));
                    } else {
                        half2* dst = (half2*)&outh[(size_t)m*N + nn];
                        dst[0] = __floats2half2_rn(v.x, v.y);
                        dst[1] = __floats2half2_rn(v.z, v.w);
                    }
                }
            }
        }
        __syncthreads();
    }
}

// ---------------- fused fp16 GEMM + residual + LN (N=256), BK=32 ---------------
#define LM 64
#define LBK 32
#define LLDA 48
#define LLDB 272
#define LA_ST (LM*LLDA)
#define LB_ST (LBK*LLDB)
#define LLDC 260
#define L_SMEM (LM*LLDC*4)

__global__ __launch_bounds__(256, 2) void k_gemm_ln(
    const hf* __restrict__ A, const hf* __restrict__ W,
    const float* __restrict__ bias, const float* __restrict__ resid,
    const float* __restrict__ gam, const float* __restrict__ bet,
    float* __restrict__ outp, hf* __restrict__ ornd, int M, int K)
{
    extern __shared__ char smraw[];
    hf* As = (hf*)smraw;
    hf* Bs = As + 2*LA_ST;
    float* Cs = (float*)smraw;

    int tid = threadIdx.x;
    int wid = tid >> 5;
    int lane = tid & 31;
    int wr = wid & 1;
    int wc = wid >> 1;
    int m0 = blockIdx.x * LM;

    wmma::fragment<wmma::accumulator, 16, 16, 16, float> c[2][4];
    #pragma unroll
    for (int i = 0; i < 2; i++)
        #pragma unroll
        for (int j = 0; j < 4; j++)
            wmma::fill_fragment(c[i][j], 0.f);

    auto load_st = [&](int t, int b) {
        int k0 = t * LBK;
        hf* as = As + b*LA_ST;
        hf* bs = Bs + b*LB_ST;
        {
            int r = tid >> 2, c8 = tid & 3;
            cp_async16(&as[r*LLDA + c8*8], &A[(size_t)(m0 + r)*K + k0 + c8*8]);
        }
        #pragma unroll
        for (int i = 0; i < 4; i++) {
            int cid = tid + i*256;
            int r = cid >> 5, c8 = cid & 31;
            cp_async16(&bs[r*LLDB + c8*8], &W[(size_t)(k0 + r)*CDIM + c8*8]);
        }
        cp_commit();
    };

    int T = K / LBK;
    load_st(0, 0);
    for (int t = 0; t < T; t++) {
        int b = t & 1;
        if (t + 1 < T) {
            load_st(t + 1, b ^ 1);
            cp_wait<1>();
        } else {
            cp_wait<0>();
        }
        __syncthreads();
        const hf* as = As + b*LA_ST;
        const hf* bs = Bs + b*LB_ST;
        #pragma unroll
        for (int kk = 0; kk < LBK; kk += 16) {
            wmma::fragment<wmma::matrix_a, 16, 16, 16, hf, wmma::row_major> a[2];
            wmma::fragment<wmma::matrix_b, 16, 16, 16, hf, wmma::row_major> bfrag[4];
            #pragma unroll
            for (int i = 0; i < 2; i++)
                wmma::load_matrix_sync(a[i], &as[(wr*32 + i*16)*LLDA + kk], LLDA);
            #pragma unroll
            for (int j = 0; j < 4; j++)
                wmma::load_matrix_sync(bfrag[j], &bs[kk*LLDB + wc*64 + j*16], LLDB);
            #pragma unroll
            for (int i = 0; i < 2; i++)
                #pragma unroll
                for (int j = 0; j < 4; j++)
                    wmma::mma_sync(c[i][j], a[i], bfrag[j], c[i][j]);
        }
        __syncthreads();
    }

    #pragma unroll
    for (int i = 0; i < 2; i++)
        #pragma unroll
        for (int j = 0; j < 4; j++)
            wmma::store_matrix_sync(&Cs[(wr*32 + i*16)*LLDC + wc*64 + j*16],
                                    c[i][j], LLDC, wmma::mem_row_major);
    __syncthreads();

    float4 bv0 = *(const float4*)&bias[lane*8];
    float4 bv1 = *(const float4*)&bias[lane*8 + 4];
    float4 gv0 = *(const float4*)&gam[lane*8];
    float4 gv1 = *(const float4*)&gam[lane*8 + 4];
    float4 tv0 = *(const float4*)&bet[lane*8];
    float4 tv1 = *(const float4*)&bet[lane*8 + 4];

    #pragma unroll
    for (int i = 0; i < 8; i++) {
        int r = wid*8 + i;
        int m = m0 + r;
        float4 c0 = *(float4*)&Cs[r*LLDC + lane*8];
        float4 c1 = *(float4*)&Cs[r*LLDC + lane*8 + 4];
        float4 q0 = *(const float4*)&resid[(size_t)m*CDIM + lane*8];
        float4 q1 = *(const float4*)&resid[(size_t)m*CDIM + lane*8 + 4];
        float x0 = q0.x + c0.x + bv0.x, x1 = q0.y + c0.y + bv0.y;
        float x2 = q0.z + c0.z + bv0.z, x3 = q0.w + c0.w + bv0.w;
        float x4 = q1.x + c1.x + bv1.x, x5 = q1.y + c1.y + bv1.y;
        float x6 = q1.z + c1.z + bv1.z, x7 = q1.w + c1.w + bv1.w;
        float s = x0+x1+x2+x3+x4+x5+x6+x7;
        #pragma unroll
        for (int o = 16; o > 0; o >>= 1) s += __shfl_xor_sync(0xffffffffu, s, o);
        float mean = s * (1.f/CDIM);
        float d0 = x0-mean, d1 = x1-mean, d2 = x2-mean, d3 = x3-mean;
        float d4 = x4-mean, d5 = x5-mean, d6 = x6-mean, d7 = x7-mean;
        float sq = d0*d0+d1*d1+d2*d2+d3*d3+d4*d4+d5*d5+d6*d6+d7*d7;
        #pragma unroll
        for (int o = 16; o > 0; o >>= 1) sq += __shfl_xor_sync(0xffffffffu, sq, o);
        float rstd = rsqrtf(sq * (1.f/CDIM) + 1e-5f);
        float o0 = d0*rstd*gv0.x + tv0.x, o1 = d1*rstd*gv0.y + tv0.y;
        float o2 = d2*rstd*gv0.z + tv0.z, o3 = d3*rstd*gv0.w + tv0.w;
        float o4 = d4*rstd*gv1.x + tv1.x, o5 = d5*rstd*gv1.y + tv1.y;
        float o6 = d6*rstd*gv1.z + tv1.z, o7 = d7*rstd*gv1.w + tv1.w;
        *(float4*)&outp[(size_t)m*CDIM + lane*8]     = make_float4(o0, o1, o2, o3);
        *(float4*)&outp[(size_t)m*CDIM + lane*8 + 4] = make_float4(o4, o5, o6, o7);
        half2* dst = (half2*)&ornd[(size_t)m*CDIM + lane*8];
        dst[0] = __floats2half2_rn(o0, o1);
        dst[1] = __floats2half2_rn(o2, o3);
        dst[2] = __floats2half2_rn(o4, o5);
        dst[3] = __floats2half2_rn(o6, o7);
    }
}

// ---------------- geometry / prep ------------------------------------------------
__global__ void k_invert(const float* __restrict__ extr) {
    int c = threadIdx.x;
    if (c >= NCAM) return;
    float a[4][8];
    for (int i = 0; i < 4; i++)
        for (int j = 0; j < 4; j++) {
            a[i][j] = extr[c*16 + i*4 + j];
            a[i][j+4] = (i == j) ? 1.f : 0.f;
        }
    for (int col = 0; col < 4; col++) {
        int piv = col;
        for (int r = col+1; r < 4; r++)
            if (fabsf(a[r][col]) > fabsf(a[piv][col])) piv = r;
        if (piv != col)
            for (int j = 0; j < 8; j++) { float t = a[col][j]; a[col][j] = a[piv][j]; a[piv][j] = t; }
        float d = 1.f / a[col][col];
        for (int j = 0; j < 8; j++) a[col][j] *= d;
        for (int r = 0; r < 4; r++) {
            if (r == col) continue;
            float f = a[r][col];
            for (int j = 0; j < 8; j++) a[r][j] -= f * a[col][j];
        }
    }
    for (int i = 0; i < 4; i++)
        for (int j = 0; j < 4; j++)
            g_inv[c*16 + i*4 + j] = a[i][j+4];
}

__global__ void k_geom(const float* __restrict__ intr) {
    int idx = blockIdx.x * blockDim.x + threadIdx.x;
    if (idx >= NCAM*NQ*NPTS) return;
    int p = idx % NPTS;
    int n = (idx / NPTS) % NQ;
    int c = idx / (NPTS * NQ);
    float gx = ((n & 127) + 0.5f) / 128.f;
    float gy = ((n >> 7)  + 0.5f) / 128.f;
    float xm = -51.2f + gx * 102.4f;
    float ym = -51.2f + gy * 102.4f;
    float zm = -5.0f + (p + 0.5f) * 2.0f;
    const float* Mi = &g_inv[c*16];
    float px = Mi[0]*xm + Mi[1]*ym + Mi[2]*zm  + Mi[3];
    float py = Mi[4]*xm + Mi[5]*ym + Mi[6]*zm  + Mi[7];
    float pz = Mi[8]*xm + Mi[9]*ym + Mi[10]*zm + Mi[11];
    const float* I = &intr[c*9];
    float ix = I[0]*px + I[1]*py + I[2]*pz;
    float iy = I[3]*px + I[4]*py + I[5]*pz;
    float iz = I[6]*px + I[7]*py + I[8]*pz;
    float zc = fmaxf(iz, 1e-5f);
    float un = ix / (zc * WF);
    float vn = iy / (zc * HF);
    float val = (iz > 1e-5f && un >= 0.f && un <= 1.f && vn >= 0.f && vn <= 1.f) ? 1.f : 0.f;
    g_refcam[idx*2+0] = un;
    g_refcam[idx*2+1] = vn;
    g_valid[idx] = val;
}

__global__ void k_cnt() {
    int n = blockIdx.x * blockDim.x + threadIdx.x;
    if (n >= NQ) return;
    float s = 0.f;
    for (int c = 0; c < NCAM; c++)
        for (int p = 0; p < NPTS; p++)
            s += g_valid[(c*NQ + n)*NPTS + p];
    g_cnt[n] = fmaxf(s, 1.f);
}

__global__ void k_feats_t(const float* __restrict__ in) {
    __shared__ float tile[32][33];
    int pix0 = blockIdx.x * 32, ch0 = blockIdx.y * 32, c = blockIdx.z;
    int tx = threadIdx.x, ty = threadIdx.y;
    for (int i = ty; i < 32; i += 8) {
        int pix = pix0 + tx;
        tile[i][tx] = (pix < NPIX) ? in[((size_t)c*CDIM + ch0 + i)*NPIX + pix] : 0.f;
    }
    __syncthreads();
    for (int i = ty; i < 32; i += 8) {
        int pix = pix0 + i;
        if (pix < NPIX)
            g_feats[((size_t)c*NPIX + pix)*CDIM + ch0 + tx] = __float2half(tile[tx][i]);
    }
}

__global__ void k_round(const float* __restrict__ W, hf* __restrict__ out, int n) {
    int i = blockIdx.x * blockDim.x + threadIdx.x;
    if (i < n) out[i] = __float2half(W[i]);
}

__global__ void k_prep_oa(const float* __restrict__ tow, const float* __restrict__ taw,
                          const float* __restrict__ sow, const float* __restrict__ saw,
                          const float* __restrict__ tob, const float* __restrict__ tab,
                          const float* __restrict__ sob, const float* __restrict__ sab) {
    int idx = blockIdx.x * blockDim.x + threadIdx.x;
    int total = 2*NLAYERS*CDIM*128;
    if (idx < total) {
        int n = idx % 128;
        int k = (idx / 128) % CDIM;
        int l = (idx / (128*CDIM)) % NLAYERS;
        int s = idx / (128*CDIM*NLAYERS);
        const float* ow = s ? sow : tow;
        const float* aw = s ? saw : taw;
        float w = 0.f;
        if (n < 64)      w = ow[((size_t)l*CDIM + k)*64 + n];
        else if (n < 96) w = aw[((size_t)l*CDIM + k)*32 + (n - 64)];
        g_oaw[idx] = __float2half(w);
    }
    if (idx < 2*NLAYERS*128) {
        int j = idx % 128;
        int l = (idx / 128) % NLAYERS;
        int s = idx / (128*NLAYERS);
        const float* ob = s ? sob : tob;
        const float* ab = s ? sab : tab;
        float b = 0.f;
        if (j < 64)      b = ob[l*64 + j];
        else if (j < 96) b = ab[l*32 + (j - 64)];
        g_oab[idx] = b;
    }
}

__global__ void k_init_q(const float* __restrict__ src) {
    int i = blockIdx.x * blockDim.x + threadIdx.x;
    if (i >= NQ*CDIM) return;
    float v = src[i];
    g_q[i] = v;
    g_q_rnd[i] = __float2half(v);
}

// ---------------- samplers: half2 lanes, warp = 2 heads, block = 2 queries --------
__device__ __forceinline__ float2 bilin_h2(const half2* __restrict__ base, int H, int W,
                                           int stride2, float ix, float iy) {
    float x0f = floorf(ix), y0f = floorf(iy);
    int x0 = (int)x0f, y0 = (int)y0f;
    float fx = ix - x0f, fy = iy - y0f;
    float2 out = make_float2(0.f, 0.f);
    #pragma unroll
    for (int dy = 0; dy < 2; dy++) {
        int yi = y0 + dy;
        if (yi < 0 || yi >= H) continue;
        float wy = dy ? fy : 1.f - fy;
        #pragma unroll
        for (int dx = 0; dx < 2; dx++) {
            int xi = x0 + dx;
            if (xi < 0 || xi >= W) continue;
            float wx = dx ? fx : 1.f - fx;
            float ww = wy * wx;
            float2 t = __half22float2(base[((size_t)yi*W + xi) * stride2]);
            out.x += ww * t.x;
            out.y += ww * t.y;
        }
    }
    return out;
}

// grid = NQ/2, block = 256 (8 warps = 2 queries x 4 head-pairs)
__global__ void k_tsa_sample() {
    int warp = threadIdx.x >> 5;
    int lane = threadIdx.x & 31;
    int n = blockIdx.x*2 + (warp >> 2);
    int g = warp & 3;
    int h = g*2 + (lane >> 4);
    int c2 = lane & 15;                 // half2 channel index within head
    const float* oa = &g_offattn[n*96];
    float lg0 = oa[64 + h*4 + 0], lg1 = oa[64 + h*4 + 1];
    float lg2 = oa[64 + h*4 + 2], lg3 = oa[64 + h*4 + 3];
    float mx = fmaxf(fmaxf(lg0, lg1), fmaxf(lg2, lg3));
    float e0 = expf(lg0-mx), e1 = expf(lg1-mx), e2 = expf(lg2-mx), e3 = expf(lg3-mx);
    float rse = 1.f / (e0+e1+e2+e3);
    float w[4] = {e0*rse, e1*rse, e2*rse, e3*rse};
    float refx = ((n & 127) + 0.5f);
    float refy = ((n >> 7)  + 0.5f);
    const half2* base = (const half2*)g_v + h*(HD/2) + c2;
    float2 acc = make_float2(0.f, 0.f);
    #pragma unroll
    for (int p = 0; p < 4; p++) {
        float ox = oa[(h*4 + p)*2 + 0];
        float oy = oa[(h*4 + p)*2 + 1];
        float2 t = bilin_h2(base, 128, 128, CDIM/2, refx + ox - 0.5f, refy + oy - 0.5f);
        acc.x += w[p] * t.x;
        acc.y += w[p] * t.y;
    }
    half2* dst = (half2*)&g_a[(size_t)n*CDIM + h*HD + c2*2];
    *dst = __floats2half2_rn(acc.x, acc.y);
}

__global__ void k_sca_sample() {
    int warp = threadIdx.x >> 5;
    int lane = threadIdx.x & 31;
    int n = blockIdx.x*2 + (warp >> 2);
    int g = warp & 3;
    int h = g*2 + (lane >> 4);
    int c2 = lane & 15;
    const float* oa = &g_offattn[n*96];
    float lg0 = oa[64 + h*4 + 0], lg1 = oa[64 + h*4 + 1];
    float lg2 = oa[64 + h*4 + 2], lg3 = oa[64 + h*4 + 3];
    float mx = fmaxf(fmaxf(lg0, lg1), fmaxf(lg2, lg3));
    float e0 = expf(lg0-mx), e1 = expf(lg1-mx), e2 = expf(lg2-mx), e3 = expf(lg3-mx);
    float rse = 1.f / (e0+e1+e2+e3);
    float w[4], ox[4], oy[4];
    w[0] = e0*rse; w[1] = e1*rse; w[2] = e2*rse; w[3] = e3*rse;
    #pragma unroll
    for (int p = 0; p < 4; p++) {
        ox[p] = oa[(h*4 + p)*2 + 0];
        oy[p] = oa[(h*4 + p)*2 + 1];
    }
    float2 acc = make_float2(0.f, 0.f);
    for (int c = 0; c < NCAM; c++) {
        const float* rc = &g_refcam[((size_t)(c*NQ + n))*NPTS*2];
        const float* vv = &g_valid[((size_t)(c*NQ + n))*NPTS];
        const half2* base = (const half2*)g_vimg + (size_t)c*NPIX*(CDIM/2) + h*(HD/2) + c2;
        #pragma unroll
        for (int p = 0; p < 4; p++) {
            if (vv[p] == 0.f) continue;
            float ix = rc[p*2+0]*WF + ox[p] - 0.5f;
            float iy = rc[p*2+1]*HF + oy[p] - 0.5f;
            float2 t = bilin_h2(base, HF, WF, CDIM/2, ix, iy);
            acc.x += w[p] * t.x;
            acc.y += w[p] * t.y;
        }
    }
    float rc_ = 1.f / g_cnt[n];
    half2* dst = (half2*)&g_a[(size_t)n*CDIM + h*HD + c2*2];
    *dst = __floats2half2_rn(acc.x * rc_, acc.y * rc_);
}

__global__ void k_out_t(float* __restrict__ out) {
    __shared__ float tile[32][33];
    int n0 = blockIdx.x * 32, c0 = blockIdx.y * 32;
    int tx = threadIdx.x, ty = threadIdx.y;
    for (int i = ty; i < 32; i += 8)
        tile[i][tx] = g_q[(size_t)(n0 + i)*CDIM + c0 + tx];
    __syncthreads();
    for (int i = ty; i < 32; i += 8)
        out[(size_t)(c0 + i)*NQ + n0 + tx] = tile[tx][i];
}

// ---------------- host --------------------------------------------------------
static void gemm128_f(cudaStream_t st, const hf* A, const hf* B,
                      const float* bias, float* outf,
                      int M, int N, int K, int ldb) {
    dim3 g((M + TBM - 1) / TBM, (ldb + TBN - 1) / TBN);
    k_gemm128<0, false><<<g, 256, T_SMEM, st>>>(A, nullptr, nullptr, B, bias, outf, nullptr, M, N, K, ldb);
}
static void gemm128_relu(cudaStream_t st, const hf* A, const hf* B,
                         const float* bias, hf* outh,
                         int M, int N, int K, int ldb) {
    dim3 g((M + TBM - 1) / TBM, (ldb + TBN - 1) / TBN);
    k_gemm128<1, false><<<g, 256, T_SMEM, st>>>(A, nullptr, nullptr, B, bias, nullptr, outh, M, N, K, ldb);
}
static void gemm128_h(cudaStream_t st, const hf* A, const hf* B,
                      const float* bias, hf* outh,
                      int M, int N, int K, int ldb) {
    dim3 g((M + TBM - 1) / TBM, (ldb + TBN - 1) / TBN);
    k_gemm128<2, false><<<g, 256, T_SMEM, st>>>(A, nullptr, nullptr, B, bias, nullptr, outh, M, N, K, ldb);
}
static void gemm128_avg_h(const float* A1, const float* A2, const hf* B,
                          const float* bias, hf* outh, int M, int N, int K, int ldb) {
    dim3 g((M + TBM - 1) / TBM, (ldb + TBN - 1) / TBN);
    k_gemm128<2, true><<<g, 256, T_SMEM>>>(nullptr, A1, A2, B, bias, nullptr, outh, M, N, K, ldb);
}
static void gemm_ln(const hf* A, const hf* W, const float* bias,
                    const float* resid, const float* gam, const float* bet,
                    float* outp, hf* ornd, int M, int K) {
    k_gemm_ln<<<M / LM, 256, L_SMEM>>>(A, W, bias, resid, gam, bet, outp, ornd, M, K);
}

extern "C" void kernel_launch(void* const* d_in, const int* in_sizes, int n_in,
                              void* d_out, int out_size) {
    static bool init_done = false;
    static cudaStream_t s2, s3;
    static cudaEvent_t ev_fork[NLAYERS], ev_join[NLAYERS];
    static cudaEvent_t ev_oaf[NLAYERS], ev_oaj[NLAYERS];
    static cudaEvent_t ev_begin, ev_setup;
    if (!init_done) {
        cudaFuncSetAttribute((const void*)k_gemm128<0, false>, cudaFuncAttributeMaxDynamicSharedMemorySize, T_SMEM);
        cudaFuncSetAttribute((const void*)k_gemm128<1, false>, cudaFuncAttributeMaxDynamicSharedMemorySize, T_SMEM);
        cudaFuncSetAttribute((const void*)k_gemm128<2, false>, cudaFuncAttributeMaxDynamicSharedMemorySize, T_SMEM);
        cudaFuncSetAttribute((const void*)k_gemm128<2, true>,  cudaFuncAttributeMaxDynamicSharedMemorySize, T_SMEM);
        cudaFuncSetAttribute((const void*)k_gemm_ln,           cudaFuncAttributeMaxDynamicSharedMemorySize, L_SMEM);
        cudaStreamCreateWithFlags(&s2, cudaStreamNonBlocking);
        cudaStreamCreateWithFlags(&s3, cudaStreamNonBlocking);
        for (int l = 0; l < NLAYERS; l++) {
            cudaEventCreateWithFlags(&ev_fork[l], cudaEventDisableTiming);
            cudaEventCreateWithFlags(&ev_join[l], cudaEventDisableTiming);
            cudaEventCreateWithFlags(&ev_oaf[l],  cudaEventDisableTiming);
            cudaEventCreateWithFlags(&ev_oaj[l],  cudaEventDisableTiming);
        }
        cudaEventCreateWithFlags(&ev_begin, cudaEventDisableTiming);
        cudaEventCreateWithFlags(&ev_setup, cudaEventDisableTiming);
        init_done = true;
    }

    const float* image_feats = (const float*)d_in[0];
    const float* intr        = (const float*)d_in[1];
    const float* extr        = (const float*)d_in[2];
    const float* prev        = (const float*)d_in[3];
    const float* bev         = (const float*)d_in[4];
    const float* tsa_vw = (const float*)d_in[5];
    const float* tsa_vb = (const float*)d_in[6];
    const float* tsa_pw = (const float*)d_in[11];
    const float* tsa_pb = (const float*)d_in[12];
    const float* sca_vw = (const float*)d_in[13];
    const float* sca_vb = (const float*)d_in[14];
    const float* sca_pw = (const float*)d_in[19];
    const float* sca_pb = (const float*)d_in[20];
    const float* ffn_w1 = (const float*)d_in[21];
    const float* ffn_b1 = (const float*)d_in[22];
    const float* ffn_w2 = (const float*)d_in[23];
    const float* ffn_b2 = (const float*)d_in[24];
    const float* ln1_g  = (const float*)d_in[25];
    const float* ln1_b  = (const float*)d_in[26];
    const float* ln2_g  = (const float*)d_in[27];
    const float* ln2_b  = (const float*)d_in[28];
    const float* ln3_g  = (const float*)d_in[29];
    const float* ln3_b  = (const float*)d_in[30];

    float *q_, *oa_, *oab_;
    hf *qr_, *a_, *hid_, *feats_, *v_, *vimg_;
    hf *tvw_, *tpw_, *svw_, *spw_, *f1w_, *f2w_, *oaw_;
    cudaGetSymbolAddress((void**)&q_,    g_q);
    cudaGetSymbolAddress((void**)&qr_,   g_q_rnd);
    cudaGetSymbolAddress((void**)&a_,    g_a);
    cudaGetSymbolAddress((void**)&hid_,  g_hid);
    cudaGetSymbolAddress((void**)&v_,    g_v);
    cudaGetSymbolAddress((void**)&vimg_, g_vimg);
    cudaGetSymbolAddress((void**)&oa_,   g_offattn);
    cudaGetSymbolAddress((void**)&feats_, g_feats);
    cudaGetSymbolAddress((void**)&tvw_,  g_tvw);
    cudaGetSymbolAddress((void**)&tpw_,  g_tpw);
    cudaGetSymbolAddress((void**)&svw_,  g_svw);
    cudaGetSymbolAddress((void**)&spw_,  g_spw);
    cudaGetSymbolAddress((void**)&f1w_,  g_f1w);
    cudaGetSymbolAddress((void**)&f2w_,  g_f2w);
    cudaGetSymbolAddress((void**)&oaw_,  g_oaw);
    cudaGetSymbolAddress((void**)&oab_,  g_oab);

    const int WB = 256;

    cudaEventRecord(ev_begin, 0);
    cudaStreamWaitEvent(s3, ev_begin, 0);
    k_round<<<(NLAYERS*CDIM*CDIM + WB-1)/WB, WB, 0, s3>>>(tsa_vw, tvw_, NLAYERS*CDIM*CDIM);
    k_round<<<(NLAYERS*CDIM*CDIM + WB-1)/WB, WB, 0, s3>>>(tsa_pw, tpw_, NLAYERS*CDIM*CDIM);
    k_round<<<(NLAYERS*CDIM*CDIM + WB-1)/WB, WB, 0, s3>>>(sca_pw, spw_, NLAYERS*CDIM*CDIM);
    k_round<<<(NLAYERS*CDIM*FFN + WB-1)/WB, WB, 0, s3>>>(ffn_w1, f1w_, NLAYERS*CDIM*FFN);
    k_round<<<(NLAYERS*FFN*CDIM + WB-1)/WB, WB, 0, s3>>>(ffn_w2, f2w_, NLAYERS*FFN*CDIM);
    k_prep_oa<<<(2*NLAYERS*CDIM*128 + WB-1)/WB, WB, 0, s3>>>(
        (const float*)d_in[7], (const float*)d_in[9],
        (const float*)d_in[15], (const float*)d_in[17],
        (const float*)d_in[8], (const float*)d_in[10],
        (const float*)d_in[16], (const float*)d_in[18]);
    cudaEventRecord(ev_setup, s3);

    {
        dim3 gt((NPIX + 31)/32, CDIM/32, NCAM);
        k_feats_t<<<gt, dim3(32, 8)>>>(image_feats);
    }
    k_round<<<(NLAYERS*CDIM*CDIM + WB-1)/WB, WB>>>(sca_vw, svw_, NLAYERS*CDIM*CDIM);
    k_invert<<<1, NCAM>>>(extr);
    gemm128_h(0, feats_, svw_, sca_vb, vimg_, NFEAT, CDIM, CDIM, CDIM);
    k_geom<<<(NCAM*NQ*NPTS + 255)/256, 256>>>(intr);
    k_cnt<<<(NQ + 255)/256, 256>>>();
    k_init_q<<<(NQ*CDIM + 255)/256, 256>>>(bev);
    cudaStreamWaitEvent(0, ev_setup, 0);

    for (int l = 0; l < NLAYERS; l++) {
        size_t wo = (size_t)l*CDIM*CDIM;

        if (l > 0) {
            cudaEventRecord(ev_fork[l], 0);
            cudaStreamWaitEvent(s2, ev_fork[l], 0);
            gemm128_h(s2, feats_, svw_ + wo, sca_vb + l*CDIM, vimg_,
                      NFEAT, CDIM, CDIM, CDIM);
            cudaEventRecord(ev_join[l], s2);
        }

        cudaEventRecord(ev_oaf[l], 0);
        cudaStreamWaitEvent(s3, ev_oaf[l], 0);
        gemm128_f(s3, qr_, oaw_ + (size_t)l*CDIM*128, oab_ + l*128, oa_,
                  NQ, 96, CDIM, 128);
        cudaEventRecord(ev_oaj[l], s3);

        // ---- TSA (main) ----
        gemm128_avg_h(q_, prev, tvw_ + wo, tsa_vb + l*CDIM, v_, NQ, CDIM, CDIM, CDIM);
        cudaStreamWaitEvent(0, ev_oaj[l], 0);
        k_tsa_sample<<<NQ/2, 256>>>();
        gemm_ln(a_, tpw_ + wo, tsa_pb + l*CDIM, q_, ln1_g + l*CDIM, ln1_b + l*CDIM,
                q_, qr_, NQ, CDIM);

        // ---- SCA ----
        gemm128_f(0, qr_, oaw_ + (size_t)(NLAYERS + l)*CDIM*128, oab_ + (NLAYERS + l)*128,
                  oa_, NQ, 96, CDIM, 128);
        if (l > 0)
            cudaStreamWaitEvent(0, ev_join[l], 0);
        k_sca_sample<<<NQ/2, 256>>>();
        gemm_ln(a_, spw_ + wo, sca_pb + l*CDIM, q_, ln2_g + l*CDIM, ln2_b + l*CDIM,
                q_, qr_, NQ, CDIM);

        // ---- FFN ----
        gemm128_relu(0, qr_, f1w_ + (size_t)l*CDIM*FFN, ffn_b1 + l*FFN, hid_,
                     NQ, FFN, CDIM, FFN);
        gemm_ln(hid_, f2w_ + (size_t)l*FFN*CDIM, ffn_b2 + l*CDIM, q_,
                ln3_g + l*CDIM, ln3_b + l*CDIM, q_, qr_, NQ, FFN);
    }

    k_out_t<<<dim3(NQ/32, CDIM/32), dim3(32, 8)>>>((float*)d_out);
}